// round 11
// baseline (speedup 1.0000x reference)
#include <cuda_runtime.h>
#include <cuda_bf16.h>
#include <math.h>
#include <stdint.h>

typedef __nv_bfloat16 bf16;

// ---------------- fixed problem dims ----------------
#define BB   2
#define TT4  4
#define N4   4096
#define CC   256
#define NC   150
#define TNE  16384
#define HID  1024
#define NH   8
#define HD   32
#define HH   64
#define WW   64
#define KPAD 160

#define OUT0_ELEMS 2097152
#define CXZ_ELEMS  4915200

// ---------------- scratch ----------------
__device__ float g_cl[4915200];
__device__ float g_cz[32768], g_cc[32768];
__device__ float g_cen[307200];
__device__ float g_cinln[76800];
__device__ float g_kbuf[76800];
__device__ float g_vbuf[76800];
__device__ float g_q[2097152];
__device__ float g_oproj[2097152];
__device__ float g_out1[2097152];
__device__ float g_h1[8388608];
__device__ float g_h2[2097152];

// bf16 hi/lo split buffers
__device__ bf16 g_xh[2097152],   g_xl[2097152];
__device__ bf16 g_memh[6291456], g_meml[6291456];
__device__ bf16 g_xth[2097152],  g_xtl[2097152];
__device__ bf16 g_memth[6291456], g_memtl[6291456];
__device__ bf16 g_cwh[38400],    g_cwl[38400];
__device__ bf16 g_t1h[25600], g_t1l[25600], g_t2h[25600], g_t2l[25600];
__device__ bf16 g_zth[5242880],  g_ztl[5242880];
__device__ bf16 g_clth[5242880], g_cltl[5242880];
__device__ bf16 g_softh[4915200];
__device__ bf16 g_obh[2097152], g_obl[2097152];
__device__ bf16 g_o1h[2097152], g_o1l[2097152];
__device__ bf16 g_gh[8388608],  g_gl[8388608];
__device__ bf16 g_qwh[65536],  g_qwl[65536];
__device__ bf16 g_pwh[65536],  g_pwl[65536];
__device__ bf16 g_f1h[262144], g_f1l[262144];
__device__ bf16 g_f2h[262144], g_f2l[262144];

// ---------------- warp-level bf16 MMA + cp.async ----------
__device__ __forceinline__ void mma16816(float* d, const uint32_t* a, const uint32_t* b) {
    asm volatile(
        "mma.sync.aligned.m16n8k16.row.col.f32.bf16.bf16.f32 "
        "{%0,%1,%2,%3}, {%4,%5,%6,%7}, {%8,%9}, {%0,%1,%2,%3};\n"
        : "+f"(d[0]), "+f"(d[1]), "+f"(d[2]), "+f"(d[3])
        : "r"(a[0]), "r"(a[1]), "r"(a[2]), "r"(a[3]), "r"(b[0]), "r"(b[1]));
}
__device__ __forceinline__ uint32_t smem_to_u32(const void* p) {
    uint32_t a;
    asm("{ .reg .u64 t; cvta.to.shared.u64 t, %1; cvt.u32.u64 %0, t; }"
        : "=r"(a) : "l"(p));
    return a;
}
__device__ __forceinline__ void cp_async16(uint32_t s, const void* g, bool v) {
    int sz = v ? 16 : 0;
    asm volatile("cp.async.cg.shared.global [%0], [%1], 16, %2;\n"
                 :: "r"(s), "l"(g), "r"(sz));
}
__device__ __forceinline__ void cp_commit() {
    asm volatile("cp.async.commit_group;\n" ::: "memory");
}
template<int N> __device__ __forceinline__ void cp_wait() {
    asm volatile("cp.async.wait_group %0;\n" :: "n"(N) : "memory");
}

#define SAS 40

// ---- 3-term chunk (A hi+lo) ----
template<int WNT>
__device__ __forceinline__ void hmma_chunk(
    bf16 (*sAh)[SAS], bf16 (*sAl)[SAS], bf16 (*sBh)[SAS], bf16 (*sBl)[SAS],
    int wm, int wn, int g, int tg, float (*acc)[WNT][4])
{
    #pragma unroll
    for (int ks = 0; ks < 2; ks++) {
        int kc = ks * 16 + tg * 2;
        uint32_t ah[2][4], al[2][4], bh[WNT][2], bl[WNT][2];
        #pragma unroll
        for (int mt = 0; mt < 2; mt++) {
            int r = wm * 32 + mt * 16 + g;
            ah[mt][0] = *(const uint32_t*)&sAh[r][kc];
            ah[mt][1] = *(const uint32_t*)&sAh[r + 8][kc];
            ah[mt][2] = *(const uint32_t*)&sAh[r][kc + 8];
            ah[mt][3] = *(const uint32_t*)&sAh[r + 8][kc + 8];
            al[mt][0] = *(const uint32_t*)&sAl[r][kc];
            al[mt][1] = *(const uint32_t*)&sAl[r + 8][kc];
            al[mt][2] = *(const uint32_t*)&sAl[r][kc + 8];
            al[mt][3] = *(const uint32_t*)&sAl[r + 8][kc + 8];
        }
        #pragma unroll
        for (int nt = 0; nt < WNT; nt++) {
            int nr = wn * (WNT * 8) + nt * 8 + g;
            bh[nt][0] = *(const uint32_t*)&sBh[nr][kc];
            bh[nt][1] = *(const uint32_t*)&sBh[nr][kc + 8];
            bl[nt][0] = *(const uint32_t*)&sBl[nr][kc];
            bl[nt][1] = *(const uint32_t*)&sBl[nr][kc + 8];
        }
        #pragma unroll
        for (int mt = 0; mt < 2; mt++)
            #pragma unroll
            for (int nt = 0; nt < WNT; nt++) {
                mma16816(acc[mt][nt], ah[mt], bh[nt]);
                mma16816(acc[mt][nt], ah[mt], bl[nt]);
                mma16816(acc[mt][nt], al[mt], bh[nt]);
            }
    }
}

// ---- 2-term chunk (A hi only) ----
template<int WNT>
__device__ __forceinline__ void hmma_chunk2(
    bf16 (*sA)[SAS], bf16 (*sBh)[SAS], bf16 (*sBl)[SAS],
    int wm, int wn, int g, int tg, float (*acc)[WNT][4])
{
    #pragma unroll
    for (int ks = 0; ks < 2; ks++) {
        int kc = ks * 16 + tg * 2;
        uint32_t a[2][4], bh[WNT][2], bl[WNT][2];
        #pragma unroll
        for (int mt = 0; mt < 2; mt++) {
            int r = wm * 32 + mt * 16 + g;
            a[mt][0] = *(const uint32_t*)&sA[r][kc];
            a[mt][1] = *(const uint32_t*)&sA[r + 8][kc];
            a[mt][2] = *(const uint32_t*)&sA[r][kc + 8];
            a[mt][3] = *(const uint32_t*)&sA[r + 8][kc + 8];
        }
        #pragma unroll
        for (int nt = 0; nt < WNT; nt++) {
            int nr = wn * (WNT * 8) + nt * 8 + g;
            bh[nt][0] = *(const uint32_t*)&sBh[nr][kc];
            bh[nt][1] = *(const uint32_t*)&sBh[nr][kc + 8];
            bl[nt][0] = *(const uint32_t*)&sBl[nr][kc];
            bl[nt][1] = *(const uint32_t*)&sBl[nr][kc + 8];
        }
        #pragma unroll
        for (int mt = 0; mt < 2; mt++)
            #pragma unroll
            for (int nt = 0; nt < WNT; nt++) {
                mma16816(acc[mt][nt], a[mt], bh[nt]);
                mma16816(acc[mt][nt], a[mt], bl[nt]);
            }
    }
}

// ---- 3-stage cp.async pipelined mainloop (3-term) ----
template<int WNT, typename F>
__device__ __forceinline__ void hmma_pipe(char* sm, int nk, F getp, float (*acc)[WNT][4])
{
    constexpr int BN = 16 * WNT;
    constexpr int ASZ = 128 * SAS * 2;
    constexpr int BSZ = BN * SAS * 2;
    constexpr int STG = 2 * ASZ + 2 * BSZ;
    int tid = threadIdx.x;
    int wid = tid >> 5, lane = tid & 31;
    int wm = wid & 3, wn = wid >> 2, g = lane >> 2, tg = lane & 3;
    int lrow = tid >> 1, lhalf = (tid & 1) * 16;
    bool bload = (WNT == 8) || (tid < BN * 2);
    uint32_t sb = smem_to_u32(sm);
    uint32_t off = (uint32_t)(lrow * SAS + lhalf) * 2;

    __syncthreads();

    auto issue = [&](int c) {
        uint32_t st = sb + (c % 3) * STG;
        const bf16 *ah, *al, *bh, *bl; bool av;
        getp(c, ah, al, bh, bl, av);
        cp_async16(st + off, ah, av);
        cp_async16(st + off + 16, ah + 8, av);
        cp_async16(st + ASZ + off, al, av);
        cp_async16(st + ASZ + off + 16, al + 8, av);
        if (bload) {
            cp_async16(st + 2 * ASZ + off, bh, true);
            cp_async16(st + 2 * ASZ + off + 16, bh + 8, true);
            cp_async16(st + 2 * ASZ + BSZ + off, bl, true);
            cp_async16(st + 2 * ASZ + BSZ + off + 16, bl + 8, true);
        }
        cp_commit();
    };

    issue(0); issue(1);
    for (int c = 0; c < nk; c++) {
        if (c + 2 <= nk) cp_wait<1>(); else cp_wait<0>();
        __syncthreads();
        {
            char* st = sm + (c % 3) * STG;
            bf16 (*sAh)[SAS] = (bf16(*)[SAS])st;
            bf16 (*sAl)[SAS] = (bf16(*)[SAS])(st + ASZ);
            bf16 (*sBh)[SAS] = (bf16(*)[SAS])(st + 2 * ASZ);
            bf16 (*sBl)[SAS] = (bf16(*)[SAS])(st + 2 * ASZ + BSZ);
            hmma_chunk<WNT>(sAh, sAl, sBh, sBl, wm, wn, g, tg, acc);
        }
        if (c + 2 < nk) issue(c + 2);
    }
}

// ---- 3-stage pipelined mainloop, A hi only (2-term) ----
template<int WNT, typename F>
__device__ __forceinline__ void hmma_pipe2(char* sm, int nk, F getp, float (*acc)[WNT][4])
{
    constexpr int BN = 16 * WNT;
    constexpr int ASZ = 128 * SAS * 2;
    constexpr int BSZ = BN * SAS * 2;
    constexpr int STG = ASZ + 2 * BSZ;
    int tid = threadIdx.x;
    int wid = tid >> 5, lane = tid & 31;
    int wm = wid & 3, wn = wid >> 2, g = lane >> 2, tg = lane & 3;
    int lrow = tid >> 1, lhalf = (tid & 1) * 16;
    bool bload = (WNT == 8) || (tid < BN * 2);
    uint32_t sb = smem_to_u32(sm);
    uint32_t off = (uint32_t)(lrow * SAS + lhalf) * 2;

    __syncthreads();

    auto issue = [&](int c) {
        uint32_t st = sb + (c % 3) * STG;
        const bf16 *ah, *bh, *bl; bool av;
        getp(c, ah, bh, bl, av);
        cp_async16(st + off, ah, av);
        cp_async16(st + off + 16, ah + 8, av);
        if (bload) {
            cp_async16(st + ASZ + off, bh, true);
            cp_async16(st + ASZ + off + 16, bh + 8, true);
            cp_async16(st + ASZ + BSZ + off, bl, true);
            cp_async16(st + ASZ + BSZ + off + 16, bl + 8, true);
        }
        cp_commit();
    };

    issue(0); issue(1);
    for (int c = 0; c < nk; c++) {
        if (c + 2 <= nk) cp_wait<1>(); else cp_wait<0>();
        __syncthreads();
        {
            char* st = sm + (c % 3) * STG;
            bf16 (*sA)[SAS] = (bf16(*)[SAS])st;
            bf16 (*sBh)[SAS] = (bf16(*)[SAS])(st + ASZ);
            bf16 (*sBl)[SAS] = (bf16(*)[SAS])(st + ASZ + BSZ);
            hmma_chunk2<WNT>(sA, sBh, sBl, wm, wn, g, tg, acc);
        }
        if (c + 2 < nk) issue(c + 2);
    }
}

// ================= HMMA GEMM (q/proj/fc1/fc2) ============
template<int WNT>
__global__ void __launch_bounds__(256)
hmma_gemm_kernel(const bf16* __restrict__ Ah, const bf16* __restrict__ Al,
                 const bf16* __restrict__ Bh, const bf16* __restrict__ Bl,
                 const float* __restrict__ bias, float* __restrict__ C,
                 int Ntot, int K, float scale)
{
    extern __shared__ char sm[];
    constexpr int BN = 16 * WNT;
    int tid = threadIdx.x, wid = tid >> 5, lane = tid & 31;
    int wm = wid & 3, wn = wid >> 2, g = lane >> 2, tg = lane & 3;
    int m0 = blockIdx.y * 128, n0 = blockIdx.x * BN;
    int lrow = tid >> 1, lhalf = (tid & 1) * 16;

    float acc[2][WNT][4] = {};
    auto getp = [&](int c, const bf16*& ah, const bf16*& al,
                    const bf16*& bh, const bf16*& bl, bool& av) {
        int k0 = (c << 5) + lhalf;
        ah = Ah + (size_t)(m0 + lrow) * K + k0;
        al = Al + (size_t)(m0 + lrow) * K + k0;
        bh = Bh + (size_t)(n0 + lrow) * K + k0;
        bl = Bl + (size_t)(n0 + lrow) * K + k0;
        av = true;
    };
    hmma_pipe<WNT>(sm, K >> 5, getp, acc);

    #pragma unroll
    for (int mt = 0; mt < 2; mt++) {
        int r0 = m0 + wm * 32 + mt * 16 + g;
        #pragma unroll
        for (int nt = 0; nt < WNT; nt++) {
            int col = n0 + wn * (WNT * 8) + nt * 8 + tg * 2;
            float b0 = bias[col], b1 = bias[col + 1];
            float2 v0, v1;
            v0.x = (acc[mt][nt][0] + b0) * scale;
            v0.y = (acc[mt][nt][1] + b1) * scale;
            v1.x = (acc[mt][nt][2] + b0) * scale;
            v1.y = (acc[mt][nt][3] + b1) * scale;
            *(float2*)&C[(size_t)r0 * Ntot + col] = v0;
            *(float2*)&C[(size_t)(r0 + 8) * Ntot + col] = v1;
        }
    }
}

// ================= cl HMMA =================
__global__ void __launch_bounds__(256)
cl_hmma_kernel(const bf16* __restrict__ cwh, const bf16* __restrict__ cwl,
               const bf16* __restrict__ xh, const bf16* __restrict__ xl,
               const bf16* __restrict__ memh, const bf16* __restrict__ meml,
               float* __restrict__ cl)
{
    extern __shared__ char sm[];
    int bt = blockIdx.z, b = bt >> 2, t = bt & 3;
    const bf16* Bh = (t < 3) ? memh + (size_t)(b * 3 + t) * 1048576 : xh + (size_t)b * 1048576;
    const bf16* Bl = (t < 3) ? meml + (size_t)(b * 3 + t) * 1048576 : xl + (size_t)b * 1048576;
    float* Cp = cl + (size_t)bt * 614400;

    int tid = threadIdx.x, wid = tid >> 5, lane = tid & 31;
    int wm = wid & 3, wn = wid >> 2, g = lane >> 2, tg = lane & 3;
    int m0 = blockIdx.y * 128, n0 = blockIdx.x * 128;
    int lrow = tid >> 1, lhalf = (tid & 1) * 16;
    bool aval = (m0 + lrow) < NC;

    float acc[2][8][4] = {};
    auto getp = [&](int c, const bf16*& ah, const bf16*& al,
                    const bf16*& bh, const bf16*& bl, bool& av) {
        int k0 = (c << 5) + lhalf;
        ah = cwh + (size_t)(m0 + lrow) * CC + k0;
        al = cwl + (size_t)(m0 + lrow) * CC + k0;
        bh = Bh + (size_t)(n0 + lrow) * CC + k0;
        bl = Bl + (size_t)(n0 + lrow) * CC + k0;
        av = aval;
    };
    hmma_pipe<8>(sm, 8, getp, acc);

    #pragma unroll
    for (int mt = 0; mt < 2; mt++) {
        int r0 = m0 + wm * 32 + mt * 16 + g;
        #pragma unroll
        for (int nt = 0; nt < 8; nt++) {
            int col = n0 + wn * 64 + nt * 8 + tg * 2;
            if (r0 < NC)
                *(float2*)&Cp[(size_t)r0 * N4 + col] = make_float2(acc[mt][nt][0], acc[mt][nt][1]);
            if (r0 + 8 < NC)
                *(float2*)&Cp[(size_t)(r0 + 8) * N4 + col] = make_float2(acc[mt][nt][2], acc[mt][nt][3]);
        }
    }
}

// ================= comb HMMA =================
__global__ void __launch_bounds__(256)
comb_hmma_kernel(const bf16* __restrict__ t1h, const bf16* __restrict__ t1l,
                 const bf16* __restrict__ t2h, const bf16* __restrict__ t2l,
                 const bf16* __restrict__ zth, const bf16* __restrict__ ztl,
                 const bf16* __restrict__ clth, const bf16* __restrict__ cltl,
                 const float* __restrict__ cz, const float* __restrict__ cc,
                 float* __restrict__ cxz, float* __restrict__ ctr)
{
    extern __shared__ char sm[];
    int b = blockIdx.z;
    int j0 = blockIdx.y * 128, n0 = blockIdx.x * 64;
    int tid = threadIdx.x, wid = tid >> 5, lane = tid & 31;
    int wm = wid & 3, wn = wid >> 2, g = lane >> 2, tg = lane & 3;
    int lrow = tid >> 1, lhalf = (tid & 1) * 16;
    bool aval = (j0 + lrow) < KPAD;

    float acc1[2][4][4] = {}, acc2[2][4][4] = {};
    const bf16* Bz_h = zth + (size_t)b * TNE * KPAD;
    const bf16* Bz_l = ztl + (size_t)b * TNE * KPAD;
    const bf16* Bc_h = clth + (size_t)b * TNE * KPAD;
    const bf16* Bc_l = cltl + (size_t)b * TNE * KPAD;

    auto getp1 = [&](int c, const bf16*& ah, const bf16*& al,
                     const bf16*& bh, const bf16*& bl, bool& av) {
        int k0 = (c << 5) + lhalf;
        ah = t1h + (size_t)(j0 + lrow) * KPAD + k0;
        al = t1l + (size_t)(j0 + lrow) * KPAD + k0;
        bh = Bz_h + (size_t)(n0 + lrow) * KPAD + k0;
        bl = Bz_l + (size_t)(n0 + lrow) * KPAD + k0;
        av = aval;
    };
    hmma_pipe<4>(sm, 5, getp1, acc1);
    auto getp2 = [&](int c, const bf16*& ah, const bf16*& al,
                     const bf16*& bh, const bf16*& bl, bool& av) {
        int k0 = (c << 5) + lhalf;
        ah = t2h + (size_t)(j0 + lrow) * KPAD + k0;
        al = t2l + (size_t)(j0 + lrow) * KPAD + k0;
        bh = Bc_h + (size_t)(n0 + lrow) * KPAD + k0;
        bl = Bc_l + (size_t)(n0 + lrow) * KPAD + k0;
        av = aval;
    };
    hmma_pipe<4>(sm, 5, getp2, acc2);

    #pragma unroll
    for (int mt = 0; mt < 2; mt++) {
        int r0 = j0 + wm * 32 + mt * 16 + g;
        #pragma unroll
        for (int nt = 0; nt < 4; nt++) {
            int col = n0 + wn * 32 + nt * 8 + tg * 2;
            float s0z = cz[(size_t)b * TNE + col],     s1z = cz[(size_t)b * TNE + col + 1];
            float s0c = cc[(size_t)b * TNE + col],     s1c = cc[(size_t)b * TNE + col + 1];
            int t = col >> 12, n = col & 4095;
            if (r0 < NC) {
                float2 v;
                v.x = s0z * acc1[mt][nt][0] + s0c * acc2[mt][nt][0];
                v.y = s1z * acc1[mt][nt][1] + s1c * acc2[mt][nt][1];
                *(float2*)&cxz[((size_t)b * NC + r0) * TNE + col] = v;
                *(float2*)&ctr[((size_t)(b * TT4 + t) * NC + r0) * N4 + n] = v;
            }
            if (r0 + 8 < NC) {
                float2 v;
                v.x = s0z * acc1[mt][nt][2] + s0c * acc2[mt][nt][2];
                v.y = s1z * acc1[mt][nt][3] + s1c * acc2[mt][nt][3];
                *(float2*)&cxz[((size_t)b * NC + r0 + 8) * TNE + col] = v;
                *(float2*)&ctr[((size_t)(b * TT4 + t) * NC + r0 + 8) * N4 + n] = v;
            }
        }
    }
}

// ================= cen HMMA (2-term, split-K, atomic) =================
__global__ void __launch_bounds__(256)
cen_hmma_kernel(const bf16* __restrict__ softh,
                const bf16* __restrict__ xth, const bf16* __restrict__ xtl,
                const bf16* __restrict__ memth, const bf16* __restrict__ memtl,
                float* __restrict__ cen)
{
    extern __shared__ char sm[];
    int bt = blockIdx.z >> 3, sp = blockIdx.z & 7;
    int b = bt >> 2, t = bt & 3;
    const bf16* Ah = softh + (size_t)bt * 614400;
    const bf16* Bh = (t < 3) ? memth + (size_t)(b * 3 + t) * 1048576 : xth + (size_t)b * 1048576;
    const bf16* Bl = (t < 3) ? memtl + (size_t)(b * 3 + t) * 1048576 : xtl + (size_t)b * 1048576;
    float* Cp = cen + (size_t)bt * 38400;
    int koff = sp * 512;

    int tid = threadIdx.x, wid = tid >> 5, lane = tid & 31;
    int wm = wid & 3, wn = wid >> 2, g = lane >> 2, tg = lane & 3;
    int m0 = blockIdx.y * 128, n0 = blockIdx.x * 128;
    int lrow = tid >> 1, lhalf = (tid & 1) * 16;
    bool aval = (m0 + lrow) < NC;

    float acc[2][8][4] = {};
    auto getp = [&](int c, const bf16*& ah,
                    const bf16*& bh, const bf16*& bl, bool& av) {
        int k0 = koff + (c << 5) + lhalf;
        ah = Ah + (size_t)(m0 + lrow) * N4 + k0;
        bh = Bh + (size_t)(n0 + lrow) * N4 + k0;
        bl = Bl + (size_t)(n0 + lrow) * N4 + k0;
        av = aval;
    };
    hmma_pipe2<8>(sm, 16, getp, acc);

    #pragma unroll
    for (int mt = 0; mt < 2; mt++) {
        int r0 = m0 + wm * 32 + mt * 16 + g;
        #pragma unroll
        for (int nt = 0; nt < 8; nt++) {
            int col = n0 + wn * 64 + nt * 8 + tg * 2;
            if (r0 < NC) {
                atomicAdd(&Cp[(size_t)r0 * CC + col], acc[mt][nt][0]);
                atomicAdd(&Cp[(size_t)r0 * CC + col + 1], acc[mt][nt][1]);
            }
            if (r0 + 8 < NC) {
                atomicAdd(&Cp[(size_t)(r0 + 8) * CC + col], acc[mt][nt][2]);
                atomicAdd(&Cp[(size_t)(r0 + 8) * CC + col + 1], acc[mt][nt][3]);
            }
        }
    }
}

// ---------------- splits ----------------
__device__ __forceinline__ void split_store4(const float4 v, bf16* hi, bf16* lo, int i) {
    bf16 h0 = __float2bfloat16(v.x), h1 = __float2bfloat16(v.y);
    bf16 h2 = __float2bfloat16(v.z), h3 = __float2bfloat16(v.w);
    *(__nv_bfloat162*)(hi + i)     = __nv_bfloat162(h0, h1);
    *(__nv_bfloat162*)(hi + i + 2) = __nv_bfloat162(h2, h3);
    *(__nv_bfloat162*)(lo + i) = __nv_bfloat162(
        __float2bfloat16(v.x - __bfloat162float(h0)),
        __float2bfloat16(v.y - __bfloat162float(h1)));
    *(__nv_bfloat162*)(lo + i + 2) = __nv_bfloat162(
        __float2bfloat16(v.z - __bfloat162float(h2)),
        __float2bfloat16(v.w - __bfloat162float(h3)));
}
__global__ void cvt_split5_kernel(
    const float* a0, bf16* h0, bf16* l0, int s0,
    const float* a1, bf16* h1, bf16* l1, int s1,
    const float* a2, bf16* h2, bf16* l2, int s2,
    const float* a3, bf16* h3, bf16* l3, int s3,
    const float* a4, bf16* h4, bf16* l4, int s4)
{
    const float* in; bf16 *hi, *lo; int n;
    switch (blockIdx.y) {
        case 0: in = a0; hi = h0; lo = l0; n = s0; break;
        case 1: in = a1; hi = h1; lo = l1; n = s1; break;
        case 2: in = a2; hi = h2; lo = l2; n = s2; break;
        case 3: in = a3; hi = h3; lo = l3; n = s3; break;
        default: in = a4; hi = h4; lo = l4; n = s4; break;
    }
    int i = (blockIdx.x * 256 + threadIdx.x) * 4;
    if (i >= n) return;
    split_store4(*(const float4*)(in + i), hi, lo, i);
}

// ---- split + transpose-split in one pass ----
__global__ void split_all_kernel(const float* __restrict__ in,
                                 bf16* __restrict__ oh, bf16* __restrict__ ol,
                                 bf16* __restrict__ toh, bf16* __restrict__ tol)
{
    __shared__ float tile[32][33];
    const float* src = in + (size_t)blockIdx.z * 1048576;
    bf16* doh = oh + (size_t)blockIdx.z * 1048576;
    bf16* dol = ol + (size_t)blockIdx.z * 1048576;
    bf16* dth = toh + (size_t)blockIdx.z * 1048576;
    bf16* dtl = tol + (size_t)blockIdx.z * 1048576;
    int tx = threadIdx.x, ty = threadIdx.y;
    int r0 = blockIdx.x * 32, c0 = blockIdx.y * 32;
    #pragma unroll
    for (int i = 0; i < 4; i++) {
        int r = r0 + ty + i * 8;
        float v = src[(size_t)r * CC + c0 + tx];
        tile[ty + i * 8][tx] = v;
        bf16 h = __float2bfloat16(v);
        doh[(size_t)r * CC + c0 + tx] = h;
        dol[(size_t)r * CC + c0 + tx] = __float2bfloat16(v - __bfloat162float(h));
    }
    __syncthreads();
    #pragma unroll
    for (int i = 0; i < 4; i++) {
        int c = c0 + ty + i * 8;
        float v = tile[tx][ty + i * 8];
        bf16 h = __float2bfloat16(v);
        dth[(size_t)c * N4 + r0 + tx] = h;
        dtl[(size_t)c * N4 + r0 + tx] = __float2bfloat16(v - __bfloat162float(h));
    }
}

// ---- zT split ----
__global__ void zT_split_kernel(const float* __restrict__ z,
                                bf16* __restrict__ oh, bf16* __restrict__ ol)
{
    __shared__ float tile[32][33];
    int b = blockIdx.z;
    int m0 = blockIdx.x * 32, k0 = blockIdx.y * 32;
    int tx = threadIdx.x, ty = threadIdx.y;
    #pragma unroll
    for (int i = 0; i < 4; i++) {
        int k = k0 + ty + i * 8;
        tile[ty + i * 8][tx] = (k < NC) ? z[((size_t)b * NC + k) * TNE + m0 + tx] : 0.f;
    }
    __syncthreads();
    #pragma unroll
    for (int i = 0; i < 4; i++) {
        int m = m0 + ty + i * 8;
        float v = tile[tx][ty + i * 8];
        bf16 h = __float2bfloat16(v);
        size_t idx = ((size_t)b * TNE + m) * KPAD + k0 + tx;
        oh[idx] = h;
        ol[idx] = __float2bfloat16(v - __bfloat162float(h));
    }
}

// ---- clT split ----
__global__ void clT_split_kernel(const float* __restrict__ cl,
                                 bf16* __restrict__ oh, bf16* __restrict__ ol)
{
    __shared__ float tile[32][33];
    int bt = blockIdx.z, b = bt >> 2, t = bt & 3;
    int n0 = blockIdx.x * 32, k0 = blockIdx.y * 32;
    int tx = threadIdx.x, ty = threadIdx.y;
    const float* src = cl + (size_t)bt * 614400;
    #pragma unroll
    for (int i = 0; i < 4; i++) {
        int k = k0 + ty + i * 8;
        tile[ty + i * 8][tx] = (k < NC) ? src[(size_t)k * N4 + n0 + tx] : 0.f;
    }
    __syncthreads();
    #pragma unroll
    for (int i = 0; i < 4; i++) {
        int n = n0 + ty + i * 8;
        float v = tile[tx][ty + i * 8];
        bf16 h = __float2bfloat16(v);
        size_t idx = ((size_t)b * TNE + t * N4 + n) * KPAD + k0 + tx;
        oh[idx] = h;
        ol[idx] = __float2bfloat16(v - __bfloat162float(h));
    }
}

// ---- tdt^T padded split ----
__global__ void tdt_prep_kernel(const float* __restrict__ tdt1, const float* __restrict__ tdt2,
                                bf16* __restrict__ t1h, bf16* __restrict__ t1l,
                                bf16* __restrict__ t2h, bf16* __restrict__ t2l)
{
    int i = blockIdx.x * 256 + threadIdx.x;
    if (i >= KPAD * KPAD) return;
    int j = i / KPAD, k = i % KPAD;
    float v1 = (j < NC && k < NC) ? tdt1[k * NC + j] : 0.f;
    float v2 = (j < NC && k < NC) ? tdt2[k * NC + j] : 0.f;
    bf16 h1 = __float2bfloat16(v1), h2 = __float2bfloat16(v2);
    t1h[i] = h1; t1l[i] = __float2bfloat16(v1 - __bfloat162float(h1));
    t2h[i] = h2; t2l[i] = __float2bfloat16(v2 - __bfloat162float(h2));
}

// ---------------- helpers ----------------
__device__ __forceinline__ float block_reduce_sum(float v, float* sbuf) {
    int tid = threadIdx.x;
    sbuf[tid] = v; __syncthreads();
    for (int s = blockDim.x >> 1; s > 0; s >>= 1) {
        if (tid < s) sbuf[tid] += sbuf[tid + s];
        __syncthreads();
    }
    float r = sbuf[0]; __syncthreads();
    return r;
}
__device__ __forceinline__ float block_reduce_max(float v, float* sbuf) {
    int tid = threadIdx.x;
    sbuf[tid] = v; __syncthreads();
    for (int s = blockDim.x >> 1; s > 0; s >>= 1) {
        if (tid < s) sbuf[tid] = fmaxf(sbuf[tid], sbuf[tid + s]);
        __syncthreads();
    }
    float r = sbuf[0]; __syncthreads();
    return r;
}

// ======== merged k/v projection ====
#define OBM 64
#define OBN 64
#define OBK 16
__global__ void gemm_kv_kernel(const float* __restrict__ A,
                               const float* __restrict__ k_w, const float* __restrict__ k_b,
                               const float* __restrict__ v_w, const float* __restrict__ v_b,
                               float* __restrict__ kout, float* __restrict__ vout)
{
    const float* B = blockIdx.z ? v_w : k_w;
    const float* bias = blockIdx.z ? v_b : k_b;
    float* C = blockIdx.z ? vout : kout;
    const int M = BB * NC;
    __shared__ float As[OBK][OBM];
    __shared__ float Bs[OBK][OBN];
    int tid = threadIdx.x;
    int tx = tid & 15, ty = tid >> 4;
    int m0 = blockIdx.y * OBM, n0 = blockIdx.x * OBN;
    float acc[4][4] = {};
    for (int k0 = 0; k0 < CC; k0 += OBK) {
        #pragma unroll
        for (int j = 0; j < 4; j++) {
            int idx = tid + j * 256;
            int ml = idx / OBK, kl = idx % OBK;
            int m = m0 + ml;
            As[kl][ml] = (m < M) ? A[(size_t)m * CC + k0 + kl] : 0.f;
        }
        #pragma unroll
        for (int j = 0; j < 4; j++) {
            int idx = tid + j * 256;
            int nl = idx / OBK, kl = idx % OBK;
            Bs[kl][nl] = B[(size_t)(n0 + nl) * CC + k0 + kl];
        }
        __syncthreads();
        #pragma unroll
        for (int kk = 0; kk < OBK; kk++) {
            float a[4], b[4];
            *(float4*)a = *(const float4*)&As[kk][ty * 4];
            *(float4*)b = *(const float4*)&Bs[kk][tx * 4];
            #pragma unroll
            for (int i = 0; i < 4; i++)
                #pragma unroll
                for (int j = 0; j < 4; j++)
                    acc[i][j] += a[i] * b[j];
        }
        __syncthreads();
    }
    #pragma unroll
    for (int i = 0; i < 4; i++) {
        int m = m0 + ty * 4 + i;
        if (m >= M) continue;
        #pragma unroll
        for (int j = 0; j < 4; j++) {
            int n = n0 + tx * 4 + j;
            C[(size_t)m * CC + n] = acc[i][j] + bias[n];
        }
    }
}

// ---- prompt cos -> cz/cc, vectorized x4 along m ----
__global__ void prompt_scale_kernel(const float* __restrict__ z,
                                    const float* __restrict__ cl,
                                    const float* __restrict__ p1,
                                    const float* __restrict__ p2,
                                    float* __restrict__ cz,
                                    float* __restrict__ cc)
{
    int m = (blockIdx.x * blockDim.x + threadIdx.x) * 4;
    int b = blockIdx.z;
    if (m >= TNE) return;
    int t = m >> 12, n = m & 4095;
    const float* zrow = z + (size_t)b * NC * TNE + m;
    const float* crow = cl + ((size_t)(b * TT4 + t) * NC) * N4 + n;
    float4 dz = {0,0,0,0}, nz = {0,0,0,0}, dc = {0,0,0,0}, ncs = {0,0,0,0};
    float p1n = 0, p2n = 0;
    for (int k = 0; k < NC; k++) {
        float4 zv = *(const float4*)(zrow + (size_t)k * TNE);
        float4 cv = *(const float4*)(crow + (size_t)k * N4);
        float a = p1[k], bb = p2[k];
        dz.x += zv.x * a; dz.y += zv.y * a; dz.z += zv.z * a; dz.w += zv.w * a;
        nz.x += zv.x * zv.x; nz.y += zv.y * zv.y; nz.z += zv.z * zv.z; nz.w += zv.w * zv.w;
        dc.x += cv.x * bb; dc.y += cv.y * bb; dc.z += cv.z * bb; dc.w += cv.w * bb;
        ncs.x += cv.x * cv.x; ncs.y += cv.y * cv.y; ncs.z += cv.z * cv.z; ncs.w += cv.w * cv.w;
        p1n += a * a; p2n += bb * bb;
    }
    float sp1 = fmaxf(sqrtf(p1n), 1e-12f), sp2 = fmaxf(sqrtf(p2n), 1e-12f);
    float4 vz, vc;
    vz.x = fminf(fmaxf(dz.x / (fmaxf(sqrtf(nz.x), 1e-12f) * sp1), 0.f), 1.f) * 0.5f;
    vz.y = fminf(fmaxf(dz.y / (fmaxf(sqrtf(nz.y), 1e-12f) * sp1), 0.f), 1.f) * 0.5f;
    vz.z = fminf(fmaxf(dz.z / (fmaxf(sqrtf(nz.z), 1e-12f) * sp1), 0.f), 1.f) * 0.5f;
    vz.w = fminf(fmaxf(dz.w / (fmaxf(sqrtf(nz.w), 1e-12f) * sp1), 0.f), 1.f) * 0.5f;
    vc.x = fminf(fmaxf(dc.x / (fmaxf(sqrtf(ncs.x), 1e-12f) * sp2), 0.f), 1.f) * 0.5f;
    vc.y = fminf(fmaxf(dc.y / (fmaxf(sqrtf(ncs.y), 1e-12f) * sp2), 0.f), 1.f) * 0.5f;
    vc.z = fminf(fmaxf(dc.z / (fmaxf(sqrtf(ncs.z), 1e-12f) * sp2), 0.f), 1.f) * 0.5f;
    vc.w = fminf(fmaxf(dc.w / (fmaxf(sqrtf(ncs.w), 1e-12f) * sp2), 0.f), 1.f) * 0.5f;
    *(float4*)(cz + (size_t)b * TNE + m) = vz;
    *(float4*)(cc + (size_t)b * TNE + m) = vc;
}

// ---- softmax -> bf16 hi only, vectorized ----
__global__ void softmax_kernel(const float* __restrict__ cxz,
                               bf16* __restrict__ softh)
{
    __shared__ float sbuf[256];
    int r = blockIdx.x;
    int k = r % NC;
    int bt = r / NC;
    int b = bt / TT4, t = bt % TT4;
    const float* src = cxz + ((size_t)b * NC + k) * TNE + t * N4;
    bf16* dh = softh + (size_t)r * N4;
    int tid = threadIdx.x;
    float4 v[4];
    float mx = -3.4e38f;
    #pragma unroll
    for (int j = 0; j < 4; j++) {
        v[j] = *(const float4*)(src + tid * 4 + j * 1024);
        mx = fmaxf(mx, fmaxf(fmaxf(v[j].x, v[j].y), fmaxf(v[j].z, v[j].w)));
    }
    mx = block_reduce_max(mx, sbuf);
    float s = 0.f;
    #pragma unroll
    for (int j = 0; j < 4; j++) {
        v[j].x = expf(v[j].x - mx); v[j].y = expf(v[j].y - mx);
        v[j].z = expf(v[j].z - mx); v[j].w = expf(v[j].w - mx);
        s += v[j].x + v[j].y + v[j].z + v[j].w;
    }
    s = block_reduce_sum(s, sbuf);
    float inv = 1.f / s;
    #pragma unroll
    for (int j = 0; j < 4; j++) {
        __nv_bfloat162 p0(__float2bfloat16(v[j].x * inv), __float2bfloat16(v[j].y * inv));
        __nv_bfloat162 p1(__float2bfloat16(v[j].z * inv), __float2bfloat16(v[j].w * inv));
        *(__nv_bfloat162*)(dh + tid * 4 + j * 1024) = p0;
        *(__nv_bfloat162*)(dh + tid * 4 + j * 1024 + 2) = p1;
    }
}

// ---- zero cen ----
__global__ void zero_cen_kernel(float* __restrict__ cen)
{
    int i = blockIdx.x * blockDim.x + threadIdx.x;
    if (i < 307200) cen[i] = 0.f;
}

// ---- C_in gating + LayerNorm ----
__global__ void cin_kernel(const float* __restrict__ cen,
                           const float* __restrict__ alpha,
                           const float* __restrict__ beta,
                           const float* __restrict__ nw,
                           const float* __restrict__ nb,
                           float* __restrict__ cinln)
{
    __shared__ float sbuf[256];
    int bk = blockIdx.x;
    int b = bk / NC, k = bk % NC;
    int c = threadIdx.x;
    float last = cen[((size_t)(b * TT4 + 3) * NC + k) * CC + c];
    float pv[3];
    #pragma unroll
    for (int t = 0; t < 3; t++)
        pv[t] = cen[((size_t)(b * TT4 + t) * NC + k) * CC + c];
    float nl = block_reduce_sum(last * last, sbuf);
    float al = alpha[0], be = beta[0];
    float g[3];
    #pragma unroll
    for (int t = 0; t < 3; t++) {
        float dt = block_reduce_sum(last * pv[t], sbuf);
        float np = block_reduce_sum(pv[t] * pv[t], sbuf);
        float denom = fmaxf(sqrtf(nl) * sqrtf(np), 1e-8f);
        g[t] = 1.f / (1.f + expf(-(be + al * dt / denom)));
    }
    float cin = last + g[0] * pv[0] + g[1] * pv[1] + g[2] * pv[2];
    float mean = block_reduce_sum(cin, sbuf) * (1.f / CC);
    float d = cin - mean;
    float var = block_reduce_sum(d * d, sbuf) * (1.f / CC);
    cinln[((size_t)b * NC + k) * CC + c] = d * rsqrtf(var + 1e-5f) * nw[c] + nb[c];
}

// ---- attention -> bf16 hi/lo output ----
__global__ void attn_kernel(const float* __restrict__ q,
                            const float* __restrict__ kbuf,
                            const float* __restrict__ vbuf,
                            bf16* __restrict__ obh, bf16* __restrict__ obl)
{
    __shared__ float kh[NC * 33];
    __shared__ float vh[NC * 33];
    int b = blockIdx.z, h = blockIdx.y;
    int tid = threadIdx.x;
    int warp = tid >> 5, lane = tid & 31;
    for (int idx = tid; idx < NC * HD; idx += blockDim.x) {
        int kk = idx / HD, d = idx % HD;
        kh[kk * 33 + d] = kbuf[((size_t)b * NC + kk) * CC + h * HD + d];
        vh[kk * 33 + d] = vbuf[((size_t)b * NC + kk) * CC + h * HD + d];
    }
    __syncthreads();
    const unsigned FULL = 0xffffffffu;
    for (int ni = warp; ni < 256; ni += 8) {
        int n = blockIdx.x * 256 + ni;
        float qv = q[((size_t)b * N4 + n) * CC + h * HD + lane];
        float lg[5];
        #pragma unroll
        for (int i = 0; i < 5; i++) {
            int kk = lane + 32 * i;
            int kks = (kk < NC) ? kk : (NC - 1);
            float acc = 0.f;
            #pragma unroll
            for (int d = 0; d < 32; d++) {
                float qd = __shfl_sync(FULL, qv, d);
                acc += qd * kh[kks * 33 + d];
            }
            lg[i] = (kk < NC) ? acc : -3.4e38f;
        }
        float mx = lg[0];
        #pragma unroll
        for (int i = 1; i < 5; i++) mx = fmaxf(mx, lg[i]);
        #pragma unroll
        for (int off = 16; off > 0; off >>= 1)
            mx = fmaxf(mx, __shfl_xor_sync(FULL, mx, off));
        float p[5], s = 0.f;
        #pragma unroll
        for (int i = 0; i < 5; i++) { p[i] = expf(lg[i] - mx); s += p[i]; }
        #pragma unroll
        for (int off = 16; off > 0; off >>= 1)
            s += __shfl_xor_sync(FULL, s, off);
        float inv = 1.f / s;
        float od = 0.f;
        #pragma unroll
        for (int i = 0; i < 5; i++) {
            float pi = p[i] * inv;
            #pragma unroll
            for (int l = 0; l < 32; l++) {
                float a = __shfl_sync(FULL, pi, l);
                int kk = l + 32 * i;
                if (kk < NC) od += a * vh[kk * 33 + lane];
            }
        }
        size_t idx = ((size_t)b * N4 + n) * CC + h * HD + lane;
        bf16 hh = __float2bfloat16(od);
        obh[idx] = hh;
        obl[idx] = __float2bfloat16(od - __bfloat162float(hh));
    }
}

// ---- out = base + LN(xin) ----
__global__ void ln_add_kernel(const float* __restrict__ base,
                              const float* __restrict__ xin,
                              const float* __restrict__ nw,
                              const float* __restrict__ nb,
                              float* __restrict__ out)
{
    __shared__ float sbuf[256];
    size_t row = blockIdx.x;
    int c = threadIdx.x;
    float v = xin[row * CC + c];
    float mean = block_reduce_sum(v, sbuf) * (1.f / CC);
    float d = v - mean;
    float var = block_reduce_sum(d * d, sbuf) * (1.f / CC);
    out[row * CC + c] = base[row * CC + c] + d * rsqrtf(var + 1e-5f) * nw[c] + nb[c];
}

// ---- out = base + LN(xin), + bf16 split ----
__global__ void ln_add_split_kernel(const float* __restrict__ base,
                                    const float* __restrict__ xin,
                                    const float* __restrict__ nw,
                                    const float* __restrict__ nb,
                                    float* __restrict__ out,
                                    bf16* __restrict__ ohi, bf16* __restrict__ olo)
{
    __shared__ float sbuf[256];
    size_t row = blockIdx.x;
    int c = threadIdx.x;
    float v = xin[row * CC + c];
    float mean = block_reduce_sum(v, sbuf) * (1.f / CC);
    float d = v - mean;
    float var = block_reduce_sum(d * d, sbuf) * (1.f / CC);
    float r = base[row * CC + c] + d * rsqrtf(var + 1e-5f) * nw[c] + nb[c];
    size_t idx = row * CC + c;
    out[idx] = r;
    bf16 h = __float2bfloat16(r);
    ohi[idx] = h;
    olo[idx] = __float2bfloat16(r - __bfloat162float(h));
}

// ---- depthwise conv + GELU -> bf16 hi/lo, 4 channels/thread ----
__global__ void dwconv_gelu_bf16_kernel(const float* __restrict__ h1,
                                        const float* __restrict__ dw_w,
                                        const float* __restrict__ dw_b,
                                        bf16* __restrict__ gh, bf16* __restrict__ gl)
{
    int idx = blockIdx.x * blockDim.x + threadIdx.x;
    if (idx >= BB * N4 * HID / 4) return;
    int c0 = (idx & (HID / 4 - 1)) * 4;
    int r = idx / (HID / 4);
    int n = r & (N4 - 1);
    int b = r >> 12;
    int y = n >> 6, x = n & 63;
    float4 acc = *(const float4*)(dw_b + c0);
    #pragma unroll
    for (int dy = 0; dy < 3; dy++) {
        int yy = y + dy - 1;
        if (yy < 0 || yy >= HH) continue;
        #pragma unroll
        for (int dx = 0; dx < 3; dx++) {
            int xx = x + dx - 1;
            if (xx < 0 || xx >= WW) continue;
            float4 v = *(const float4*)(h1 + ((size_t)b * N4 + yy * WW + xx) * HID + c0);
            int tap = dy * 3 + dx;
            acc.x += v.x * dw_w[(c0 + 0) * 9 + tap];
            acc.y += v.y * dw_w[(c0 + 1) * 9 + tap];
            acc.z += v.z * dw_w[(c0 + 2) * 9 + tap];
            acc.w += v.w * dw_w[(c0 + 3) * 9 + tap];
        }
    }
    float4 g;
    g.x = 0.5f * acc.x * (1.0f + erff(acc.x * 0.70710678118654752f));
    g.y = 0.5f * acc.y * (1.0f + erff(acc.y * 0.70710678118654752f));
    g.z = 0.5f * acc.z * (1.0f + erff(acc.z * 0.70710678118654752f));
    g.w = 0.5f * acc.w * (1.0f + erff(acc.w * 0.70710678118654752f));
    size_t o = (size_t)r * HID + c0;
    bf16 h0 = __float2bfloat16(g.x), h1b = __float2bfloat16(g.y);
    bf16 h2 = __float2bfloat16(g.z), h3 = __float2bfloat16(g.w);
    *(__nv_bfloat162*)(gh + o)     = __nv_bfloat162(h0, h1b);
    *(__nv_bfloat162*)(gh + o + 2) = __nv_bfloat162(h2, h3);
    *(__nv_bfloat162*)(gl + o) = __nv_bfloat162(
        __float2bfloat16(g.x - __bfloat162float(h0)),
        __float2bfloat16(g.y - __bfloat162float(h1b)));
    *(__nv_bfloat162*)(gl + o + 2) = __nv_bfloat162(
        __float2bfloat16(g.z - __bfloat162float(h2)),
        __float2bfloat16(g.w - __bfloat162float(h3)));
}

// ================= host launcher =================
#define SMEM_W4  92160
#define SMEM_W8  122880
#define SMEM_P2  92160   // pipe2 WNT=8: 3*(10240+20480)

extern "C" void kernel_launch(void* const* d_in, const int* in_sizes, int n_in,
                              void* d_out, int out_size)
{
    const float* x      = (const float*)d_in[0];
    const float* z      = (const float*)d_in[1];
    const float* mem    = (const float*)d_in[2];
    const float* cw     = (const float*)d_in[3];
    const float* p1     = (const float*)d_in[4];
    const float* tdt1   = (const float*)d_in[5];
    const float* p2     = (const float*)d_in[6];
    const float* tdt2   = (const float*)d_in[7];
    const float* alpha  = (const float*)d_in[8];
    const float* beta   = (const float*)d_in[9];
    const float* q_w    = (const float*)d_in[10];
    const float* q_b    = (const float*)d_in[11];
    const float* k_w    = (const float*)d_in[12];
    const float* k_b    = (const float*)d_in[13];
    const float* v_w    = (const float*)d_in[14];
    const float* v_b    = (const float*)d_in[15];
    const float* proj_w = (const float*)d_in[16];
    const float* proj_b = (const float*)d_in[17];
    const float* norm_w = (const float*)d_in[18];
    const float* norm_b = (const float*)d_in[19];
    const float* fc1_w  = (const float*)d_in[20];
    const float* fc1_b  = (const float*)d_in[21];
    const float* dw_w   = (const float*)d_in[22];
    const float* dw_b   = (const float*)d_in[23];
    const float* fc2_w  = (const float*)d_in[24];
    const float* fc2_b  = (const float*)d_in[25];

    float* out0 = (float*)d_out;
    float* cxz  = out0 + OUT0_ELEMS;
    float* ctr  = out0 + OUT0_ELEMS + CXZ_ELEMS;

    float *cl, *cz, *cc, *cen, *cinln, *kb, *vb, *qb, *oproj, *out1, *h1, *h2;
    bf16 *xh, *xl, *memh, *meml, *xth, *xtl, *memth, *memtl, *cwh, *cwl;
    bf16 *t1h, *t1l, *t2h, *t2l, *zth, *ztl, *clth, *cltl;
    bf16 *softh, *obh, *obl, *o1h, *o1l, *gh, *gl;
    bf16 *qwh, *qwl, *pwh, *pwl, *f1h, *f1l, *f2h, *f2l;
    cudaGetSymbolAddress((void**)&cl,    g_cl);
    cudaGetSymbolAddress((void**)&cz,    g_cz);
    cudaGetSymbolAddress((void**)&cc,    g_cc);
    cudaGetSymbolAddress((void**)&cen,   g_cen);
    cudaGetSymbolAddress((void**)&cinln, g_cinln);
    cudaGetSymbolAddress((void**)&kb,    g_kbuf);
    cudaGetSymbolAddress((void**)&vb,    g_vbuf);
    cudaGetSymbolAddress((void**)&qb,    g_q);
    cudaGetSymbolAddress((void**)&oproj, g_oproj);
    cudaGetSymbolAddress((void**)&out1,  g_out1);
    cudaGetSymbolAddress((void**)&h1,    g_h1);
    cudaGetSymbolAddress((void**)&h2,    g_h2);
    cudaGetSymbolAddress((void**)&xh,   g_xh);   cudaGetSymbolAddress((void**)&xl,   g_xl);
    cudaGetSymbolAddress((void**)&memh, g_memh); cudaGetSymbolAddress((void**)&meml, g_meml);
    cudaGetSymbolAddress((void**)&xth,  g_xth);  cudaGetSymbolAddress((void**)&xtl,  g_xtl);
    cudaGetSymbolAddress((void**)&memth, g_memth); cudaGetSymbolAddress((void**)&memtl, g_memtl);
    cudaGetSymbolAddress((void**)&cwh,  g_cwh);  cudaGetSymbolAddress((void**)&cwl,  g_cwl);
    cudaGetSymbolAddress((void**)&t1h,  g_t1h);  cudaGetSymbolAddress((void**)&t1l,  g_t1l);
    cudaGetSymbolAddress((void**)&t2h,  g_t2h);  cudaGetSymbolAddress((void**)&t2l,  g_t2l);
    cudaGetSymbolAddress((void**)&zth,  g_zth);  cudaGetSymbolAddress((void**)&ztl,  g_ztl);
    cudaGetSymbolAddress((void**)&clth, g_clth); cudaGetSymbolAddress((void**)&cltl, g_cltl);
    cudaGetSymbolAddress((void**)&softh, g_softh);
    cudaGetSymbolAddress((void**)&obh, g_obh); cudaGetSymbolAddress((void**)&obl, g_obl);
    cudaGetSymbolAddress((void**)&o1h, g_o1h); cudaGetSymbolAddress((void**)&o1l, g_o1l);
    cudaGetSymbolAddress((void**)&gh,  g_gh);  cudaGetSymbolAddress((void**)&gl,  g_gl);
    cudaGetSymbolAddress((void**)&qwh, g_qwh); cudaGetSymbolAddress((void**)&qwl, g_qwl);
    cudaGetSymbolAddress((void**)&pwh, g_pwh); cudaGetSymbolAddress((void**)&pwl, g_pwl);
    cudaGetSymbolAddress((void**)&f1h, g_f1h); cudaGetSymbolAddress((void**)&f1l, g_f1l);
    cudaGetSymbolAddress((void**)&f2h, g_f2h); cudaGetSymbolAddress((void**)&f2l, g_f2l);

    cudaFuncSetAttribute(hmma_gemm_kernel<4>,
                         cudaFuncAttributeMaxDynamicSharedMemorySize, SMEM_W4);
    cudaFuncSetAttribute(hmma_gemm_kernel<8>,
                         cudaFuncAttributeMaxDynamicSharedMemorySize, SMEM_W8);
    cudaFuncSetAttribute(cl_hmma_kernel,
                         cudaFuncAttributeMaxDynamicSharedMemorySize, SMEM_W8);
    cudaFuncSetAttribute(cen_hmma_kernel,
                         cudaFuncAttributeMaxDynamicSharedMemorySize, SMEM_P2);
    cudaFuncSetAttribute(comb_hmma_kernel,
                         cudaFuncAttributeMaxDynamicSharedMemorySize, SMEM_W4);

    // 0) prep
    split_all_kernel<<<dim3(128, 8, 2), dim3(32, 8)>>>(x, xh, xl, xth, xtl);
    split_all_kernel<<<dim3(128, 8, 6), dim3(32, 8)>>>(mem, memh, meml, memth, memtl);
    cvt_split5_kernel<<<dim3(256, 5), 256>>>(
        q_w, qwh, qwl, 65536,
        proj_w, pwh, pwl, 65536,
        fc1_w, f1h, f1l, 262144,
        fc2_w, f2h, f2l, 262144,
        cw, cwh, cwl, 38400);
    tdt_prep_kernel<<<100, 256>>>(tdt1, tdt2, t1h, t1l, t2h, t2l);
    zT_split_kernel<<<dim3(512, 5, 2), dim3(32, 8)>>>(z, zth, ztl);

    // 1) cl (HMMA)
    cl_hmma_kernel<<<dim3(32, 2, 8), 256, SMEM_W8>>>(cwh, cwl, xh, xl, memh, meml, cl);
    // 2) prompt cos -> scale vectors; clT split
    prompt_scale_kernel<<<dim3(TNE / 1024, 1, BB), 256>>>(z, cl, p1, p2, cz, cc);
    clT_split_kernel<<<dim3(128, 5, 8), dim3(32, 8)>>>(cl, clth, cltl);
    // 3) combine (HMMA) -> cluster_x_z + center
    comb_hmma_kernel<<<dim3(256, 2, 2), 256, SMEM_W4>>>(
        t1h, t1l, t2h, t2l, zth, ztl, clth, cltl, cz, cc, cxz, ctr);
    // 4) softmax -> bf16 hi only
    softmax_kernel<<<BB * TT4 * NC, 256>>>(cxz, softh);
    // 5) cen (HMMA 2-term, split-K atomic)
    zero_cen_kernel<<<(307200 + 255) / 256, 256>>>(cen);
    cen_hmma_kernel<<<dim3(2, 2, 64), 256, SMEM_P2>>>(softh, xth, xtl, memth, memtl, cen);
    // 6) gating + LN
    cin_kernel<<<BB * NC, 256>>>(cen, alpha, beta, norm_w, norm_b, cinln);
    // 7) k/v projections (merged)
    gemm_kv_kernel<<<dim3(4, 5, 2), 256>>>(cinln, k_w, k_b, v_w, v_b, kb, vb);
    // 8) q projection
    hmma_gemm_kernel<4><<<dim3(4, 64), 256, SMEM_W4>>>(
        xh, xl, qwh, qwl, q_b, qb, CC, CC, 0.17677669529663687f);
    // 9) attention -> bf16 split
    attn_kernel<<<dim3(N4 / 256, NH, BB), 256>>>(qb, kb, vb, obh, obl);
    // 10) output projection
    hmma_gemm_kernel<4><<<dim3(4, 64), 256, SMEM_W4>>>(
        obh, obl, pwh, pwl, proj_b, oproj, CC, CC, 1.f);
    // 11) out1 = x + LN(oproj), + split
    ln_add_split_kernel<<<BB * N4, 256>>>(x, oproj, norm_w, norm_b, out1, o1h, o1l);
    // 12) fc1
    hmma_gemm_kernel<8><<<dim3(8, 64), 256, SMEM_W8>>>(
        o1h, o1l, f1h, f1l, fc1_b, h1, HID, CC, 1.f);
    // 13) depthwise conv + gelu -> split
    dwconv_gelu_bf16_kernel<<<(BB * N4 * HID / 4 + 255) / 256, 256>>>(h1, dw_w, dw_b, gh, gl);
    // 14) fc2
    hmma_gemm_kernel<4><<<dim3(4, 64), 256, SMEM_W4>>>(
        gh, gl, f2h, f2l, fc2_b, h2, CC, HID, 1.f);
    // 15) out = out1 + LN(h2)
    ln_add_kernel<<<BB * N4, 256>>>(out1, h2, norm_w, norm_b, out0);
}

// round 12
// speedup vs baseline: 1.0044x; 1.0044x over previous
#include <cuda_runtime.h>
#include <cuda_bf16.h>
#include <math.h>
#include <stdint.h>

typedef __nv_bfloat16 bf16;

// ---------------- fixed problem dims ----------------
#define BB   2
#define TT4  4
#define N4   4096
#define CC   256
#define NC   150
#define TNE  16384
#define HID  1024
#define NH   8
#define HD   32
#define HH   64
#define WW   64
#define KPAD 160

#define OUT0_ELEMS 2097152
#define CXZ_ELEMS  4915200

// ---------------- scratch ----------------
__device__ float g_cl[4915200];
__device__ float g_cz[32768], g_cc[32768];
__device__ float g_cen[307200];
__device__ float g_cinln[76800];
__device__ float g_kbuf[76800];
__device__ float g_vbuf[76800];
__device__ float g_q[2097152];
__device__ float g_oproj[2097152];
__device__ float g_out1[2097152];
__device__ float g_h1[8388608];
__device__ float g_h2[2097152];

// bf16 hi/lo split buffers
__device__ bf16 g_xh[2097152],   g_xl[2097152];
__device__ bf16 g_memh[6291456], g_meml[6291456];
__device__ bf16 g_xth[2097152],  g_xtl[2097152];
__device__ bf16 g_memth[6291456], g_memtl[6291456];
__device__ bf16 g_cwh[38400],    g_cwl[38400];
__device__ bf16 g_t1h[25600], g_t1l[25600], g_t2h[25600], g_t2l[25600];
__device__ bf16 g_zth[5242880],  g_ztl[5242880];
__device__ bf16 g_clth[5242880], g_cltl[5242880];
__device__ bf16 g_softh[4915200], g_softl[4915200];
__device__ bf16 g_obh[2097152], g_obl[2097152];
__device__ bf16 g_o1h[2097152], g_o1l[2097152];
__device__ bf16 g_gh[8388608],  g_gl[8388608];
__device__ bf16 g_qwh[65536],  g_qwl[65536];
__device__ bf16 g_pwh[65536],  g_pwl[65536];
__device__ bf16 g_f1h[262144], g_f1l[262144];
__device__ bf16 g_f2h[262144], g_f2l[262144];

// ---------------- warp-level bf16 MMA + cp.async ----------
__device__ __forceinline__ void mma16816(float* d, const uint32_t* a, const uint32_t* b) {
    asm volatile(
        "mma.sync.aligned.m16n8k16.row.col.f32.bf16.bf16.f32 "
        "{%0,%1,%2,%3}, {%4,%5,%6,%7}, {%8,%9}, {%0,%1,%2,%3};\n"
        : "+f"(d[0]), "+f"(d[1]), "+f"(d[2]), "+f"(d[3])
        : "r"(a[0]), "r"(a[1]), "r"(a[2]), "r"(a[3]), "r"(b[0]), "r"(b[1]));
}
__device__ __forceinline__ uint32_t smem_to_u32(const void* p) {
    uint32_t a;
    asm("{ .reg .u64 t; cvta.to.shared.u64 t, %1; cvt.u32.u64 %0, t; }"
        : "=r"(a) : "l"(p));
    return a;
}
__device__ __forceinline__ void cp_async16(uint32_t s, const void* g, bool v) {
    int sz = v ? 16 : 0;
    asm volatile("cp.async.cg.shared.global [%0], [%1], 16, %2;\n"
                 :: "r"(s), "l"(g), "r"(sz));
}
__device__ __forceinline__ void cp_commit() {
    asm volatile("cp.async.commit_group;\n" ::: "memory");
}
template<int N> __device__ __forceinline__ void cp_wait() {
    asm volatile("cp.async.wait_group %0;\n" :: "n"(N) : "memory");
}

#define SAS 40

// inner compute: WNT n-subtiles per warp, one 32-deep K chunk, 3-term split
template<int WNT>
__device__ __forceinline__ void hmma_chunk(
    bf16 (*sAh)[SAS], bf16 (*sAl)[SAS], bf16 (*sBh)[SAS], bf16 (*sBl)[SAS],
    int wm, int wn, int g, int tg, float (*acc)[WNT][4])
{
    #pragma unroll
    for (int ks = 0; ks < 2; ks++) {
        int kc = ks * 16 + tg * 2;
        uint32_t ah[2][4], al[2][4], bh[WNT][2], bl[WNT][2];
        #pragma unroll
        for (int mt = 0; mt < 2; mt++) {
            int r = wm * 32 + mt * 16 + g;
            ah[mt][0] = *(const uint32_t*)&sAh[r][kc];
            ah[mt][1] = *(const uint32_t*)&sAh[r + 8][kc];
            ah[mt][2] = *(const uint32_t*)&sAh[r][kc + 8];
            ah[mt][3] = *(const uint32_t*)&sAh[r + 8][kc + 8];
            al[mt][0] = *(const uint32_t*)&sAl[r][kc];
            al[mt][1] = *(const uint32_t*)&sAl[r + 8][kc];
            al[mt][2] = *(const uint32_t*)&sAl[r][kc + 8];
            al[mt][3] = *(const uint32_t*)&sAl[r + 8][kc + 8];
        }
        #pragma unroll
        for (int nt = 0; nt < WNT; nt++) {
            int nr = wn * (WNT * 8) + nt * 8 + g;
            bh[nt][0] = *(const uint32_t*)&sBh[nr][kc];
            bh[nt][1] = *(const uint32_t*)&sBh[nr][kc + 8];
            bl[nt][0] = *(const uint32_t*)&sBl[nr][kc];
            bl[nt][1] = *(const uint32_t*)&sBl[nr][kc + 8];
        }
        #pragma unroll
        for (int mt = 0; mt < 2; mt++)
            #pragma unroll
            for (int nt = 0; nt < WNT; nt++) {
                mma16816(acc[mt][nt], ah[mt], bh[nt]);
                mma16816(acc[mt][nt], ah[mt], bl[nt]);
                mma16816(acc[mt][nt], al[mt], bh[nt]);
            }
    }
}

// ---- 3-stage cp.async pipelined mainloop ----
template<int WNT, typename F>
__device__ __forceinline__ void hmma_pipe(char* sm, int nk, F getp, float (*acc)[WNT][4])
{
    constexpr int BN = 16 * WNT;
    constexpr int ASZ = 128 * SAS * 2;
    constexpr int BSZ = BN * SAS * 2;
    constexpr int STG = 2 * ASZ + 2 * BSZ;
    int tid = threadIdx.x;
    int wid = tid >> 5, lane = tid & 31;
    int wm = wid & 3, wn = wid >> 2, g = lane >> 2, tg = lane & 3;
    int lrow = tid >> 1, lhalf = (tid & 1) * 16;
    bool bload = (WNT == 8) || (tid < BN * 2);
    uint32_t sb = smem_to_u32(sm);
    uint32_t off = (uint32_t)(lrow * SAS + lhalf) * 2;

    __syncthreads();

    auto issue = [&](int c) {
        uint32_t st = sb + (c % 3) * STG;
        const bf16 *ah, *al, *bh, *bl; bool av;
        getp(c, ah, al, bh, bl, av);
        cp_async16(st + off, ah, av);
        cp_async16(st + off + 16, ah + 8, av);
        cp_async16(st + ASZ + off, al, av);
        cp_async16(st + ASZ + off + 16, al + 8, av);
        if (bload) {
            cp_async16(st + 2 * ASZ + off, bh, true);
            cp_async16(st + 2 * ASZ + off + 16, bh + 8, true);
            cp_async16(st + 2 * ASZ + BSZ + off, bl, true);
            cp_async16(st + 2 * ASZ + BSZ + off + 16, bl + 8, true);
        }
        cp_commit();
    };

    issue(0); issue(1);
    for (int c = 0; c < nk; c++) {
        if (c + 2 <= nk) cp_wait<1>(); else cp_wait<0>();
        __syncthreads();
        {
            char* st = sm + (c % 3) * STG;
            bf16 (*sAh)[SAS] = (bf16(*)[SAS])st;
            bf16 (*sAl)[SAS] = (bf16(*)[SAS])(st + ASZ);
            bf16 (*sBh)[SAS] = (bf16(*)[SAS])(st + 2 * ASZ);
            bf16 (*sBl)[SAS] = (bf16(*)[SAS])(st + 2 * ASZ + BSZ);
            hmma_chunk<WNT>(sAh, sAl, sBh, sBl, wm, wn, g, tg, acc);
        }
        if (c + 2 < nk) issue(c + 2);
    }
}

// ================= HMMA GEMM (q/proj/fc1/fc2) ============
template<int WNT>
__global__ void __launch_bounds__(256)
hmma_gemm_kernel(const bf16* __restrict__ Ah, const bf16* __restrict__ Al,
                 const bf16* __restrict__ Bh, const bf16* __restrict__ Bl,
                 const float* __restrict__ bias, float* __restrict__ C,
                 int Ntot, int K, float scale)
{
    extern __shared__ char sm[];
    constexpr int BN = 16 * WNT;
    int tid = threadIdx.x, wid = tid >> 5, lane = tid & 31;
    int wm = wid & 3, wn = wid >> 2, g = lane >> 2, tg = lane & 3;
    int m0 = blockIdx.y * 128, n0 = blockIdx.x * BN;
    int lrow = tid >> 1, lhalf = (tid & 1) * 16;

    float acc[2][WNT][4] = {};
    auto getp = [&](int c, const bf16*& ah, const bf16*& al,
                    const bf16*& bh, const bf16*& bl, bool& av) {
        int k0 = (c << 5) + lhalf;
        ah = Ah + (size_t)(m0 + lrow) * K + k0;
        al = Al + (size_t)(m0 + lrow) * K + k0;
        bh = Bh + (size_t)(n0 + lrow) * K + k0;
        bl = Bl + (size_t)(n0 + lrow) * K + k0;
        av = true;
    };
    hmma_pipe<WNT>(sm, K >> 5, getp, acc);

    #pragma unroll
    for (int mt = 0; mt < 2; mt++) {
        int r0 = m0 + wm * 32 + mt * 16 + g;
        #pragma unroll
        for (int nt = 0; nt < WNT; nt++) {
            int col = n0 + wn * (WNT * 8) + nt * 8 + tg * 2;
            float b0 = bias[col], b1 = bias[col + 1];
            float2 v0, v1;
            v0.x = (acc[mt][nt][0] + b0) * scale;
            v0.y = (acc[mt][nt][1] + b1) * scale;
            v1.x = (acc[mt][nt][2] + b0) * scale;
            v1.y = (acc[mt][nt][3] + b1) * scale;
            *(float2*)&C[(size_t)r0 * Ntot + col] = v0;
            *(float2*)&C[(size_t)(r0 + 8) * Ntot + col] = v1;
        }
    }
}

// ================= cl HMMA =================
__global__ void __launch_bounds__(256)
cl_hmma_kernel(const bf16* __restrict__ cwh, const bf16* __restrict__ cwl,
               const bf16* __restrict__ xh, const bf16* __restrict__ xl,
               const bf16* __restrict__ memh, const bf16* __restrict__ meml,
               float* __restrict__ cl)
{
    extern __shared__ char sm[];
    int bt = blockIdx.z, b = bt >> 2, t = bt & 3;
    const bf16* Bh = (t < 3) ? memh + (size_t)(b * 3 + t) * 1048576 : xh + (size_t)b * 1048576;
    const bf16* Bl = (t < 3) ? meml + (size_t)(b * 3 + t) * 1048576 : xl + (size_t)b * 1048576;
    float* Cp = cl + (size_t)bt * 614400;

    int tid = threadIdx.x, wid = tid >> 5, lane = tid & 31;
    int wm = wid & 3, wn = wid >> 2, g = lane >> 2, tg = lane & 3;
    int m0 = blockIdx.y * 128, n0 = blockIdx.x * 128;
    int lrow = tid >> 1, lhalf = (tid & 1) * 16;
    bool aval = (m0 + lrow) < NC;

    float acc[2][8][4] = {};
    auto getp = [&](int c, const bf16*& ah, const bf16*& al,
                    const bf16*& bh, const bf16*& bl, bool& av) {
        int k0 = (c << 5) + lhalf;
        ah = cwh + (size_t)(m0 + lrow) * CC + k0;
        al = cwl + (size_t)(m0 + lrow) * CC + k0;
        bh = Bh + (size_t)(n0 + lrow) * CC + k0;
        bl = Bl + (size_t)(n0 + lrow) * CC + k0;
        av = aval;
    };
    hmma_pipe<8>(sm, 8, getp, acc);

    #pragma unroll
    for (int mt = 0; mt < 2; mt++) {
        int r0 = m0 + wm * 32 + mt * 16 + g;
        #pragma unroll
        for (int nt = 0; nt < 8; nt++) {
            int col = n0 + wn * 64 + nt * 8 + tg * 2;
            if (r0 < NC)
                *(float2*)&Cp[(size_t)r0 * N4 + col] = make_float2(acc[mt][nt][0], acc[mt][nt][1]);
            if (r0 + 8 < NC)
                *(float2*)&Cp[(size_t)(r0 + 8) * N4 + col] = make_float2(acc[mt][nt][2], acc[mt][nt][3]);
        }
    }
}

// ================= comb HMMA =================
__global__ void __launch_bounds__(256)
comb_hmma_kernel(const bf16* __restrict__ t1h, const bf16* __restrict__ t1l,
                 const bf16* __restrict__ t2h, const bf16* __restrict__ t2l,
                 const bf16* __restrict__ zth, const bf16* __restrict__ ztl,
                 const bf16* __restrict__ clth, const bf16* __restrict__ cltl,
                 const float* __restrict__ cz, const float* __restrict__ cc,
                 float* __restrict__ cxz, float* __restrict__ ctr)
{
    extern __shared__ char sm[];
    int b = blockIdx.z;
    int j0 = blockIdx.y * 128, n0 = blockIdx.x * 64;
    int tid = threadIdx.x, wid = tid >> 5, lane = tid & 31;
    int wm = wid & 3, wn = wid >> 2, g = lane >> 2, tg = lane & 3;
    int lrow = tid >> 1, lhalf = (tid & 1) * 16;
    bool aval = (j0 + lrow) < KPAD;

    float acc1[2][4][4] = {}, acc2[2][4][4] = {};
    const bf16* Bz_h = zth + (size_t)b * TNE * KPAD;
    const bf16* Bz_l = ztl + (size_t)b * TNE * KPAD;
    const bf16* Bc_h = clth + (size_t)b * TNE * KPAD;
    const bf16* Bc_l = cltl + (size_t)b * TNE * KPAD;

    auto getp1 = [&](int c, const bf16*& ah, const bf16*& al,
                     const bf16*& bh, const bf16*& bl, bool& av) {
        int k0 = (c << 5) + lhalf;
        ah = t1h + (size_t)(j0 + lrow) * KPAD + k0;
        al = t1l + (size_t)(j0 + lrow) * KPAD + k0;
        bh = Bz_h + (size_t)(n0 + lrow) * KPAD + k0;
        bl = Bz_l + (size_t)(n0 + lrow) * KPAD + k0;
        av = aval;
    };
    hmma_pipe<4>(sm, 5, getp1, acc1);
    auto getp2 = [&](int c, const bf16*& ah, const bf16*& al,
                     const bf16*& bh, const bf16*& bl, bool& av) {
        int k0 = (c << 5) + lhalf;
        ah = t2h + (size_t)(j0 + lrow) * KPAD + k0;
        al = t2l + (size_t)(j0 + lrow) * KPAD + k0;
        bh = Bc_h + (size_t)(n0 + lrow) * KPAD + k0;
        bl = Bc_l + (size_t)(n0 + lrow) * KPAD + k0;
        av = aval;
    };
    hmma_pipe<4>(sm, 5, getp2, acc2);

    #pragma unroll
    for (int mt = 0; mt < 2; mt++) {
        int r0 = j0 + wm * 32 + mt * 16 + g;
        #pragma unroll
        for (int nt = 0; nt < 4; nt++) {
            int col = n0 + wn * 32 + nt * 8 + tg * 2;
            float s0z = cz[(size_t)b * TNE + col],     s1z = cz[(size_t)b * TNE + col + 1];
            float s0c = cc[(size_t)b * TNE + col],     s1c = cc[(size_t)b * TNE + col + 1];
            int t = col >> 12, n = col & 4095;
            if (r0 < NC) {
                float2 v;
                v.x = s0z * acc1[mt][nt][0] + s0c * acc2[mt][nt][0];
                v.y = s1z * acc1[mt][nt][1] + s1c * acc2[mt][nt][1];
                *(float2*)&cxz[((size_t)b * NC + r0) * TNE + col] = v;
                *(float2*)&ctr[((size_t)(b * TT4 + t) * NC + r0) * N4 + n] = v;
            }
            if (r0 + 8 < NC) {
                float2 v;
                v.x = s0z * acc1[mt][nt][2] + s0c * acc2[mt][nt][2];
                v.y = s1z * acc1[mt][nt][3] + s1c * acc2[mt][nt][3];
                *(float2*)&cxz[((size_t)b * NC + r0 + 8) * TNE + col] = v;
                *(float2*)&ctr[((size_t)(b * TT4 + t) * NC + r0 + 8) * N4 + n] = v;
            }
        }
    }
}

// ================= cen HMMA (3-term, split-K, atomic) =================
__global__ void __launch_bounds__(256)
cen_hmma_kernel(const bf16* __restrict__ softh, const bf16* __restrict__ softl,
                const bf16* __restrict__ xth, const bf16* __restrict__ xtl,
                const bf16* __restrict__ memth, const bf16* __restrict__ memtl,
                float* __restrict__ cen)
{
    extern __shared__ char sm[];
    int bt = blockIdx.z >> 3, sp = blockIdx.z & 7;
    int b = bt >> 2, t = bt & 3;
    const bf16* Ah = softh + (size_t)bt * 614400;
    const bf16* Al = softl + (size_t)bt * 614400;
    const bf16* Bh = (t < 3) ? memth + (size_t)(b * 3 + t) * 1048576 : xth + (size_t)b * 1048576;
    const bf16* Bl = (t < 3) ? memtl + (size_t)(b * 3 + t) * 1048576 : xtl + (size_t)b * 1048576;
    float* Cp = cen + (size_t)bt * 38400;
    int koff = sp * 512;

    int tid = threadIdx.x, wid = tid >> 5, lane = tid & 31;
    int wm = wid & 3, wn = wid >> 2, g = lane >> 2, tg = lane & 3;
    int m0 = blockIdx.y * 128, n0 = blockIdx.x * 128;
    int lrow = tid >> 1, lhalf = (tid & 1) * 16;
    bool aval = (m0 + lrow) < NC;

    float acc[2][8][4] = {};
    auto getp = [&](int c, const bf16*& ah, const bf16*& al,
                    const bf16*& bh, const bf16*& bl, bool& av) {
        int k0 = koff + (c << 5) + lhalf;
        ah = Ah + (size_t)(m0 + lrow) * N4 + k0;
        al = Al + (size_t)(m0 + lrow) * N4 + k0;
        bh = Bh + (size_t)(n0 + lrow) * N4 + k0;
        bl = Bl + (size_t)(n0 + lrow) * N4 + k0;
        av = aval;
    };
    hmma_pipe<8>(sm, 16, getp, acc);

    #pragma unroll
    for (int mt = 0; mt < 2; mt++) {
        int r0 = m0 + wm * 32 + mt * 16 + g;
        #pragma unroll
        for (int nt = 0; nt < 8; nt++) {
            int col = n0 + wn * 64 + nt * 8 + tg * 2;
            if (r0 < NC) {
                atomicAdd(&Cp[(size_t)r0 * CC + col], acc[mt][nt][0]);
                atomicAdd(&Cp[(size_t)r0 * CC + col + 1], acc[mt][nt][1]);
            }
            if (r0 + 8 < NC) {
                atomicAdd(&Cp[(size_t)(r0 + 8) * CC + col], acc[mt][nt][2]);
                atomicAdd(&Cp[(size_t)(r0 + 8) * CC + col + 1], acc[mt][nt][3]);
            }
        }
    }
}

// ---------------- splits ----------------
__device__ __forceinline__ void split_store4(const float4 v, bf16* hi, bf16* lo, int i) {
    bf16 h0 = __float2bfloat16(v.x), h1 = __float2bfloat16(v.y);
    bf16 h2 = __float2bfloat16(v.z), h3 = __float2bfloat16(v.w);
    *(__nv_bfloat162*)(hi + i)     = __nv_bfloat162(h0, h1);
    *(__nv_bfloat162*)(hi + i + 2) = __nv_bfloat162(h2, h3);
    *(__nv_bfloat162*)(lo + i) = __nv_bfloat162(
        __float2bfloat16(v.x - __bfloat162float(h0)),
        __float2bfloat16(v.y - __bfloat162float(h1)));
    *(__nv_bfloat162*)(lo + i + 2) = __nv_bfloat162(
        __float2bfloat16(v.z - __bfloat162float(h2)),
        __float2bfloat16(v.w - __bfloat162float(h3)));
}
__global__ void cvt_split5_kernel(
    const float* a0, bf16* h0, bf16* l0, int s0,
    const float* a1, bf16* h1, bf16* l1, int s1,
    const float* a2, bf16* h2, bf16* l2, int s2,
    const float* a3, bf16* h3, bf16* l3, int s3,
    const float* a4, bf16* h4, bf16* l4, int s4)
{
    const float* in; bf16 *hi, *lo; int n;
    switch (blockIdx.y) {
        case 0: in = a0; hi = h0; lo = l0; n = s0; break;
        case 1: in = a1; hi = h1; lo = l1; n = s1; break;
        case 2: in = a2; hi = h2; lo = l2; n = s2; break;
        case 3: in = a3; hi = h3; lo = l3; n = s3; break;
        default: in = a4; hi = h4; lo = l4; n = s4; break;
    }
    int i = (blockIdx.x * 256 + threadIdx.x) * 4;
    if (i >= n) return;
    split_store4(*(const float4*)(in + i), hi, lo, i);
}

// ---- split + transpose-split in one pass ----
__global__ void split_all_kernel(const float* __restrict__ in,
                                 bf16* __restrict__ oh, bf16* __restrict__ ol,
                                 bf16* __restrict__ toh, bf16* __restrict__ tol)
{
    __shared__ float tile[32][33];
    const float* src = in + (size_t)blockIdx.z * 1048576;
    bf16* doh = oh + (size_t)blockIdx.z * 1048576;
    bf16* dol = ol + (size_t)blockIdx.z * 1048576;
    bf16* dth = toh + (size_t)blockIdx.z * 1048576;
    bf16* dtl = tol + (size_t)blockIdx.z * 1048576;
    int tx = threadIdx.x, ty = threadIdx.y;
    int r0 = blockIdx.x * 32, c0 = blockIdx.y * 32;
    #pragma unroll
    for (int i = 0; i < 4; i++) {
        int r = r0 + ty + i * 8;
        float v = src[(size_t)r * CC + c0 + tx];
        tile[ty + i * 8][tx] = v;
        bf16 h = __float2bfloat16(v);
        doh[(size_t)r * CC + c0 + tx] = h;
        dol[(size_t)r * CC + c0 + tx] = __float2bfloat16(v - __bfloat162float(h));
    }
    __syncthreads();
    #pragma unroll
    for (int i = 0; i < 4; i++) {
        int c = c0 + ty + i * 8;
        float v = tile[tx][ty + i * 8];
        bf16 h = __float2bfloat16(v);
        dth[(size_t)c * N4 + r0 + tx] = h;
        dtl[(size_t)c * N4 + r0 + tx] = __float2bfloat16(v - __bfloat162float(h));
    }
}

// ---- zT split ----
__global__ void zT_split_kernel(const float* __restrict__ z,
                                bf16* __restrict__ oh, bf16* __restrict__ ol)
{
    __shared__ float tile[32][33];
    int b = blockIdx.z;
    int m0 = blockIdx.x * 32, k0 = blockIdx.y * 32;
    int tx = threadIdx.x, ty = threadIdx.y;
    #pragma unroll
    for (int i = 0; i < 4; i++) {
        int k = k0 + ty + i * 8;
        tile[ty + i * 8][tx] = (k < NC) ? z[((size_t)b * NC + k) * TNE + m0 + tx] : 0.f;
    }
    __syncthreads();
    #pragma unroll
    for (int i = 0; i < 4; i++) {
        int m = m0 + ty + i * 8;
        float v = tile[tx][ty + i * 8];
        bf16 h = __float2bfloat16(v);
        size_t idx = ((size_t)b * TNE + m) * KPAD + k0 + tx;
        oh[idx] = h;
        ol[idx] = __float2bfloat16(v - __bfloat162float(h));
    }
}

// ---- clT split ----
__global__ void clT_split_kernel(const float* __restrict__ cl,
                                 bf16* __restrict__ oh, bf16* __restrict__ ol)
{
    __shared__ float tile[32][33];
    int bt = blockIdx.z, b = bt >> 2, t = bt & 3;
    int n0 = blockIdx.x * 32, k0 = blockIdx.y * 32;
    int tx = threadIdx.x, ty = threadIdx.y;
    const float* src = cl + (size_t)bt * 614400;
    #pragma unroll
    for (int i = 0; i < 4; i++) {
        int k = k0 + ty + i * 8;
        tile[ty + i * 8][tx] = (k < NC) ? src[(size_t)k * N4 + n0 + tx] : 0.f;
    }
    __syncthreads();
    #pragma unroll
    for (int i = 0; i < 4; i++) {
        int n = n0 + ty + i * 8;
        float v = tile[tx][ty + i * 8];
        bf16 h = __float2bfloat16(v);
        size_t idx = ((size_t)b * TNE + t * N4 + n) * KPAD + k0 + tx;
        oh[idx] = h;
        ol[idx] = __float2bfloat16(v - __bfloat162float(h));
    }
}

// ---- tdt^T padded split ----
__global__ void tdt_prep_kernel(const float* __restrict__ tdt1, const float* __restrict__ tdt2,
                                bf16* __restrict__ t1h, bf16* __restrict__ t1l,
                                bf16* __restrict__ t2h, bf16* __restrict__ t2l)
{
    int i = blockIdx.x * 256 + threadIdx.x;
    if (i >= KPAD * KPAD) return;
    int j = i / KPAD, k = i % KPAD;
    float v1 = (j < NC && k < NC) ? tdt1[k * NC + j] : 0.f;
    float v2 = (j < NC && k < NC) ? tdt2[k * NC + j] : 0.f;
    bf16 h1 = __float2bfloat16(v1), h2 = __float2bfloat16(v2);
    t1h[i] = h1; t1l[i] = __float2bfloat16(v1 - __bfloat162float(h1));
    t2h[i] = h2; t2l[i] = __float2bfloat16(v2 - __bfloat162float(h2));
}

// ---------------- helpers ----------------
__device__ __forceinline__ float block_reduce_sum(float v, float* sbuf) {
    int tid = threadIdx.x;
    sbuf[tid] = v; __syncthreads();
    for (int s = blockDim.x >> 1; s > 0; s >>= 1) {
        if (tid < s) sbuf[tid] += sbuf[tid + s];
        __syncthreads();
    }
    float r = sbuf[0]; __syncthreads();
    return r;
}
__device__ __forceinline__ float block_reduce_max(float v, float* sbuf) {
    int tid = threadIdx.x;
    sbuf[tid] = v; __syncthreads();
    for (int s = blockDim.x >> 1; s > 0; s >>= 1) {
        if (tid < s) sbuf[tid] = fmaxf(sbuf[tid], sbuf[tid + s]);
        __syncthreads();
    }
    float r = sbuf[0]; __syncthreads();
    return r;
}

// ======== merged k/v projection ====
#define OBM 64
#define OBN 64
#define OBK 16
__global__ void gemm_kv_kernel(const float* __restrict__ A,
                               const float* __restrict__ k_w, const float* __restrict__ k_b,
                               const float* __restrict__ v_w, const float* __restrict__ v_b,
                               float* __restrict__ kout, float* __restrict__ vout)
{
    const float* B = blockIdx.z ? v_w : k_w;
    const float* bias = blockIdx.z ? v_b : k_b;
    float* C = blockIdx.z ? vout : kout;
    const int M = BB * NC;
    __shared__ float As[OBK][OBM];
    __shared__ float Bs[OBK][OBN];
    int tid = threadIdx.x;
    int tx = tid & 15, ty = tid >> 4;
    int m0 = blockIdx.y * OBM, n0 = blockIdx.x * OBN;
    float acc[4][4] = {};
    for (int k0 = 0; k0 < CC; k0 += OBK) {
        #pragma unroll
        for (int j = 0; j < 4; j++) {
            int idx = tid + j * 256;
            int ml = idx / OBK, kl = idx % OBK;
            int m = m0 + ml;
            As[kl][ml] = (m < M) ? A[(size_t)m * CC + k0 + kl] : 0.f;
        }
        #pragma unroll
        for (int j = 0; j < 4; j++) {
            int idx = tid + j * 256;
            int nl = idx / OBK, kl = idx % OBK;
            Bs[kl][nl] = B[(size_t)(n0 + nl) * CC + k0 + kl];
        }
        __syncthreads();
        #pragma unroll
        for (int kk = 0; kk < OBK; kk++) {
            float a[4], b[4];
            *(float4*)a = *(const float4*)&As[kk][ty * 4];
            *(float4*)b = *(const float4*)&Bs[kk][tx * 4];
            #pragma unroll
            for (int i = 0; i < 4; i++)
                #pragma unroll
                for (int j = 0; j < 4; j++)
                    acc[i][j] += a[i] * b[j];
        }
        __syncthreads();
    }
    #pragma unroll
    for (int i = 0; i < 4; i++) {
        int m = m0 + ty * 4 + i;
        if (m >= M) continue;
        #pragma unroll
        for (int j = 0; j < 4; j++) {
            int n = n0 + tx * 4 + j;
            C[(size_t)m * CC + n] = acc[i][j] + bias[n];
        }
    }
}

// ---- prompt cos -> cz/cc scale vectors (scalar, 128 CTAs) ----
__global__ void prompt_scale_kernel(const float* __restrict__ z,
                                    const float* __restrict__ cl,
                                    const float* __restrict__ p1,
                                    const float* __restrict__ p2,
                                    float* __restrict__ cz,
                                    float* __restrict__ cc)
{
    int m = blockIdx.x * blockDim.x + threadIdx.x;
    int b = blockIdx.z;
    if (m >= TNE) return;
    int t = m >> 12, n = m & 4095;
    const float* zrow = z + (size_t)b * NC * TNE + m;
    const float* crow = cl + ((size_t)(b * TT4 + t) * NC) * N4 + n;
    float dz = 0, nz = 0, dc = 0, ncs = 0, p1n = 0, p2n = 0;
    for (int k = 0; k < NC; k++) {
        float zv = zrow[(size_t)k * TNE];
        float cv = crow[(size_t)k * N4];
        float a = p1[k], bb = p2[k];
        dz += zv * a; nz += zv * zv; p1n += a * a;
        dc += cv * bb; ncs += cv * cv; p2n += bb * bb;
    }
    float vz = dz / (fmaxf(sqrtf(nz), 1e-12f) * fmaxf(sqrtf(p1n), 1e-12f));
    float vc = dc / (fmaxf(sqrtf(ncs), 1e-12f) * fmaxf(sqrtf(p2n), 1e-12f));
    cz[(size_t)b * TNE + m] = fminf(fmaxf(vz, 0.f), 1.f) * 0.5f;
    cc[(size_t)b * TNE + m] = fminf(fmaxf(vc, 0.f), 1.f) * 0.5f;
}

// ---- softmax -> bf16 hi/lo, vectorized loads ----
__global__ void softmax_kernel(const float* __restrict__ cxz,
                               bf16* __restrict__ softh, bf16* __restrict__ softl)
{
    __shared__ float sbuf[256];
    int r = blockIdx.x;
    int k = r % NC;
    int bt = r / NC;
    int b = bt / TT4, t = bt % TT4;
    const float* src = cxz + ((size_t)b * NC + k) * TNE + t * N4;
    bf16* dh = softh + (size_t)r * N4;
    bf16* dl = softl + (size_t)r * N4;
    int tid = threadIdx.x;
    float4 v[4];
    float mx = -3.4e38f;
    #pragma unroll
    for (int j = 0; j < 4; j++) {
        v[j] = *(const float4*)(src + tid * 4 + j * 1024);
        mx = fmaxf(mx, fmaxf(fmaxf(v[j].x, v[j].y), fmaxf(v[j].z, v[j].w)));
    }
    mx = block_reduce_max(mx, sbuf);
    float s = 0.f;
    #pragma unroll
    for (int j = 0; j < 4; j++) {
        v[j].x = expf(v[j].x - mx); v[j].y = expf(v[j].y - mx);
        v[j].z = expf(v[j].z - mx); v[j].w = expf(v[j].w - mx);
        s += v[j].x + v[j].y + v[j].z + v[j].w;
    }
    s = block_reduce_sum(s, sbuf);
    float inv = 1.f / s;
    #pragma unroll
    for (int j = 0; j < 4; j++) {
        float p0 = v[j].x * inv, p1 = v[j].y * inv;
        float p2 = v[j].z * inv, p3 = v[j].w * inv;
        bf16 h0 = __float2bfloat16(p0), h1 = __float2bfloat16(p1);
        bf16 h2 = __float2bfloat16(p2), h3 = __float2bfloat16(p3);
        int o = tid * 4 + j * 1024;
        *(__nv_bfloat162*)(dh + o)     = __nv_bfloat162(h0, h1);
        *(__nv_bfloat162*)(dh + o + 2) = __nv_bfloat162(h2, h3);
        *(__nv_bfloat162*)(dl + o) = __nv_bfloat162(
            __float2bfloat16(p0 - __bfloat162float(h0)),
            __float2bfloat16(p1 - __bfloat162float(h1)));
        *(__nv_bfloat162*)(dl + o + 2) = __nv_bfloat162(
            __float2bfloat16(p2 - __bfloat162float(h2)),
            __float2bfloat16(p3 - __bfloat162float(h3)));
    }
}

// ---- zero cen ----
__global__ void zero_cen_kernel(float* __restrict__ cen)
{
    int i = blockIdx.x * blockDim.x + threadIdx.x;
    if (i < 307200) cen[i] = 0.f;
}

// ---- C_in gating + LayerNorm ----
__global__ void cin_kernel(const float* __restrict__ cen,
                           const float* __restrict__ alpha,
                           const float* __restrict__ beta,
                           const float* __restrict__ nw,
                           const float* __restrict__ nb,
                           float* __restrict__ cinln)
{
    __shared__ float sbuf[256];
    int bk = blockIdx.x;
    int b = bk / NC, k = bk % NC;
    int c = threadIdx.x;
    float last = cen[((size_t)(b * TT4 + 3) * NC + k) * CC + c];
    float pv[3];
    #pragma unroll
    for (int t = 0; t < 3; t++)
        pv[t] = cen[((size_t)(b * TT4 + t) * NC + k) * CC + c];
    float nl = block_reduce_sum(last * last, sbuf);
    float al = alpha[0], be = beta[0];
    float g[3];
    #pragma unroll
    for (int t = 0; t < 3; t++) {
        float dt = block_reduce_sum(last * pv[t], sbuf);
        float np = block_reduce_sum(pv[t] * pv[t], sbuf);
        float denom = fmaxf(sqrtf(nl) * sqrtf(np), 1e-8f);
        g[t] = 1.f / (1.f + expf(-(be + al * dt / denom)));
    }
    float cin = last + g[0] * pv[0] + g[1] * pv[1] + g[2] * pv[2];
    float mean = block_reduce_sum(cin, sbuf) * (1.f / CC);
    float d = cin - mean;
    float var = block_reduce_sum(d * d, sbuf) * (1.f / CC);
    cinln[((size_t)b * NC + k) * CC + c] = d * rsqrtf(var + 1e-5f) * nw[c] + nb[c];
}

// ---- attention -> bf16 hi/lo output ----
__global__ void attn_kernel(const float* __restrict__ q,
                            const float* __restrict__ kbuf,
                            const float* __restrict__ vbuf,
                            bf16* __restrict__ obh, bf16* __restrict__ obl)
{
    __shared__ float kh[NC * 33];
    __shared__ float vh[NC * 33];
    int b = blockIdx.z, h = blockIdx.y;
    int tid = threadIdx.x;
    int warp = tid >> 5, lane = tid & 31;
    for (int idx = tid; idx < NC * HD; idx += blockDim.x) {
        int kk = idx / HD, d = idx % HD;
        kh[kk * 33 + d] = kbuf[((size_t)b * NC + kk) * CC + h * HD + d];
        vh[kk * 33 + d] = vbuf[((size_t)b * NC + kk) * CC + h * HD + d];
    }
    __syncthreads();
    const unsigned FULL = 0xffffffffu;
    for (int ni = warp; ni < 256; ni += 8) {
        int n = blockIdx.x * 256 + ni;
        float qv = q[((size_t)b * N4 + n) * CC + h * HD + lane];
        float lg[5];
        #pragma unroll
        for (int i = 0; i < 5; i++) {
            int kk = lane + 32 * i;
            int kks = (kk < NC) ? kk : (NC - 1);
            float acc = 0.f;
            #pragma unroll
            for (int d = 0; d < 32; d++) {
                float qd = __shfl_sync(FULL, qv, d);
                acc += qd * kh[kks * 33 + d];
            }
            lg[i] = (kk < NC) ? acc : -3.4e38f;
        }
        float mx = lg[0];
        #pragma unroll
        for (int i = 1; i < 5; i++) mx = fmaxf(mx, lg[i]);
        #pragma unroll
        for (int off = 16; off > 0; off >>= 1)
            mx = fmaxf(mx, __shfl_xor_sync(FULL, mx, off));
        float p[5], s = 0.f;
        #pragma unroll
        for (int i = 0; i < 5; i++) { p[i] = expf(lg[i] - mx); s += p[i]; }
        #pragma unroll
        for (int off = 16; off > 0; off >>= 1)
            s += __shfl_xor_sync(FULL, s, off);
        float inv = 1.f / s;
        float od = 0.f;
        #pragma unroll
        for (int i = 0; i < 5; i++) {
            float pi = p[i] * inv;
            #pragma unroll
            for (int l = 0; l < 32; l++) {
                float a = __shfl_sync(FULL, pi, l);
                int kk = l + 32 * i;
                if (kk < NC) od += a * vh[kk * 33 + lane];
            }
        }
        size_t idx = ((size_t)b * N4 + n) * CC + h * HD + lane;
        bf16 hh = __float2bfloat16(od);
        obh[idx] = hh;
        obl[idx] = __float2bfloat16(od - __bfloat162float(hh));
    }
}

// ---- out = base + LN(xin) ----
__global__ void ln_add_kernel(const float* __restrict__ base,
                              const float* __restrict__ xin,
                              const float* __restrict__ nw,
                              const float* __restrict__ nb,
                              float* __restrict__ out)
{
    __shared__ float sbuf[256];
    size_t row = blockIdx.x;
    int c = threadIdx.x;
    float v = xin[row * CC + c];
    float mean = block_reduce_sum(v, sbuf) * (1.f / CC);
    float d = v - mean;
    float var = block_reduce_sum(d * d, sbuf) * (1.f / CC);
    out[row * CC + c] = base[row * CC + c] + d * rsqrtf(var + 1e-5f) * nw[c] + nb[c];
}

// ---- out = base + LN(xin), + bf16 split ----
__global__ void ln_add_split_kernel(const float* __restrict__ base,
                                    const float* __restrict__ xin,
                                    const float* __restrict__ nw,
                                    const float* __restrict__ nb,
                                    float* __restrict__ out,
                                    bf16* __restrict__ ohi, bf16* __restrict__ olo)
{
    __shared__ float sbuf[256];
    size_t row = blockIdx.x;
    int c = threadIdx.x;
    float v = xin[row * CC + c];
    float mean = block_reduce_sum(v, sbuf) * (1.f / CC);
    float d = v - mean;
    float var = block_reduce_sum(d * d, sbuf) * (1.f / CC);
    float r = base[row * CC + c] + d * rsqrtf(var + 1e-5f) * nw[c] + nb[c];
    size_t idx = row * CC + c;
    out[idx] = r;
    bf16 h = __float2bfloat16(r);
    ohi[idx] = h;
    olo[idx] = __float2bfloat16(r - __bfloat162float(h));
}

// ---- depthwise conv + GELU -> bf16 hi/lo, 4 channels/thread ----
__global__ void dwconv_gelu_bf16_kernel(const float* __restrict__ h1,
                                        const float* __restrict__ dw_w,
                                        const float* __restrict__ dw_b,
                                        bf16* __restrict__ gh, bf16* __restrict__ gl)
{
    int idx = blockIdx.x * blockDim.x + threadIdx.x;
    if (idx >= BB * N4 * HID / 4) return;
    int c0 = (idx & (HID / 4 - 1)) * 4;
    int r = idx / (HID / 4);
    int n = r & (N4 - 1);
    int b = r >> 12;
    int y = n >> 6, x = n & 63;
    float4 acc = *(const float4*)(dw_b + c0);
    #pragma unroll
    for (int dy = 0; dy < 3; dy++) {
        int yy = y + dy - 1;
        if (yy < 0 || yy >= HH) continue;
        #pragma unroll
        for (int dx = 0; dx < 3; dx++) {
            int xx = x + dx - 1;
            if (xx < 0 || xx >= WW) continue;
            float4 v = *(const float4*)(h1 + ((size_t)b * N4 + yy * WW + xx) * HID + c0);
            int tap = dy * 3 + dx;
            acc.x += v.x * dw_w[(c0 + 0) * 9 + tap];
            acc.y += v.y * dw_w[(c0 + 1) * 9 + tap];
            acc.z += v.z * dw_w[(c0 + 2) * 9 + tap];
            acc.w += v.w * dw_w[(c0 + 3) * 9 + tap];
        }
    }
    float4 g;
    g.x = 0.5f * acc.x * (1.0f + erff(acc.x * 0.70710678118654752f));
    g.y = 0.5f * acc.y * (1.0f + erff(acc.y * 0.70710678118654752f));
    g.z = 0.5f * acc.z * (1.0f + erff(acc.z * 0.70710678118654752f));
    g.w = 0.5f * acc.w * (1.0f + erff(acc.w * 0.70710678118654752f));
    size_t o = (size_t)r * HID + c0;
    bf16 h0 = __float2bfloat16(g.x), h1b = __float2bfloat16(g.y);
    bf16 h2 = __float2bfloat16(g.z), h3 = __float2bfloat16(g.w);
    *(__nv_bfloat162*)(gh + o)     = __nv_bfloat162(h0, h1b);
    *(__nv_bfloat162*)(gh + o + 2) = __nv_bfloat162(h2, h3);
    *(__nv_bfloat162*)(gl + o) = __nv_bfloat162(
        __float2bfloat16(g.x - __bfloat162float(h0)),
        __float2bfloat16(g.y - __bfloat162float(h1b)));
    *(__nv_bfloat162*)(gl + o + 2) = __nv_bfloat162(
        __float2bfloat16(g.z - __bfloat162float(h2)),
        __float2bfloat16(g.w - __bfloat162float(h3)));
}

// ================= host launcher =================
#define SMEM_W4  92160
#define SMEM_W8  122880

extern "C" void kernel_launch(void* const* d_in, const int* in_sizes, int n_in,
                              void* d_out, int out_size)
{
    const float* x      = (const float*)d_in[0];
    const float* z      = (const float*)d_in[1];
    const float* mem    = (const float*)d_in[2];
    const float* cw     = (const float*)d_in[3];
    const float* p1     = (const float*)d_in[4];
    const float* tdt1   = (const float*)d_in[5];
    const float* p2     = (const float*)d_in[6];
    const float* tdt2   = (const float*)d_in[7];
    const float* alpha  = (const float*)d_in[8];
    const float* beta   = (const float*)d_in[9];
    const float* q_w    = (const float*)d_in[10];
    const float* q_b    = (const float*)d_in[11];
    const float* k_w    = (const float*)d_in[12];
    const float* k_b    = (const float*)d_in[13];
    const float* v_w    = (const float*)d_in[14];
    const float* v_b    = (const float*)d_in[15];
    const float* proj_w = (const float*)d_in[16];
    const float* proj_b = (const float*)d_in[17];
    const float* norm_w = (const float*)d_in[18];
    const float* norm_b = (const float*)d_in[19];
    const float* fc1_w  = (const float*)d_in[20];
    const float* fc1_b  = (const float*)d_in[21];
    const float* dw_w   = (const float*)d_in[22];
    const float* dw_b   = (const float*)d_in[23];
    const float* fc2_w  = (const float*)d_in[24];
    const float* fc2_b  = (const float*)d_in[25];

    float* out0 = (float*)d_out;
    float* cxz  = out0 + OUT0_ELEMS;
    float* ctr  = out0 + OUT0_ELEMS + CXZ_ELEMS;

    float *cl, *cz, *cc, *cen, *cinln, *kb, *vb, *qb, *oproj, *out1, *h1, *h2;
    bf16 *xh, *xl, *memh, *meml, *xth, *xtl, *memth, *memtl, *cwh, *cwl;
    bf16 *t1h, *t1l, *t2h, *t2l, *zth, *ztl, *clth, *cltl;
    bf16 *softh, *softl, *obh, *obl, *o1h, *o1l, *gh, *gl;
    bf16 *qwh, *qwl, *pwh, *pwl, *f1h, *f1l, *f2h, *f2l;
    cudaGetSymbolAddress((void**)&cl,    g_cl);
    cudaGetSymbolAddress((void**)&cz,    g_cz);
    cudaGetSymbolAddress((void**)&cc,    g_cc);
    cudaGetSymbolAddress((void**)&cen,   g_cen);
    cudaGetSymbolAddress((void**)&cinln, g_cinln);
    cudaGetSymbolAddress((void**)&kb,    g_kbuf);
    cudaGetSymbolAddress((void**)&vb,    g_vbuf);
    cudaGetSymbolAddress((void**)&qb,    g_q);
    cudaGetSymbolAddress((void**)&oproj, g_oproj);
    cudaGetSymbolAddress((void**)&out1,  g_out1);
    cudaGetSymbolAddress((void**)&h1,    g_h1);
    cudaGetSymbolAddress((void**)&h2,    g_h2);
    cudaGetSymbolAddress((void**)&xh,   g_xh);   cudaGetSymbolAddress((void**)&xl,   g_xl);
    cudaGetSymbolAddress((void**)&memh, g_memh); cudaGetSymbolAddress((void**)&meml, g_meml);
    cudaGetSymbolAddress((void**)&xth,  g_xth);  cudaGetSymbolAddress((void**)&xtl,  g_xtl);
    cudaGetSymbolAddress((void**)&memth, g_memth); cudaGetSymbolAddress((void**)&memtl, g_memtl);
    cudaGetSymbolAddress((void**)&cwh,  g_cwh);  cudaGetSymbolAddress((void**)&cwl,  g_cwl);
    cudaGetSymbolAddress((void**)&t1h,  g_t1h);  cudaGetSymbolAddress((void**)&t1l,  g_t1l);
    cudaGetSymbolAddress((void**)&t2h,  g_t2h);  cudaGetSymbolAddress((void**)&t2l,  g_t2l);
    cudaGetSymbolAddress((void**)&zth,  g_zth);  cudaGetSymbolAddress((void**)&ztl,  g_ztl);
    cudaGetSymbolAddress((void**)&clth, g_clth); cudaGetSymbolAddress((void**)&cltl, g_cltl);
    cudaGetSymbolAddress((void**)&softh, g_softh); cudaGetSymbolAddress((void**)&softl, g_softl);
    cudaGetSymbolAddress((void**)&obh, g_obh); cudaGetSymbolAddress((void**)&obl, g_obl);
    cudaGetSymbolAddress((void**)&o1h, g_o1h); cudaGetSymbolAddress((void**)&o1l, g_o1l);
    cudaGetSymbolAddress((void**)&gh,  g_gh);  cudaGetSymbolAddress((void**)&gl,  g_gl);
    cudaGetSymbolAddress((void**)&qwh, g_qwh); cudaGetSymbolAddress((void**)&qwl, g_qwl);
    cudaGetSymbolAddress((void**)&pwh, g_pwh); cudaGetSymbolAddress((void**)&pwl, g_pwl);
    cudaGetSymbolAddress((void**)&f1h, g_f1h); cudaGetSymbolAddress((void**)&f1l, g_f1l);
    cudaGetSymbolAddress((void**)&f2h, g_f2h); cudaGetSymbolAddress((void**)&f2l, g_f2l);

    cudaFuncSetAttribute(hmma_gemm_kernel<4>,
                         cudaFuncAttributeMaxDynamicSharedMemorySize, SMEM_W4);
    cudaFuncSetAttribute(hmma_gemm_kernel<8>,
                         cudaFuncAttributeMaxDynamicSharedMemorySize, SMEM_W8);
    cudaFuncSetAttribute(cl_hmma_kernel,
                         cudaFuncAttributeMaxDynamicSharedMemorySize, SMEM_W8);
    cudaFuncSetAttribute(cen_hmma_kernel,
                         cudaFuncAttributeMaxDynamicSharedMemorySize, SMEM_W8);
    cudaFuncSetAttribute(comb_hmma_kernel,
                         cudaFuncAttributeMaxDynamicSharedMemorySize, SMEM_W4);

    // 0) prep
    split_all_kernel<<<dim3(128, 8, 2), dim3(32, 8)>>>(x, xh, xl, xth, xtl);
    split_all_kernel<<<dim3(128, 8, 6), dim3(32, 8)>>>(mem, memh, meml, memth, memtl);
    cvt_split5_kernel<<<dim3(256, 5), 256>>>(
        q_w, qwh, qwl, 65536,
        proj_w, pwh, pwl, 65536,
        fc1_w, f1h, f1l, 262144,
        fc2_w, f2h, f2l, 262144,
        cw, cwh, cwl, 38400);
    tdt_prep_kernel<<<100, 256>>>(tdt1, tdt2, t1h, t1l, t2h, t2l);
    zT_split_kernel<<<dim3(512, 5, 2), dim3(32, 8)>>>(z, zth, ztl);

    // 1) cl (HMMA)
    cl_hmma_kernel<<<dim3(32, 2, 8), 256, SMEM_W8>>>(cwh, cwl, xh, xl, memh, meml, cl);
    // 2) prompt cos -> scale vectors; clT split
    prompt_scale_kernel<<<dim3(TNE / 256, 1, BB), 256>>>(z, cl, p1, p2, cz, cc);
    clT_split_kernel<<<dim3(128, 5, 8), dim3(32, 8)>>>(cl, clth, cltl);
    // 3) combine (HMMA) -> cluster_x_z + center
    comb_hmma_kernel<<<dim3(256, 2, 2), 256, SMEM_W4>>>(
        t1h, t1l, t2h, t2l, zth, ztl, clth, cltl, cz, cc, cxz, ctr);
    // 4) softmax -> bf16 hi/lo
    softmax_kernel<<<BB * TT4 * NC, 256>>>(cxz, softh, softl);
    // 5) cen (HMMA, split-K atomic)
    zero_cen_kernel<<<(307200 + 255) / 256, 256>>>(cen);
    cen_hmma_kernel<<<dim3(2, 2, 64), 256, SMEM_W8>>>(softh, softl, xth, xtl, memth, memtl, cen);
    // 6) gating + LN
    cin_kernel<<<BB * NC, 256>>>(cen, alpha, beta, norm_w, norm_b, cinln);
    // 7) k/v projections (merged)
    gemm_kv_kernel<<<dim3(4, 5, 2), 256>>>(cinln, k_w, k_b, v_w, v_b, kb, vb);
    // 8) q projection
    hmma_gemm_kernel<4><<<dim3(4, 64), 256, SMEM_W4>>>(
        xh, xl, qwh, qwl, q_b, qb, CC, CC, 0.17677669529663687f);
    // 9) attention -> bf16 split
    attn_kernel<<<dim3(N4 / 256, NH, BB), 256>>>(qb, kb, vb, obh, obl);
    // 10) output projection
    hmma_gemm_kernel<4><<<dim3(4, 64), 256, SMEM_W4>>>(
        obh, obl, pwh, pwl, proj_b, oproj, CC, CC, 1.f);
    // 11) out1 = x + LN(oproj), + split
    ln_add_split_kernel<<<BB * N4, 256>>>(x, oproj, norm_w, norm_b, out1, o1h, o1l);
    // 12) fc1
    hmma_gemm_kernel<8><<<dim3(8, 64), 256, SMEM_W8>>>(
        o1h, o1l, f1h, f1l, fc1_b, h1, HID, CC, 1.f);
    // 13) depthwise conv + gelu -> split
    dwconv_gelu_bf16_kernel<<<(BB * N4 * HID / 4 + 255) / 256, 256>>>(h1, dw_w, dw_b, gh, gl);
    // 14) fc2
    hmma_gemm_kernel<4><<<dim3(4, 64), 256, SMEM_W4>>>(
        gh, gl, f2h, f2l, fc2_b, h2, CC, HID, 1.f);
    // 15) out = out1 + LN(h2)
    ln_add_kernel<<<BB * N4, 256>>>(out1, h2, norm_w, norm_b, out0);
}

// round 15
// speedup vs baseline: 1.0772x; 1.0725x over previous
#include <cuda_runtime.h>
#include <cuda_bf16.h>
#include <math.h>
#include <stdint.h>

typedef __nv_bfloat16 bf16;

// ---------------- fixed problem dims ----------------
#define BB   2
#define TT4  4
#define N4   4096
#define CC   256
#define NC   150
#define TNE  16384
#define HID  1024
#define NH   8
#define HD   32
#define HH   64
#define WW   64
#define KPAD 160

#define OUT0_ELEMS 2097152
#define CXZ_ELEMS  4915200

// ---------------- scratch ----------------
__device__ float g_cl[4915200];
__device__ float g_cz[32768], g_cc[32768];
__device__ float g_cen[307200];
__device__ float g_cinln[76800];
__device__ float g_kbuf[76800];
__device__ float g_vbuf[76800];
__device__ float g_q[2097152];
__device__ float g_oproj[2097152];
__device__ float g_out1[2097152];
__device__ float g_h1[8388608];
__device__ float g_h2[2097152];

// bf16 hi/lo split buffers
__device__ bf16 g_xh[2097152],   g_xl[2097152];
__device__ bf16 g_memh[6291456], g_meml[6291456];
__device__ bf16 g_xth[2097152],  g_xtl[2097152];
__device__ bf16 g_memth[6291456], g_memtl[6291456];
__device__ bf16 g_cwh[38400],    g_cwl[38400];
__device__ bf16 g_t1h[25600], g_t1l[25600], g_t2h[25600], g_t2l[25600];
__device__ bf16 g_zth[5242880],  g_ztl[5242880];
__device__ bf16 g_clth[5242880], g_cltl[5242880];
__device__ bf16 g_softh[4915200], g_softl[4915200];
__device__ bf16 g_obh[2097152], g_obl[2097152];
__device__ bf16 g_o1h[2097152], g_o1l[2097152];
__device__ bf16 g_gh[8388608],  g_gl[8388608];
__device__ bf16 g_qwh[65536],  g_qwl[65536];
__device__ bf16 g_pwh[65536],  g_pwl[65536];
__device__ bf16 g_f1h[262144], g_f1l[262144];
__device__ bf16 g_f2h[262144], g_f2l[262144];

// ---------------- warp-level bf16 MMA + cp.async ----------
__device__ __forceinline__ void mma16816(float* d, const uint32_t* a, const uint32_t* b) {
    asm volatile(
        "mma.sync.aligned.m16n8k16.row.col.f32.bf16.bf16.f32 "
        "{%0,%1,%2,%3}, {%4,%5,%6,%7}, {%8,%9}, {%0,%1,%2,%3};\n"
        : "+f"(d[0]), "+f"(d[1]), "+f"(d[2]), "+f"(d[3])
        : "r"(a[0]), "r"(a[1]), "r"(a[2]), "r"(a[3]), "r"(b[0]), "r"(b[1]));
}
__device__ __forceinline__ uint32_t smem_to_u32(const void* p) {
    uint32_t a;
    asm("{ .reg .u64 t; cvta.to.shared.u64 t, %1; cvt.u32.u64 %0, t; }"
        : "=r"(a) : "l"(p));
    return a;
}
__device__ __forceinline__ void cp_async16(uint32_t s, const void* g, bool v) {
    int sz = v ? 16 : 0;
    asm volatile("cp.async.cg.shared.global [%0], [%1], 16, %2;\n"
                 :: "r"(s), "l"(g), "r"(sz));
}
__device__ __forceinline__ void cp_commit() {
    asm volatile("cp.async.commit_group;\n" ::: "memory");
}
template<int N> __device__ __forceinline__ void cp_wait() {
    asm volatile("cp.async.wait_group %0;\n" :: "n"(N) : "memory");
}

#define SAS 40

// inner compute: WNT n-subtiles per warp, one 32-deep K chunk, 3-term split
template<int WNT>
__device__ __forceinline__ void hmma_chunk(
    bf16 (*sAh)[SAS], bf16 (*sAl)[SAS], bf16 (*sBh)[SAS], bf16 (*sBl)[SAS],
    int wm, int wn, int g, int tg, float (*acc)[WNT][4])
{
    #pragma unroll
    for (int ks = 0; ks < 2; ks++) {
        int kc = ks * 16 + tg * 2;
        uint32_t ah[2][4], al[2][4], bh[WNT][2], bl[WNT][2];
        #pragma unroll
        for (int mt = 0; mt < 2; mt++) {
            int r = wm * 32 + mt * 16 + g;
            ah[mt][0] = *(const uint32_t*)&sAh[r][kc];
            ah[mt][1] = *(const uint32_t*)&sAh[r + 8][kc];
            ah[mt][2] = *(const uint32_t*)&sAh[r][kc + 8];
            ah[mt][3] = *(const uint32_t*)&sAh[r + 8][kc + 8];
            al[mt][0] = *(const uint32_t*)&sAl[r][kc];
            al[mt][1] = *(const uint32_t*)&sAl[r + 8][kc];
            al[mt][2] = *(const uint32_t*)&sAl[r][kc + 8];
            al[mt][3] = *(const uint32_t*)&sAl[r + 8][kc + 8];
        }
        #pragma unroll
        for (int nt = 0; nt < WNT; nt++) {
            int nr = wn * (WNT * 8) + nt * 8 + g;
            bh[nt][0] = *(const uint32_t*)&sBh[nr][kc];
            bh[nt][1] = *(const uint32_t*)&sBh[nr][kc + 8];
            bl[nt][0] = *(const uint32_t*)&sBl[nr][kc];
            bl[nt][1] = *(const uint32_t*)&sBl[nr][kc + 8];
        }
        #pragma unroll
        for (int mt = 0; mt < 2; mt++)
            #pragma unroll
            for (int nt = 0; nt < WNT; nt++) {
                mma16816(acc[mt][nt], ah[mt], bh[nt]);
                mma16816(acc[mt][nt], ah[mt], bl[nt]);
                mma16816(acc[mt][nt], al[mt], bh[nt]);
            }
    }
}

// ---- 3-stage cp.async pipelined mainloop ----
template<int WNT, typename F>
__device__ __forceinline__ void hmma_pipe(char* sm, int nk, F getp, float (*acc)[WNT][4])
{
    constexpr int BN = 16 * WNT;
    constexpr int ASZ = 128 * SAS * 2;
    constexpr int BSZ = BN * SAS * 2;
    constexpr int STG = 2 * ASZ + 2 * BSZ;
    int tid = threadIdx.x;
    int wid = tid >> 5, lane = tid & 31;
    int wm = wid & 3, wn = wid >> 2, g = lane >> 2, tg = lane & 3;
    int lrow = tid >> 1, lhalf = (tid & 1) * 16;
    bool bload = (WNT == 8) || (tid < BN * 2);
    uint32_t sb = smem_to_u32(sm);
    uint32_t off = (uint32_t)(lrow * SAS + lhalf) * 2;

    __syncthreads();

    auto issue = [&](int c) {
        uint32_t st = sb + (c % 3) * STG;
        const bf16 *ah, *al, *bh, *bl; bool av;
        getp(c, ah, al, bh, bl, av);
        cp_async16(st + off, ah, av);
        cp_async16(st + off + 16, ah + 8, av);
        cp_async16(st + ASZ + off, al, av);
        cp_async16(st + ASZ + off + 16, al + 8, av);
        if (bload) {
            cp_async16(st + 2 * ASZ + off, bh, true);
            cp_async16(st + 2 * ASZ + off + 16, bh + 8, true);
            cp_async16(st + 2 * ASZ + BSZ + off, bl, true);
            cp_async16(st + 2 * ASZ + BSZ + off + 16, bl + 8, true);
        }
        cp_commit();
    };

    issue(0); issue(1);
    for (int c = 0; c < nk; c++) {
        if (c + 2 <= nk) cp_wait<1>(); else cp_wait<0>();
        __syncthreads();
        {
            char* st = sm + (c % 3) * STG;
            bf16 (*sAh)[SAS] = (bf16(*)[SAS])st;
            bf16 (*sAl)[SAS] = (bf16(*)[SAS])(st + ASZ);
            bf16 (*sBh)[SAS] = (bf16(*)[SAS])(st + 2 * ASZ);
            bf16 (*sBl)[SAS] = (bf16(*)[SAS])(st + 2 * ASZ + BSZ);
            hmma_chunk<WNT>(sAh, sAl, sBh, sBl, wm, wn, g, tg, acc);
        }
        if (c + 2 < nk) issue(c + 2);
    }
}

// ================= HMMA GEMM (q/proj/fc1/fc2) ============
template<int WNT>
__global__ void __launch_bounds__(256)
hmma_gemm_kernel(const bf16* __restrict__ Ah, const bf16* __restrict__ Al,
                 const bf16* __restrict__ Bh, const bf16* __restrict__ Bl,
                 const float* __restrict__ bias, float* __restrict__ C,
                 int Ntot, int K, float scale)
{
    extern __shared__ char sm[];
    constexpr int BN = 16 * WNT;
    int tid = threadIdx.x, wid = tid >> 5, lane = tid & 31;
    int wm = wid & 3, wn = wid >> 2, g = lane >> 2, tg = lane & 3;
    int m0 = blockIdx.y * 128, n0 = blockIdx.x * BN;
    int lrow = tid >> 1, lhalf = (tid & 1) * 16;

    float acc[2][WNT][4] = {};
    auto getp = [&](int c, const bf16*& ah, const bf16*& al,
                    const bf16*& bh, const bf16*& bl, bool& av) {
        int k0 = (c << 5) + lhalf;
        ah = Ah + (size_t)(m0 + lrow) * K + k0;
        al = Al + (size_t)(m0 + lrow) * K + k0;
        bh = Bh + (size_t)(n0 + lrow) * K + k0;
        bl = Bl + (size_t)(n0 + lrow) * K + k0;
        av = true;
    };
    hmma_pipe<WNT>(sm, K >> 5, getp, acc);

    #pragma unroll
    for (int mt = 0; mt < 2; mt++) {
        int r0 = m0 + wm * 32 + mt * 16 + g;
        #pragma unroll
        for (int nt = 0; nt < WNT; nt++) {
            int col = n0 + wn * (WNT * 8) + nt * 8 + tg * 2;
            float b0 = bias[col], b1 = bias[col + 1];
            float2 v0, v1;
            v0.x = (acc[mt][nt][0] + b0) * scale;
            v0.y = (acc[mt][nt][1] + b1) * scale;
            v1.x = (acc[mt][nt][2] + b0) * scale;
            v1.y = (acc[mt][nt][3] + b1) * scale;
            *(float2*)&C[(size_t)r0 * Ntot + col] = v0;
            *(float2*)&C[(size_t)(r0 + 8) * Ntot + col] = v1;
        }
    }
}

// ================= cl HMMA =================
__global__ void __launch_bounds__(256)
cl_hmma_kernel(const bf16* __restrict__ cwh, const bf16* __restrict__ cwl,
               const bf16* __restrict__ xh, const bf16* __restrict__ xl,
               const bf16* __restrict__ memh, const bf16* __restrict__ meml,
               float* __restrict__ cl)
{
    extern __shared__ char sm[];
    int bt = blockIdx.z, b = bt >> 2, t = bt & 3;
    const bf16* Bh = (t < 3) ? memh + (size_t)(b * 3 + t) * 1048576 : xh + (size_t)b * 1048576;
    const bf16* Bl = (t < 3) ? meml + (size_t)(b * 3 + t) * 1048576 : xl + (size_t)b * 1048576;
    float* Cp = cl + (size_t)bt * 614400;

    int tid = threadIdx.x, wid = tid >> 5, lane = tid & 31;
    int wm = wid & 3, wn = wid >> 2, g = lane >> 2, tg = lane & 3;
    int m0 = blockIdx.y * 128, n0 = blockIdx.x * 128;
    int lrow = tid >> 1, lhalf = (tid & 1) * 16;
    bool aval = (m0 + lrow) < NC;

    float acc[2][8][4] = {};
    auto getp = [&](int c, const bf16*& ah, const bf16*& al,
                    const bf16*& bh, const bf16*& bl, bool& av) {
        int k0 = (c << 5) + lhalf;
        ah = cwh + (size_t)(m0 + lrow) * CC + k0;
        al = cwl + (size_t)(m0 + lrow) * CC + k0;
        bh = Bh + (size_t)(n0 + lrow) * CC + k0;
        bl = Bl + (size_t)(n0 + lrow) * CC + k0;
        av = aval;
    };
    hmma_pipe<8>(sm, 8, getp, acc);

    #pragma unroll
    for (int mt = 0; mt < 2; mt++) {
        int r0 = m0 + wm * 32 + mt * 16 + g;
        #pragma unroll
        for (int nt = 0; nt < 8; nt++) {
            int col = n0 + wn * 64 + nt * 8 + tg * 2;
            if (r0 < NC)
                *(float2*)&Cp[(size_t)r0 * N4 + col] = make_float2(acc[mt][nt][0], acc[mt][nt][1]);
            if (r0 + 8 < NC)
                *(float2*)&Cp[(size_t)(r0 + 8) * N4 + col] = make_float2(acc[mt][nt][2], acc[mt][nt][3]);
        }
    }
}

// ================= comb HMMA =================
__global__ void __launch_bounds__(256)
comb_hmma_kernel(const bf16* __restrict__ t1h, const bf16* __restrict__ t1l,
                 const bf16* __restrict__ t2h, const bf16* __restrict__ t2l,
                 const bf16* __restrict__ zth, const bf16* __restrict__ ztl,
                 const bf16* __restrict__ clth, const bf16* __restrict__ cltl,
                 const float* __restrict__ cz, const float* __restrict__ cc,
                 float* __restrict__ cxz, float* __restrict__ ctr)
{
    extern __shared__ char sm[];
    int b = blockIdx.z;
    int j0 = blockIdx.y * 128, n0 = blockIdx.x * 64;
    int tid = threadIdx.x, wid = tid >> 5, lane = tid & 31;
    int wm = wid & 3, wn = wid >> 2, g = lane >> 2, tg = lane & 3;
    int lrow = tid >> 1, lhalf = (tid & 1) * 16;
    bool aval = (j0 + lrow) < KPAD;

    float acc1[2][4][4] = {}, acc2[2][4][4] = {};
    const bf16* Bz_h = zth + (size_t)b * TNE * KPAD;
    const bf16* Bz_l = ztl + (size_t)b * TNE * KPAD;
    const bf16* Bc_h = clth + (size_t)b * TNE * KPAD;
    const bf16* Bc_l = cltl + (size_t)b * TNE * KPAD;

    auto getp1 = [&](int c, const bf16*& ah, const bf16*& al,
                     const bf16*& bh, const bf16*& bl, bool& av) {
        int k0 = (c << 5) + lhalf;
        ah = t1h + (size_t)(j0 + lrow) * KPAD + k0;
        al = t1l + (size_t)(j0 + lrow) * KPAD + k0;
        bh = Bz_h + (size_t)(n0 + lrow) * KPAD + k0;
        bl = Bz_l + (size_t)(n0 + lrow) * KPAD + k0;
        av = aval;
    };
    hmma_pipe<4>(sm, 5, getp1, acc1);
    auto getp2 = [&](int c, const bf16*& ah, const bf16*& al,
                     const bf16*& bh, const bf16*& bl, bool& av) {
        int k0 = (c << 5) + lhalf;
        ah = t2h + (size_t)(j0 + lrow) * KPAD + k0;
        al = t2l + (size_t)(j0 + lrow) * KPAD + k0;
        bh = Bc_h + (size_t)(n0 + lrow) * KPAD + k0;
        bl = Bc_l + (size_t)(n0 + lrow) * KPAD + k0;
        av = aval;
    };
    hmma_pipe<4>(sm, 5, getp2, acc2);

    #pragma unroll
    for (int mt = 0; mt < 2; mt++) {
        int r0 = j0 + wm * 32 + mt * 16 + g;
        #pragma unroll
        for (int nt = 0; nt < 4; nt++) {
            int col = n0 + wn * 32 + nt * 8 + tg * 2;
            float s0z = cz[(size_t)b * TNE + col],     s1z = cz[(size_t)b * TNE + col + 1];
            float s0c = cc[(size_t)b * TNE + col],     s1c = cc[(size_t)b * TNE + col + 1];
            int t = col >> 12, n = col & 4095;
            if (r0 < NC) {
                float2 v;
                v.x = s0z * acc1[mt][nt][0] + s0c * acc2[mt][nt][0];
                v.y = s1z * acc1[mt][nt][1] + s1c * acc2[mt][nt][1];
                *(float2*)&cxz[((size_t)b * NC + r0) * TNE + col] = v;
                *(float2*)&ctr[((size_t)(b * TT4 + t) * NC + r0) * N4 + n] = v;
            }
            if (r0 + 8 < NC) {
                float2 v;
                v.x = s0z * acc1[mt][nt][2] + s0c * acc2[mt][nt][2];
                v.y = s1z * acc1[mt][nt][3] + s1c * acc2[mt][nt][3];
                *(float2*)&cxz[((size_t)b * NC + r0 + 8) * TNE + col] = v;
                *(float2*)&ctr[((size_t)(b * TT4 + t) * NC + r0 + 8) * N4 + n] = v;
            }
        }
    }
}

// ================= cen HMMA (3-term, split-K, atomic) =================
__global__ void __launch_bounds__(256)
cen_hmma_kernel(const bf16* __restrict__ softh, const bf16* __restrict__ softl,
                const bf16* __restrict__ xth, const bf16* __restrict__ xtl,
                const bf16* __restrict__ memth, const bf16* __restrict__ memtl,
                float* __restrict__ cen)
{
    extern __shared__ char sm[];
    int bt = blockIdx.z >> 3, sp = blockIdx.z & 7;
    int b = bt >> 2, t = bt & 3;
    const bf16* Ah = softh + (size_t)bt * 614400;
    const bf16* Al = softl + (size_t)bt * 614400;
    const bf16* Bh = (t < 3) ? memth + (size_t)(b * 3 + t) * 1048576 : xth + (size_t)b * 1048576;
    const bf16* Bl = (t < 3) ? memtl + (size_t)(b * 3 + t) * 1048576 : xtl + (size_t)b * 1048576;
    float* Cp = cen + (size_t)bt * 38400;
    int koff = sp * 512;

    int tid = threadIdx.x, wid = tid >> 5, lane = tid & 31;
    int wm = wid & 3, wn = wid >> 2, g = lane >> 2, tg = lane & 3;
    int m0 = blockIdx.y * 128, n0 = blockIdx.x * 128;
    int lrow = tid >> 1, lhalf = (tid & 1) * 16;
    bool aval = (m0 + lrow) < NC;

    float acc[2][8][4] = {};
    auto getp = [&](int c, const bf16*& ah, const bf16*& al,
                    const bf16*& bh, const bf16*& bl, bool& av) {
        int k0 = koff + (c << 5) + lhalf;
        ah = Ah + (size_t)(m0 + lrow) * N4 + k0;
        al = Al + (size_t)(m0 + lrow) * N4 + k0;
        bh = Bh + (size_t)(n0 + lrow) * N4 + k0;
        bl = Bl + (size_t)(n0 + lrow) * N4 + k0;
        av = aval;
    };
    hmma_pipe<8>(sm, 16, getp, acc);

    #pragma unroll
    for (int mt = 0; mt < 2; mt++) {
        int r0 = m0 + wm * 32 + mt * 16 + g;
        #pragma unroll
        for (int nt = 0; nt < 8; nt++) {
            int col = n0 + wn * 64 + nt * 8 + tg * 2;
            if (r0 < NC) {
                atomicAdd(&Cp[(size_t)r0 * CC + col], acc[mt][nt][0]);
                atomicAdd(&Cp[(size_t)r0 * CC + col + 1], acc[mt][nt][1]);
            }
            if (r0 + 8 < NC) {
                atomicAdd(&Cp[(size_t)(r0 + 8) * CC + col], acc[mt][nt][2]);
                atomicAdd(&Cp[(size_t)(r0 + 8) * CC + col + 1], acc[mt][nt][3]);
            }
        }
    }
}

// ---------------- splits ----------------
__device__ __forceinline__ void split_store4(const float4 v, bf16* hi, bf16* lo, int i) {
    bf16 h0 = __float2bfloat16(v.x), h1 = __float2bfloat16(v.y);
    bf16 h2 = __float2bfloat16(v.z), h3 = __float2bfloat16(v.w);
    *(__nv_bfloat162*)(hi + i)     = __nv_bfloat162(h0, h1);
    *(__nv_bfloat162*)(hi + i + 2) = __nv_bfloat162(h2, h3);
    *(__nv_bfloat162*)(lo + i) = __nv_bfloat162(
        __float2bfloat16(v.x - __bfloat162float(h0)),
        __float2bfloat16(v.y - __bfloat162float(h1)));
    *(__nv_bfloat162*)(lo + i + 2) = __nv_bfloat162(
        __float2bfloat16(v.z - __bfloat162float(h2)),
        __float2bfloat16(v.w - __bfloat162float(h3)));
}
__global__ void cvt_split5_kernel(
    const float* a0, bf16* h0, bf16* l0, int s0,
    const float* a1, bf16* h1, bf16* l1, int s1,
    const float* a2, bf16* h2, bf16* l2, int s2,
    const float* a3, bf16* h3, bf16* l3, int s3,
    const float* a4, bf16* h4, bf16* l4, int s4)
{
    const float* in; bf16 *hi, *lo; int n;
    switch (blockIdx.y) {
        case 0: in = a0; hi = h0; lo = l0; n = s0; break;
        case 1: in = a1; hi = h1; lo = l1; n = s1; break;
        case 2: in = a2; hi = h2; lo = l2; n = s2; break;
        case 3: in = a3; hi = h3; lo = l3; n = s3; break;
        default: in = a4; hi = h4; lo = l4; n = s4; break;
    }
    int i = (blockIdx.x * 256 + threadIdx.x) * 4;
    if (i >= n) return;
    split_store4(*(const float4*)(in + i), hi, lo, i);
}

// ---- split + transpose-split in one pass ----
__global__ void split_all_kernel(const float* __restrict__ in,
                                 bf16* __restrict__ oh, bf16* __restrict__ ol,
                                 bf16* __restrict__ toh, bf16* __restrict__ tol)
{
    __shared__ float tile[32][33];
    const float* src = in + (size_t)blockIdx.z * 1048576;
    bf16* doh = oh + (size_t)blockIdx.z * 1048576;
    bf16* dol = ol + (size_t)blockIdx.z * 1048576;
    bf16* dth = toh + (size_t)blockIdx.z * 1048576;
    bf16* dtl = tol + (size_t)blockIdx.z * 1048576;
    int tx = threadIdx.x, ty = threadIdx.y;
    int r0 = blockIdx.x * 32, c0 = blockIdx.y * 32;
    #pragma unroll
    for (int i = 0; i < 4; i++) {
        int r = r0 + ty + i * 8;
        float v = src[(size_t)r * CC + c0 + tx];
        tile[ty + i * 8][tx] = v;
        bf16 h = __float2bfloat16(v);
        doh[(size_t)r * CC + c0 + tx] = h;
        dol[(size_t)r * CC + c0 + tx] = __float2bfloat16(v - __bfloat162float(h));
    }
    __syncthreads();
    #pragma unroll
    for (int i = 0; i < 4; i++) {
        int c = c0 + ty + i * 8;
        float v = tile[tx][ty + i * 8];
        bf16 h = __float2bfloat16(v);
        dth[(size_t)c * N4 + r0 + tx] = h;
        dtl[(size_t)c * N4 + r0 + tx] = __float2bfloat16(v - __bfloat162float(h));
    }
}

// ---- zT split ----
__global__ void zT_split_kernel(const float* __restrict__ z,
                                bf16* __restrict__ oh, bf16* __restrict__ ol)
{
    __shared__ float tile[32][33];
    int b = blockIdx.z;
    int m0 = blockIdx.x * 32, k0 = blockIdx.y * 32;
    int tx = threadIdx.x, ty = threadIdx.y;
    #pragma unroll
    for (int i = 0; i < 4; i++) {
        int k = k0 + ty + i * 8;
        tile[ty + i * 8][tx] = (k < NC) ? z[((size_t)b * NC + k) * TNE + m0 + tx] : 0.f;
    }
    __syncthreads();
    #pragma unroll
    for (int i = 0; i < 4; i++) {
        int m = m0 + ty + i * 8;
        float v = tile[tx][ty + i * 8];
        bf16 h = __float2bfloat16(v);
        size_t idx = ((size_t)b * TNE + m) * KPAD + k0 + tx;
        oh[idx] = h;
        ol[idx] = __float2bfloat16(v - __bfloat162float(h));
    }
}

// ---- clT split ----
__global__ void clT_split_kernel(const float* __restrict__ cl,
                                 bf16* __restrict__ oh, bf16* __restrict__ ol)
{
    __shared__ float tile[32][33];
    int bt = blockIdx.z, b = bt >> 2, t = bt & 3;
    int n0 = blockIdx.x * 32, k0 = blockIdx.y * 32;
    int tx = threadIdx.x, ty = threadIdx.y;
    const float* src = cl + (size_t)bt * 614400;
    #pragma unroll
    for (int i = 0; i < 4; i++) {
        int k = k0 + ty + i * 8;
        tile[ty + i * 8][tx] = (k < NC) ? src[(size_t)k * N4 + n0 + tx] : 0.f;
    }
    __syncthreads();
    #pragma unroll
    for (int i = 0; i < 4; i++) {
        int n = n0 + ty + i * 8;
        float v = tile[tx][ty + i * 8];
        bf16 h = __float2bfloat16(v);
        size_t idx = ((size_t)b * TNE + t * N4 + n) * KPAD + k0 + tx;
        oh[idx] = h;
        ol[idx] = __float2bfloat16(v - __bfloat162float(h));
    }
}

// ---- tdt^T padded split ----
__global__ void tdt_prep_kernel(const float* __restrict__ tdt1, const float* __restrict__ tdt2,
                                bf16* __restrict__ t1h, bf16* __restrict__ t1l,
                                bf16* __restrict__ t2h, bf16* __restrict__ t2l)
{
    int i = blockIdx.x * 256 + threadIdx.x;
    if (i >= KPAD * KPAD) return;
    int j = i / KPAD, k = i % KPAD;
    float v1 = (j < NC && k < NC) ? tdt1[k * NC + j] : 0.f;
    float v2 = (j < NC && k < NC) ? tdt2[k * NC + j] : 0.f;
    bf16 h1 = __float2bfloat16(v1), h2 = __float2bfloat16(v2);
    t1h[i] = h1; t1l[i] = __float2bfloat16(v1 - __bfloat162float(h1));
    t2h[i] = h2; t2l[i] = __float2bfloat16(v2 - __bfloat162float(h2));
}

// ---------------- hybrid warp-shuffle block reductions (256 threads) -----
__device__ __forceinline__ float block_reduce_sum(float v, float* sbuf) {
    int tid = threadIdx.x, lane = tid & 31, wid = tid >> 5;
    #pragma unroll
    for (int off = 16; off > 0; off >>= 1)
        v += __shfl_xor_sync(0xffffffffu, v, off);
    if (lane == 0) sbuf[wid] = v;
    __syncthreads();
    float r = sbuf[0] + sbuf[1] + sbuf[2] + sbuf[3]
            + sbuf[4] + sbuf[5] + sbuf[6] + sbuf[7];
    __syncthreads();
    return r;
}
__device__ __forceinline__ float block_reduce_max(float v, float* sbuf) {
    int tid = threadIdx.x, lane = tid & 31, wid = tid >> 5;
    #pragma unroll
    for (int off = 16; off > 0; off >>= 1)
        v = fmaxf(v, __shfl_xor_sync(0xffffffffu, v, off));
    if (lane == 0) sbuf[wid] = v;
    __syncthreads();
    float r = fmaxf(fmaxf(fmaxf(sbuf[0], sbuf[1]), fmaxf(sbuf[2], sbuf[3])),
                    fmaxf(fmaxf(sbuf[4], sbuf[5]), fmaxf(sbuf[6], sbuf[7])));
    __syncthreads();
    return r;
}

// ======== merged k/v projection ====
#define OBM 64
#define OBN 64
#define OBK 16
__global__ void gemm_kv_kernel(const float* __restrict__ A,
                               const float* __restrict__ k_w, const float* __restrict__ k_b,
                               const float* __restrict__ v_w, const float* __restrict__ v_b,
                               float* __restrict__ kout, float* __restrict__ vout)
{
    const float* B = blockIdx.z ? v_w : k_w;
    const float* bias = blockIdx.z ? v_b : k_b;
    float* C = blockIdx.z ? vout : kout;
    const int M = BB * NC;
    __shared__ float As[OBK][OBM];
    __shared__ float Bs[OBK][OBN];
    int tid = threadIdx.x;
    int tx = tid & 15, ty = tid >> 4;
    int m0 = blockIdx.y * OBM, n0 = blockIdx.x * OBN;
    float acc[4][4] = {};
    for (int k0 = 0; k0 < CC; k0 += OBK) {
        #pragma unroll
        for (int j = 0; j < 4; j++) {
            int idx = tid + j * 256;
            int ml = idx / OBK, kl = idx % OBK;
            int m = m0 + ml;
            As[kl][ml] = (m < M) ? A[(size_t)m * CC + k0 + kl] : 0.f;
        }
        #pragma unroll
        for (int j = 0; j < 4; j++) {
            int idx = tid + j * 256;
            int nl = idx / OBK, kl = idx % OBK;
            Bs[kl][nl] = B[(size_t)(n0 + nl) * CC + k0 + kl];
        }
        __syncthreads();
        #pragma unroll
        for (int kk = 0; kk < OBK; kk++) {
            float a[4], b[4];
            *(float4*)a = *(const float4*)&As[kk][ty * 4];
            *(float4*)b = *(const float4*)&Bs[kk][tx * 4];
            #pragma unroll
            for (int i = 0; i < 4; i++)
                #pragma unroll
                for (int j = 0; j < 4; j++)
                    acc[i][j] += a[i] * b[j];
        }
        __syncthreads();
    }
    #pragma unroll
    for (int i = 0; i < 4; i++) {
        int m = m0 + ty * 4 + i;
        if (m >= M) continue;
        #pragma unroll
        for (int j = 0; j < 4; j++) {
            int n = n0 + tx * 4 + j;
            C[(size_t)m * CC + n] = acc[i][j] + bias[n];
        }
    }
}

// ---- prompt cos -> cz/cc scale vectors ----
__global__ void prompt_scale_kernel(const float* __restrict__ z,
                                    const float* __restrict__ cl,
                                    const float* __restrict__ p1,
                                    const float* __restrict__ p2,
                                    float* __restrict__ cz,
                                    float* __restrict__ cc)
{
    int m = blockIdx.x * blockDim.x + threadIdx.x;
    int b = blockIdx.z;
    if (m >= TNE) return;
    int t = m >> 12, n = m & 4095;
    const float* zrow = z + (size_t)b * NC * TNE + m;
    const float* crow = cl + ((size_t)(b * TT4 + t) * NC) * N4 + n;
    float dz = 0, nz = 0, dc = 0, ncs = 0, p1n = 0, p2n = 0;
    for (int k = 0; k < NC; k++) {
        float zv = zrow[(size_t)k * TNE];
        float cv = crow[(size_t)k * N4];
        float a = p1[k], bb = p2[k];
        dz += zv * a; nz += zv * zv; p1n += a * a;
        dc += cv * bb; ncs += cv * cv; p2n += bb * bb;
    }
    float vz = dz / (fmaxf(sqrtf(nz), 1e-12f) * fmaxf(sqrtf(p1n), 1e-12f));
    float vc = dc / (fmaxf(sqrtf(ncs), 1e-12f) * fmaxf(sqrtf(p2n), 1e-12f));
    cz[(size_t)b * TNE + m] = fminf(fmaxf(vz, 0.f), 1.f) * 0.5f;
    cc[(size_t)b * TNE + m] = fminf(fmaxf(vc, 0.f), 1.f) * 0.5f;
}

// ---- softmax -> bf16 hi/lo ----
__global__ void softmax_kernel(const float* __restrict__ cxz,
                               bf16* __restrict__ softh, bf16* __restrict__ softl)
{
    __shared__ float sbuf[8];
    int r = blockIdx.x;
    int k = r % NC;
    int bt = r / NC;
    int b = bt / TT4, t = bt % TT4;
    const float* src = cxz + ((size_t)b * NC + k) * TNE + t * N4;
    bf16* dh = softh + (size_t)r * N4;
    bf16* dl = softl + (size_t)r * N4;
    int tid = threadIdx.x;
    float mx = -3.4e38f;
    for (int i = tid; i < N4; i += 256) mx = fmaxf(mx, src[i]);
    mx = block_reduce_max(mx, sbuf);
    float s = 0.f;
    float ev[16];
    #pragma unroll
    for (int j = 0; j < 16; j++) {
        int i = tid + j * 256;
        ev[j] = expf(src[i] - mx);
        s += ev[j];
    }
    s = block_reduce_sum(s, sbuf);
    float inv = 1.f / s;
    #pragma unroll
    for (int j = 0; j < 16; j++) {
        int i = tid + j * 256;
        float v = ev[j] * inv;
        bf16 h = __float2bfloat16(v);
        dh[i] = h;
        dl[i] = __float2bfloat16(v - __bfloat162float(h));
    }
}

// ---- zero cen ----
__global__ void zero_cen_kernel(float* __restrict__ cen)
{
    int i = blockIdx.x * blockDim.x + threadIdx.x;
    if (i < 307200) cen[i] = 0.f;
}

// ---- C_in gating + LayerNorm ----
__global__ void cin_kernel(const float* __restrict__ cen,
                           const float* __restrict__ alpha,
                           const float* __restrict__ beta,
                           const float* __restrict__ nw,
                           const float* __restrict__ nb,
                           float* __restrict__ cinln)
{
    __shared__ float sbuf[8];
    int bk = blockIdx.x;
    int b = bk / NC, k = bk % NC;
    int c = threadIdx.x;
    float last = cen[((size_t)(b * TT4 + 3) * NC + k) * CC + c];
    float pv[3];
    #pragma unroll
    for (int t = 0; t < 3; t++)
        pv[t] = cen[((size_t)(b * TT4 + t) * NC + k) * CC + c];
    float nl = block_reduce_sum(last * last, sbuf);
    float al = alpha[0], be = beta[0];
    float g[3];
    #pragma unroll
    for (int t = 0; t < 3; t++) {
        float dt = block_reduce_sum(last * pv[t], sbuf);
        float np = block_reduce_sum(pv[t] * pv[t], sbuf);
        float denom = fmaxf(sqrtf(nl) * sqrtf(np), 1e-8f);
        g[t] = 1.f / (1.f + expf(-(be + al * dt / denom)));
    }
    float cin = last + g[0] * pv[0] + g[1] * pv[1] + g[2] * pv[2];
    float mean = block_reduce_sum(cin, sbuf) * (1.f / CC);
    float d = cin - mean;
    float var = block_reduce_sum(d * d, sbuf) * (1.f / CC);
    cinln[((size_t)b * NC + k) * CC + c] = d * rsqrtf(var + 1e-5f) * nw[c] + nb[c];
}

// ---- attention -> bf16 hi/lo output ----
__global__ void attn_kernel(const float* __restrict__ q,
                            const float* __restrict__ kbuf,
                            const float* __restrict__ vbuf,
                            bf16* __restrict__ obh, bf16* __restrict__ obl)
{
    __shared__ float kh[NC * 33];
    __shared__ float vh[NC * 33];
    int b = blockIdx.z, h = blockIdx.y;
    int tid = threadIdx.x;
    int warp = tid >> 5, lane = tid & 31;
    for (int idx = tid; idx < NC * HD; idx += blockDim.x) {
        int kk = idx / HD, d = idx % HD;
        kh[kk * 33 + d] = kbuf[((size_t)b * NC + kk) * CC + h * HD + d];
        vh[kk * 33 + d] = vbuf[((size_t)b * NC + kk) * CC + h * HD + d];
    }
    __syncthreads();
    const unsigned FULL = 0xffffffffu;
    for (int ni = warp; ni < 256; ni += 8) {
        int n = blockIdx.x * 256 + ni;
        float qv = q[((size_t)b * N4 + n) * CC + h * HD + lane];
        float lg[5];
        #pragma unroll
        for (int i = 0; i < 5; i++) {
            int kk = lane + 32 * i;
            int kks = (kk < NC) ? kk : (NC - 1);
            float acc = 0.f;
            #pragma unroll
            for (int d = 0; d < 32; d++) {
                float qd = __shfl_sync(FULL, qv, d);
                acc += qd * kh[kks * 33 + d];
            }
            lg[i] = (kk < NC) ? acc : -3.4e38f;
        }
        float mx = lg[0];
        #pragma unroll
        for (int i = 1; i < 5; i++) mx = fmaxf(mx, lg[i]);
        #pragma unroll
        for (int off = 16; off > 0; off >>= 1)
            mx = fmaxf(mx, __shfl_xor_sync(FULL, mx, off));
        float p[5], s = 0.f;
        #pragma unroll
        for (int i = 0; i < 5; i++) { p[i] = expf(lg[i] - mx); s += p[i]; }
        #pragma unroll
        for (int off = 16; off > 0; off >>= 1)
            s += __shfl_xor_sync(FULL, s, off);
        float inv = 1.f / s;
        float od = 0.f;
        #pragma unroll
        for (int i = 0; i < 5; i++) {
            float pi = p[i] * inv;
            #pragma unroll
            for (int l = 0; l < 32; l++) {
                float a = __shfl_sync(FULL, pi, l);
                int kk = l + 32 * i;
                if (kk < NC) od += a * vh[kk * 33 + lane];
            }
        }
        size_t idx = ((size_t)b * N4 + n) * CC + h * HD + lane;
        bf16 hh = __float2bfloat16(od);
        obh[idx] = hh;
        obl[idx] = __float2bfloat16(od - __bfloat162float(hh));
    }
}

// ---- out = base + LN(xin) ----
__global__ void ln_add_kernel(const float* __restrict__ base,
                              const float* __restrict__ xin,
                              const float* __restrict__ nw,
                              const float* __restrict__ nb,
                              float* __restrict__ out)
{
    __shared__ float sbuf[8];
    size_t row = blockIdx.x;
    int c = threadIdx.x;
    float v = xin[row * CC + c];
    float mean = block_reduce_sum(v, sbuf) * (1.f / CC);
    float d = v - mean;
    float var = block_reduce_sum(d * d, sbuf) * (1.f / CC);
    out[row * CC + c] = base[row * CC + c] + d * rsqrtf(var + 1e-5f) * nw[c] + nb[c];
}

// ---- out = base + LN(xin), + bf16 split ----
__global__ void ln_add_split_kernel(const float* __restrict__ base,
                                    const float* __restrict__ xin,
                                    const float* __restrict__ nw,
                                    const float* __restrict__ nb,
                                    float* __restrict__ out,
                                    bf16* __restrict__ ohi, bf16* __restrict__ olo)
{
    __shared__ float sbuf[8];
    size_t row = blockIdx.x;
    int c = threadIdx.x;
    float v = xin[row * CC + c];
    float mean = block_reduce_sum(v, sbuf) * (1.f / CC);
    float d = v - mean;
    float var = block_reduce_sum(d * d, sbuf) * (1.f / CC);
    float r = base[row * CC + c] + d * rsqrtf(var + 1e-5f) * nw[c] + nb[c];
    size_t idx = row * CC + c;
    out[idx] = r;
    bf16 h = __float2bfloat16(r);
    ohi[idx] = h;
    olo[idx] = __float2bfloat16(r - __bfloat162float(h));
}

// ---- depthwise conv + GELU -> bf16 hi/lo ----
__global__ void dwconv_gelu_bf16_kernel(const float* __restrict__ h1,
                                        const float* __restrict__ dw_w,
                                        const float* __restrict__ dw_b,
                                        bf16* __restrict__ gh, bf16* __restrict__ gl)
{
    int idx = blockIdx.x * blockDim.x + threadIdx.x;
    if (idx >= BB * N4 * HID) return;
    int ch = idx & (HID - 1);
    int r = idx >> 10;
    int n = r & (N4 - 1);
    int b = r >> 12;
    int y = n >> 6, x = n & 63;
    float acc = dw_b[ch];
    #pragma unroll
    for (int dy = 0; dy < 3; dy++) {
        int yy = y + dy - 1;
        if (yy < 0 || yy >= HH) continue;
        #pragma unroll
        for (int dx = 0; dx < 3; dx++) {
            int xx = x + dx - 1;
            if (xx < 0 || xx >= WW) continue;
            acc += h1[((size_t)b * N4 + yy * WW + xx) * HID + ch] *
                   dw_w[ch * 9 + dy * 3 + dx];
        }
    }
    float v = 0.5f * acc * (1.0f + erff(acc * 0.70710678118654752f));
    bf16 h = __float2bfloat16(v);
    gh[idx] = h;
    gl[idx] = __float2bfloat16(v - __bfloat162float(h));
}

// ================= host launcher =================
#define SMEM_W4  92160
#define SMEM_W8  122880

extern "C" void kernel_launch(void* const* d_in, const int* in_sizes, int n_in,
                              void* d_out, int out_size)
{
    const float* x      = (const float*)d_in[0];
    const float* z      = (const float*)d_in[1];
    const float* mem    = (const float*)d_in[2];
    const float* cw     = (const float*)d_in[3];
    const float* p1     = (const float*)d_in[4];
    const float* tdt1   = (const float*)d_in[5];
    const float* p2     = (const float*)d_in[6];
    const float* tdt2   = (const float*)d_in[7];
    const float* alpha  = (const float*)d_in[8];
    const float* beta   = (const float*)d_in[9];
    const float* q_w    = (const float*)d_in[10];
    const float* q_b    = (const float*)d_in[11];
    const float* k_w    = (const float*)d_in[12];
    const float* k_b    = (const float*)d_in[13];
    const float* v_w    = (const float*)d_in[14];
    const float* v_b    = (const float*)d_in[15];
    const float* proj_w = (const float*)d_in[16];
    const float* proj_b = (const float*)d_in[17];
    const float* norm_w = (const float*)d_in[18];
    const float* norm_b = (const float*)d_in[19];
    const float* fc1_w  = (const float*)d_in[20];
    const float* fc1_b  = (const float*)d_in[21];
    const float* dw_w   = (const float*)d_in[22];
    const float* dw_b   = (const float*)d_in[23];
    const float* fc2_w  = (const float*)d_in[24];
    const float* fc2_b  = (const float*)d_in[25];

    float* out0 = (float*)d_out;
    float* cxz  = out0 + OUT0_ELEMS;
    float* ctr  = out0 + OUT0_ELEMS + CXZ_ELEMS;

    float *cl, *cz, *cc, *cen, *cinln, *kb, *vb, *qb, *oproj, *out1, *h1, *h2;
    bf16 *xh, *xl, *memh, *meml, *xth, *xtl, *memth, *memtl, *cwh, *cwl;
    bf16 *t1h, *t1l, *t2h, *t2l, *zth, *ztl, *clth, *cltl;
    bf16 *softh, *softl, *obh, *obl, *o1h, *o1l, *gh, *gl;
    bf16 *qwh, *qwl, *pwh, *pwl, *f1h, *f1l, *f2h, *f2l;
    cudaGetSymbolAddress((void**)&cl,    g_cl);
    cudaGetSymbolAddress((void**)&cz,    g_cz);
    cudaGetSymbolAddress((void**)&cc,    g_cc);
    cudaGetSymbolAddress((void**)&cen,   g_cen);
    cudaGetSymbolAddress((void**)&cinln, g_cinln);
    cudaGetSymbolAddress((void**)&kb,    g_kbuf);
    cudaGetSymbolAddress((void**)&vb,    g_vbuf);
    cudaGetSymbolAddress((void**)&qb,    g_q);
    cudaGetSymbolAddress((void**)&oproj, g_oproj);
    cudaGetSymbolAddress((void**)&out1,  g_out1);
    cudaGetSymbolAddress((void**)&h1,    g_h1);
    cudaGetSymbolAddress((void**)&h2,    g_h2);
    cudaGetSymbolAddress((void**)&xh,   g_xh);   cudaGetSymbolAddress((void**)&xl,   g_xl);
    cudaGetSymbolAddress((void**)&memh, g_memh); cudaGetSymbolAddress((void**)&meml, g_meml);
    cudaGetSymbolAddress((void**)&xth,  g_xth);  cudaGetSymbolAddress((void**)&xtl,  g_xtl);
    cudaGetSymbolAddress((void**)&memth, g_memth); cudaGetSymbolAddress((void**)&memtl, g_memtl);
    cudaGetSymbolAddress((void**)&cwh,  g_cwh);  cudaGetSymbolAddress((void**)&cwl,  g_cwl);
    cudaGetSymbolAddress((void**)&t1h,  g_t1h);  cudaGetSymbolAddress((void**)&t1l,  g_t1l);
    cudaGetSymbolAddress((void**)&t2h,  g_t2h);  cudaGetSymbolAddress((void**)&t2l,  g_t2l);
    cudaGetSymbolAddress((void**)&zth,  g_zth);  cudaGetSymbolAddress((void**)&ztl,  g_ztl);
    cudaGetSymbolAddress((void**)&clth, g_clth); cudaGetSymbolAddress((void**)&cltl, g_cltl);
    cudaGetSymbolAddress((void**)&softh, g_softh); cudaGetSymbolAddress((void**)&softl, g_softl);
    cudaGetSymbolAddress((void**)&obh, g_obh); cudaGetSymbolAddress((void**)&obl, g_obl);
    cudaGetSymbolAddress((void**)&o1h, g_o1h); cudaGetSymbolAddress((void**)&o1l, g_o1l);
    cudaGetSymbolAddress((void**)&gh,  g_gh);  cudaGetSymbolAddress((void**)&gl,  g_gl);
    cudaGetSymbolAddress((void**)&qwh, g_qwh); cudaGetSymbolAddress((void**)&qwl, g_qwl);
    cudaGetSymbolAddress((void**)&pwh, g_pwh); cudaGetSymbolAddress((void**)&pwl, g_pwl);
    cudaGetSymbolAddress((void**)&f1h, g_f1h); cudaGetSymbolAddress((void**)&f1l, g_f1l);
    cudaGetSymbolAddress((void**)&f2h, g_f2h); cudaGetSymbolAddress((void**)&f2l, g_f2l);

    cudaFuncSetAttribute(hmma_gemm_kernel<4>,
                         cudaFuncAttributeMaxDynamicSharedMemorySize, SMEM_W4);
    cudaFuncSetAttribute(hmma_gemm_kernel<8>,
                         cudaFuncAttributeMaxDynamicSharedMemorySize, SMEM_W8);
    cudaFuncSetAttribute(cl_hmma_kernel,
                         cudaFuncAttributeMaxDynamicSharedMemorySize, SMEM_W8);
    cudaFuncSetAttribute(cen_hmma_kernel,
                         cudaFuncAttributeMaxDynamicSharedMemorySize, SMEM_W8);
    cudaFuncSetAttribute(comb_hmma_kernel,
                         cudaFuncAttributeMaxDynamicSharedMemorySize, SMEM_W4);

    // 0) prep
    split_all_kernel<<<dim3(128, 8, 2), dim3(32, 8)>>>(x, xh, xl, xth, xtl);
    split_all_kernel<<<dim3(128, 8, 6), dim3(32, 8)>>>(mem, memh, meml, memth, memtl);
    cvt_split5_kernel<<<dim3(256, 5), 256>>>(
        q_w, qwh, qwl, 65536,
        proj_w, pwh, pwl, 65536,
        fc1_w, f1h, f1l, 262144,
        fc2_w, f2h, f2l, 262144,
        cw, cwh, cwl, 38400);
    tdt_prep_kernel<<<100, 256>>>(tdt1, tdt2, t1h, t1l, t2h, t2l);
    zT_split_kernel<<<dim3(512, 5, 2), dim3(32, 8)>>>(z, zth, ztl);

    // 1) cl (HMMA)
    cl_hmma_kernel<<<dim3(32, 2, 8), 256, SMEM_W8>>>(cwh, cwl, xh, xl, memh, meml, cl);
    // 2) prompt cos -> scale vectors; clT split
    prompt_scale_kernel<<<dim3(TNE / 256, 1, BB), 256>>>(z, cl, p1, p2, cz, cc);
    clT_split_kernel<<<dim3(128, 5, 8), dim3(32, 8)>>>(cl, clth, cltl);
    // 3) combine (HMMA) -> cluster_x_z + center
    comb_hmma_kernel<<<dim3(256, 2, 2), 256, SMEM_W4>>>(
        t1h, t1l, t2h, t2l, zth, ztl, clth, cltl, cz, cc, cxz, ctr);
    // 4) softmax -> bf16 hi/lo
    softmax_kernel<<<BB * TT4 * NC, 256>>>(cxz, softh, softl);
    // 5) cen (HMMA, split-K atomic)
    zero_cen_kernel<<<(307200 + 255) / 256, 256>>>(cen);
    cen_hmma_kernel<<<dim3(2, 2, 64), 256, SMEM_W8>>>(softh, softl, xth, xtl, memth, memtl, cen);
    // 6) gating + LN
    cin_kernel<<<BB * NC, 256>>>(cen, alpha, beta, norm_w, norm_b, cinln);
    // 7) k/v projections (merged)
    gemm_kv_kernel<<<dim3(4, 5, 2), 256>>>(cinln, k_w, k_b, v_w, v_b, kb, vb);
    // 8) q projection
    hmma_gemm_kernel<4><<<dim3(4, 64), 256, SMEM_W4>>>(
        xh, xl, qwh, qwl, q_b, qb, CC, CC, 0.17677669529663687f);
    // 9) attention -> bf16 split
    attn_kernel<<<dim3(N4 / 256, NH, BB), 256>>>(qb, kb, vb, obh, obl);
    // 10) output projection
    hmma_gemm_kernel<4><<<dim3(4, 64), 256, SMEM_W4>>>(
        obh, obl, pwh, pwl, proj_b, oproj, CC, CC, 1.f);
    // 11) out1 = x + LN(oproj), + split
    ln_add_split_kernel<<<BB * N4, 256>>>(x, oproj, norm_w, norm_b, out1, o1h, o1l);
    // 12) fc1
    hmma_gemm_kernel<8><<<dim3(8, 64), 256, SMEM_W8>>>(
        o1h, o1l, f1h, f1l, fc1_b, h1, HID, CC, 1.f);
    // 13) depthwise conv + gelu -> split
    dwconv_gelu_bf16_kernel<<<(BB * N4 * HID + 255) / 256, 256>>>(h1, dw_w, dw_b, gh, gl);
    // 14) fc2
    hmma_gemm_kernel<4><<<dim3(4, 64), 256, SMEM_W4>>>(
        gh, gl, f2h, f2l, fc2_b, h2, CC, HID, 1.f);
    // 15) out = out1 + LN(h2)
    ln_add_kernel<<<BB * N4, 256>>>(out1, h2, norm_w, norm_b, out0);
}

// round 16
// speedup vs baseline: 1.0862x; 1.0084x over previous
#include <cuda_runtime.h>
#include <cuda_bf16.h>
#include <math.h>
#include <stdint.h>

typedef __nv_bfloat16 bf16;

// ---------------- fixed problem dims ----------------
#define BB   2
#define TT4  4
#define N4   4096
#define CC   256
#define NC   150
#define TNE  16384
#define HID  1024
#define NH   8
#define HD   32
#define HH   64
#define WW   64
#define KPAD 160

#define OUT0_ELEMS 2097152
#define CXZ_ELEMS  4915200

// ---------------- scratch ----------------
__device__ float g_cl[4915200];
__device__ float g_cz[32768], g_cc[32768];
__device__ float g_cen[307200];
__device__ float g_cinln[76800];
__device__ float g_kbuf[76800];
__device__ float g_vbuf[76800];
__device__ float g_q[2097152];
__device__ float g_oproj[2097152];
__device__ float g_out1[2097152];
__device__ float g_h1[8388608];
__device__ float g_h2[2097152];

// bf16 hi/lo split buffers
__device__ bf16 g_xh[2097152],   g_xl[2097152];
__device__ bf16 g_memh[6291456], g_meml[6291456];
__device__ bf16 g_xth[2097152],  g_xtl[2097152];
__device__ bf16 g_memth[6291456], g_memtl[6291456];
__device__ bf16 g_cwh[38400],    g_cwl[38400];
__device__ bf16 g_t1h[25600], g_t1l[25600], g_t2h[25600], g_t2l[25600];
__device__ bf16 g_zth[5242880],  g_ztl[5242880];
__device__ bf16 g_clth[5242880], g_cltl[5242880];
__device__ bf16 g_softh[4915200], g_softl[4915200];
__device__ bf16 g_obh[2097152], g_obl[2097152];
__device__ bf16 g_o1h[2097152], g_o1l[2097152];
__device__ bf16 g_gh[8388608],  g_gl[8388608];
__device__ bf16 g_qwh[65536],  g_qwl[65536];
__device__ bf16 g_pwh[65536],  g_pwl[65536];
__device__ bf16 g_f1h[262144], g_f1l[262144];
__device__ bf16 g_f2h[262144], g_f2l[262144];

// ---------------- warp-level bf16 MMA + cp.async ----------
__device__ __forceinline__ void mma16816(float* d, const uint32_t* a, const uint32_t* b) {
    asm volatile(
        "mma.sync.aligned.m16n8k16.row.col.f32.bf16.bf16.f32 "
        "{%0,%1,%2,%3}, {%4,%5,%6,%7}, {%8,%9}, {%0,%1,%2,%3};\n"
        : "+f"(d[0]), "+f"(d[1]), "+f"(d[2]), "+f"(d[3])
        : "r"(a[0]), "r"(a[1]), "r"(a[2]), "r"(a[3]), "r"(b[0]), "r"(b[1]));
}
__device__ __forceinline__ uint32_t smem_to_u32(const void* p) {
    uint32_t a;
    asm("{ .reg .u64 t; cvta.to.shared.u64 t, %1; cvt.u32.u64 %0, t; }"
        : "=r"(a) : "l"(p));
    return a;
}
__device__ __forceinline__ void cp_async16(uint32_t s, const void* g, bool v) {
    int sz = v ? 16 : 0;
    asm volatile("cp.async.cg.shared.global [%0], [%1], 16, %2;\n"
                 :: "r"(s), "l"(g), "r"(sz));
}
__device__ __forceinline__ void cp_commit() {
    asm volatile("cp.async.commit_group;\n" ::: "memory");
}
template<int N> __device__ __forceinline__ void cp_wait() {
    asm volatile("cp.async.wait_group %0;\n" :: "n"(N) : "memory");
}

#define SAS 40

template<int WNT>
__device__ __forceinline__ void hmma_chunk(
    bf16 (*sAh)[SAS], bf16 (*sAl)[SAS], bf16 (*sBh)[SAS], bf16 (*sBl)[SAS],
    int wm, int wn, int g, int tg, float (*acc)[WNT][4])
{
    #pragma unroll
    for (int ks = 0; ks < 2; ks++) {
        int kc = ks * 16 + tg * 2;
        uint32_t ah[2][4], al[2][4], bh[WNT][2], bl[WNT][2];
        #pragma unroll
        for (int mt = 0; mt < 2; mt++) {
            int r = wm * 32 + mt * 16 + g;
            ah[mt][0] = *(const uint32_t*)&sAh[r][kc];
            ah[mt][1] = *(const uint32_t*)&sAh[r + 8][kc];
            ah[mt][2] = *(const uint32_t*)&sAh[r][kc + 8];
            ah[mt][3] = *(const uint32_t*)&sAh[r + 8][kc + 8];
            al[mt][0] = *(const uint32_t*)&sAl[r][kc];
            al[mt][1] = *(const uint32_t*)&sAl[r + 8][kc];
            al[mt][2] = *(const uint32_t*)&sAl[r][kc + 8];
            al[mt][3] = *(const uint32_t*)&sAl[r + 8][kc + 8];
        }
        #pragma unroll
        for (int nt = 0; nt < WNT; nt++) {
            int nr = wn * (WNT * 8) + nt * 8 + g;
            bh[nt][0] = *(const uint32_t*)&sBh[nr][kc];
            bh[nt][1] = *(const uint32_t*)&sBh[nr][kc + 8];
            bl[nt][0] = *(const uint32_t*)&sBl[nr][kc];
            bl[nt][1] = *(const uint32_t*)&sBl[nr][kc + 8];
        }
        #pragma unroll
        for (int mt = 0; mt < 2; mt++)
            #pragma unroll
            for (int nt = 0; nt < WNT; nt++) {
                mma16816(acc[mt][nt], ah[mt], bh[nt]);
                mma16816(acc[mt][nt], ah[mt], bl[nt]);
                mma16816(acc[mt][nt], al[mt], bh[nt]);
            }
    }
}

// ---- 3-stage cp.async pipelined mainloop ----
template<int WNT, typename F>
__device__ __forceinline__ void hmma_pipe(char* sm, int nk, F getp, float (*acc)[WNT][4])
{
    constexpr int BN = 16 * WNT;
    constexpr int ASZ = 128 * SAS * 2;
    constexpr int BSZ = BN * SAS * 2;
    constexpr int STG = 2 * ASZ + 2 * BSZ;
    int tid = threadIdx.x;
    int wid = tid >> 5, lane = tid & 31;
    int wm = wid & 3, wn = wid >> 2, g = lane >> 2, tg = lane & 3;
    int lrow = tid >> 1, lhalf = (tid & 1) * 16;
    bool bload = (WNT == 8) || (tid < BN * 2);
    uint32_t sb = smem_to_u32(sm);
    uint32_t off = (uint32_t)(lrow * SAS + lhalf) * 2;

    __syncthreads();

    auto issue = [&](int c) {
        uint32_t st = sb + (c % 3) * STG;
        const bf16 *ah, *al, *bh, *bl; bool av;
        getp(c, ah, al, bh, bl, av);
        cp_async16(st + off, ah, av);
        cp_async16(st + off + 16, ah + 8, av);
        cp_async16(st + ASZ + off, al, av);
        cp_async16(st + ASZ + off + 16, al + 8, av);
        if (bload) {
            cp_async16(st + 2 * ASZ + off, bh, true);
            cp_async16(st + 2 * ASZ + off + 16, bh + 8, true);
            cp_async16(st + 2 * ASZ + BSZ + off, bl, true);
            cp_async16(st + 2 * ASZ + BSZ + off + 16, bl + 8, true);
        }
        cp_commit();
    };

    issue(0); issue(1);
    for (int c = 0; c < nk; c++) {
        if (c + 2 <= nk) cp_wait<1>(); else cp_wait<0>();
        __syncthreads();
        {
            char* st = sm + (c % 3) * STG;
            bf16 (*sAh)[SAS] = (bf16(*)[SAS])st;
            bf16 (*sAl)[SAS] = (bf16(*)[SAS])(st + ASZ);
            bf16 (*sBh)[SAS] = (bf16(*)[SAS])(st + 2 * ASZ);
            bf16 (*sBl)[SAS] = (bf16(*)[SAS])(st + 2 * ASZ + BSZ);
            hmma_chunk<WNT>(sAh, sAl, sBh, sBl, wm, wn, g, tg, acc);
        }
        if (c + 2 < nk) issue(c + 2);
    }
}

// ================= HMMA GEMM (proj/fc1/fc2) ============
template<int WNT>
__global__ void __launch_bounds__(256)
hmma_gemm_kernel(const bf16* __restrict__ Ah, const bf16* __restrict__ Al,
                 const bf16* __restrict__ Bh, const bf16* __restrict__ Bl,
                 const float* __restrict__ bias, float* __restrict__ C,
                 int Ntot, int K, float scale)
{
    extern __shared__ char sm[];
    constexpr int BN = 16 * WNT;
    int tid = threadIdx.x, wid = tid >> 5, lane = tid & 31;
    int wm = wid & 3, wn = wid >> 2, g = lane >> 2, tg = lane & 3;
    int m0 = blockIdx.y * 128, n0 = blockIdx.x * BN;
    int lrow = tid >> 1, lhalf = (tid & 1) * 16;

    float acc[2][WNT][4] = {};
    auto getp = [&](int c, const bf16*& ah, const bf16*& al,
                    const bf16*& bh, const bf16*& bl, bool& av) {
        int k0 = (c << 5) + lhalf;
        ah = Ah + (size_t)(m0 + lrow) * K + k0;
        al = Al + (size_t)(m0 + lrow) * K + k0;
        bh = Bh + (size_t)(n0 + lrow) * K + k0;
        bl = Bl + (size_t)(n0 + lrow) * K + k0;
        av = true;
    };
    hmma_pipe<WNT>(sm, K >> 5, getp, acc);

    #pragma unroll
    for (int mt = 0; mt < 2; mt++) {
        int r0 = m0 + wm * 32 + mt * 16 + g;
        #pragma unroll
        for (int nt = 0; nt < WNT; nt++) {
            int col = n0 + wn * (WNT * 8) + nt * 8 + tg * 2;
            float b0 = bias[col], b1 = bias[col + 1];
            float2 v0, v1;
            v0.x = (acc[mt][nt][0] + b0) * scale;
            v0.y = (acc[mt][nt][1] + b1) * scale;
            v1.x = (acc[mt][nt][2] + b0) * scale;
            v1.y = (acc[mt][nt][3] + b1) * scale;
            *(float2*)&C[(size_t)r0 * Ntot + col] = v0;
            *(float2*)&C[(size_t)(r0 + 8) * Ntot + col] = v1;
        }
    }
}

// ================= merged cl + q HMMA =================
// grid (32, 2, 12): z<8 -> cl tile (bt=z), z>=8 -> q-projection tile
__global__ void __launch_bounds__(256)
clq_hmma_kernel(const bf16* __restrict__ cwh, const bf16* __restrict__ cwl,
                const bf16* __restrict__ xh, const bf16* __restrict__ xl,
                const bf16* __restrict__ memh, const bf16* __restrict__ meml,
                float* __restrict__ cl,
                const bf16* __restrict__ qwh, const bf16* __restrict__ qwl,
                const float* __restrict__ q_b, float* __restrict__ qb)
{
    extern __shared__ char sm[];
    int tid = threadIdx.x, wid = tid >> 5, lane = tid & 31;
    int wm = wid & 3, wn = wid >> 2, g = lane >> 2, tg = lane & 3;
    int lrow = tid >> 1, lhalf = (tid & 1) * 16;

    if (blockIdx.z < 8) {
        int bt = blockIdx.z, b = bt >> 2, t = bt & 3;
        const bf16* Bh = (t < 3) ? memh + (size_t)(b * 3 + t) * 1048576 : xh + (size_t)b * 1048576;
        const bf16* Bl = (t < 3) ? meml + (size_t)(b * 3 + t) * 1048576 : xl + (size_t)b * 1048576;
        float* Cp = cl + (size_t)bt * 614400;
        int m0 = blockIdx.y * 128, n0 = blockIdx.x * 128;
        bool aval = (m0 + lrow) < NC;

        float acc[2][8][4] = {};
        auto getp = [&](int c, const bf16*& ah, const bf16*& al,
                        const bf16*& bh, const bf16*& bl, bool& av) {
            int k0 = (c << 5) + lhalf;
            ah = cwh + (size_t)(m0 + lrow) * CC + k0;
            al = cwl + (size_t)(m0 + lrow) * CC + k0;
            bh = Bh + (size_t)(n0 + lrow) * CC + k0;
            bl = Bl + (size_t)(n0 + lrow) * CC + k0;
            av = aval;
        };
        hmma_pipe<8>(sm, 8, getp, acc);

        #pragma unroll
        for (int mt = 0; mt < 2; mt++) {
            int r0 = m0 + wm * 32 + mt * 16 + g;
            #pragma unroll
            for (int nt = 0; nt < 8; nt++) {
                int col = n0 + wn * 64 + nt * 8 + tg * 2;
                if (r0 < NC)
                    *(float2*)&Cp[(size_t)r0 * N4 + col] = make_float2(acc[mt][nt][0], acc[mt][nt][1]);
                if (r0 + 8 < NC)
                    *(float2*)&Cp[(size_t)(r0 + 8) * N4 + col] = make_float2(acc[mt][nt][2], acc[mt][nt][3]);
            }
        }
    } else {
        int id = (blockIdx.z - 8) * 64 + blockIdx.y * 32 + blockIdx.x;   // 0..255
        int m0 = (id >> 2) * 128, n0 = (id & 3) * 64;
        const float scale = 0.17677669529663687f;

        float acc[2][4][4] = {};
        auto getp = [&](int c, const bf16*& ah, const bf16*& al,
                        const bf16*& bh, const bf16*& bl, bool& av) {
            int k0 = (c << 5) + lhalf;
            ah = xh + (size_t)(m0 + lrow) * CC + k0;
            al = xl + (size_t)(m0 + lrow) * CC + k0;
            bh = qwh + (size_t)(n0 + lrow) * CC + k0;
            bl = qwl + (size_t)(n0 + lrow) * CC + k0;
            av = true;
        };
        hmma_pipe<4>(sm, 8, getp, acc);

        #pragma unroll
        for (int mt = 0; mt < 2; mt++) {
            int r0 = m0 + wm * 32 + mt * 16 + g;
            #pragma unroll
            for (int nt = 0; nt < 4; nt++) {
                int col = n0 + wn * 32 + nt * 8 + tg * 2;
                float b0 = q_b[col], b1 = q_b[col + 1];
                float2 v0, v1;
                v0.x = (acc[mt][nt][0] + b0) * scale;
                v0.y = (acc[mt][nt][1] + b1) * scale;
                v1.x = (acc[mt][nt][2] + b0) * scale;
                v1.y = (acc[mt][nt][3] + b1) * scale;
                *(float2*)&qb[(size_t)r0 * CC + col] = v0;
                *(float2*)&qb[(size_t)(r0 + 8) * CC + col] = v1;
            }
        }
    }
}

// ================= comb HMMA =================
__global__ void __launch_bounds__(256)
comb_hmma_kernel(const bf16* __restrict__ t1h, const bf16* __restrict__ t1l,
                 const bf16* __restrict__ t2h, const bf16* __restrict__ t2l,
                 const bf16* __restrict__ zth, const bf16* __restrict__ ztl,
                 const bf16* __restrict__ clth, const bf16* __restrict__ cltl,
                 const float* __restrict__ cz, const float* __restrict__ cc,
                 float* __restrict__ cxz, float* __restrict__ ctr)
{
    extern __shared__ char sm[];
    int b = blockIdx.z;
    int j0 = blockIdx.y * 128, n0 = blockIdx.x * 64;
    int tid = threadIdx.x, wid = tid >> 5, lane = tid & 31;
    int wm = wid & 3, wn = wid >> 2, g = lane >> 2, tg = lane & 3;
    int lrow = tid >> 1, lhalf = (tid & 1) * 16;
    bool aval = (j0 + lrow) < KPAD;

    float acc1[2][4][4] = {}, acc2[2][4][4] = {};
    const bf16* Bz_h = zth + (size_t)b * TNE * KPAD;
    const bf16* Bz_l = ztl + (size_t)b * TNE * KPAD;
    const bf16* Bc_h = clth + (size_t)b * TNE * KPAD;
    const bf16* Bc_l = cltl + (size_t)b * TNE * KPAD;

    auto getp1 = [&](int c, const bf16*& ah, const bf16*& al,
                     const bf16*& bh, const bf16*& bl, bool& av) {
        int k0 = (c << 5) + lhalf;
        ah = t1h + (size_t)(j0 + lrow) * KPAD + k0;
        al = t1l + (size_t)(j0 + lrow) * KPAD + k0;
        bh = Bz_h + (size_t)(n0 + lrow) * KPAD + k0;
        bl = Bz_l + (size_t)(n0 + lrow) * KPAD + k0;
        av = aval;
    };
    hmma_pipe<4>(sm, 5, getp1, acc1);
    auto getp2 = [&](int c, const bf16*& ah, const bf16*& al,
                     const bf16*& bh, const bf16*& bl, bool& av) {
        int k0 = (c << 5) + lhalf;
        ah = t2h + (size_t)(j0 + lrow) * KPAD + k0;
        al = t2l + (size_t)(j0 + lrow) * KPAD + k0;
        bh = Bc_h + (size_t)(n0 + lrow) * KPAD + k0;
        bl = Bc_l + (size_t)(n0 + lrow) * KPAD + k0;
        av = aval;
    };
    hmma_pipe<4>(sm, 5, getp2, acc2);

    #pragma unroll
    for (int mt = 0; mt < 2; mt++) {
        int r0 = j0 + wm * 32 + mt * 16 + g;
        #pragma unroll
        for (int nt = 0; nt < 4; nt++) {
            int col = n0 + wn * 32 + nt * 8 + tg * 2;
            float s0z = cz[(size_t)b * TNE + col],     s1z = cz[(size_t)b * TNE + col + 1];
            float s0c = cc[(size_t)b * TNE + col],     s1c = cc[(size_t)b * TNE + col + 1];
            int t = col >> 12, n = col & 4095;
            if (r0 < NC) {
                float2 v;
                v.x = s0z * acc1[mt][nt][0] + s0c * acc2[mt][nt][0];
                v.y = s1z * acc1[mt][nt][1] + s1c * acc2[mt][nt][1];
                *(float2*)&cxz[((size_t)b * NC + r0) * TNE + col] = v;
                *(float2*)&ctr[((size_t)(b * TT4 + t) * NC + r0) * N4 + n] = v;
            }
            if (r0 + 8 < NC) {
                float2 v;
                v.x = s0z * acc1[mt][nt][2] + s0c * acc2[mt][nt][2];
                v.y = s1z * acc1[mt][nt][3] + s1c * acc2[mt][nt][3];
                *(float2*)&cxz[((size_t)b * NC + r0 + 8) * TNE + col] = v;
                *(float2*)&ctr[((size_t)(b * TT4 + t) * NC + r0 + 8) * N4 + n] = v;
            }
        }
    }
}

// ================= cen HMMA (3-term, split-K, atomic) =================
__global__ void __launch_bounds__(256)
cen_hmma_kernel(const bf16* __restrict__ softh, const bf16* __restrict__ softl,
                const bf16* __restrict__ xth, const bf16* __restrict__ xtl,
                const bf16* __restrict__ memth, const bf16* __restrict__ memtl,
                float* __restrict__ cen)
{
    extern __shared__ char sm[];
    int bt = blockIdx.z >> 3, sp = blockIdx.z & 7;
    int b = bt >> 2, t = bt & 3;
    const bf16* Ah = softh + (size_t)bt * 614400;
    const bf16* Al = softl + (size_t)bt * 614400;
    const bf16* Bh = (t < 3) ? memth + (size_t)(b * 3 + t) * 1048576 : xth + (size_t)b * 1048576;
    const bf16* Bl = (t < 3) ? memtl + (size_t)(b * 3 + t) * 1048576 : xtl + (size_t)b * 1048576;
    float* Cp = cen + (size_t)bt * 38400;
    int koff = sp * 512;

    int tid = threadIdx.x, wid = tid >> 5, lane = tid & 31;
    int wm = wid & 3, wn = wid >> 2, g = lane >> 2, tg = lane & 3;
    int m0 = blockIdx.y * 128, n0 = blockIdx.x * 128;
    int lrow = tid >> 1, lhalf = (tid & 1) * 16;
    bool aval = (m0 + lrow) < NC;

    float acc[2][8][4] = {};
    auto getp = [&](int c, const bf16*& ah, const bf16*& al,
                    const bf16*& bh, const bf16*& bl, bool& av) {
        int k0 = koff + (c << 5) + lhalf;
        ah = Ah + (size_t)(m0 + lrow) * N4 + k0;
        al = Al + (size_t)(m0 + lrow) * N4 + k0;
        bh = Bh + (size_t)(n0 + lrow) * N4 + k0;
        bl = Bl + (size_t)(n0 + lrow) * N4 + k0;
        av = aval;
    };
    hmma_pipe<8>(sm, 16, getp, acc);

    #pragma unroll
    for (int mt = 0; mt < 2; mt++) {
        int r0 = m0 + wm * 32 + mt * 16 + g;
        #pragma unroll
        for (int nt = 0; nt < 8; nt++) {
            int col = n0 + wn * 64 + nt * 8 + tg * 2;
            if (r0 < NC) {
                atomicAdd(&Cp[(size_t)r0 * CC + col], acc[mt][nt][0]);
                atomicAdd(&Cp[(size_t)r0 * CC + col + 1], acc[mt][nt][1]);
            }
            if (r0 + 8 < NC) {
                atomicAdd(&Cp[(size_t)(r0 + 8) * CC + col], acc[mt][nt][2]);
                atomicAdd(&Cp[(size_t)(r0 + 8) * CC + col + 1], acc[mt][nt][3]);
            }
        }
    }
}

// ---------------- split helpers ----------------
__device__ __forceinline__ void split_store4(const float4 v, bf16* hi, bf16* lo, int i) {
    bf16 h0 = __float2bfloat16(v.x), h1 = __float2bfloat16(v.y);
    bf16 h2 = __float2bfloat16(v.z), h3 = __float2bfloat16(v.w);
    *(__nv_bfloat162*)(hi + i)     = __nv_bfloat162(h0, h1);
    *(__nv_bfloat162*)(hi + i + 2) = __nv_bfloat162(h2, h3);
    *(__nv_bfloat162*)(lo + i) = __nv_bfloat162(
        __float2bfloat16(v.x - __bfloat162float(h0)),
        __float2bfloat16(v.y - __bfloat162float(h1)));
    *(__nv_bfloat162*)(lo + i + 2) = __nv_bfloat162(
        __float2bfloat16(v.z - __bfloat162float(h2)),
        __float2bfloat16(v.w - __bfloat162float(h3)));
}

// ---- body: split + transpose-split (needs tile) ----
__device__ __forceinline__ void split_all_body(
    float (*tile)[33], const float* in, bf16* oh, bf16* ol, bf16* toh, bf16* tol,
    int bx, int by, int bz, int tx, int ty)
{
    const float* src = in + (size_t)bz * 1048576;
    bf16* doh = oh + (size_t)bz * 1048576;
    bf16* dol = ol + (size_t)bz * 1048576;
    bf16* dth = toh + (size_t)bz * 1048576;
    bf16* dtl = tol + (size_t)bz * 1048576;
    int r0 = bx * 32, c0 = by * 32;
    #pragma unroll
    for (int i = 0; i < 4; i++) {
        int r = r0 + ty + i * 8;
        float v = src[(size_t)r * CC + c0 + tx];
        tile[ty + i * 8][tx] = v;
        bf16 h = __float2bfloat16(v);
        doh[(size_t)r * CC + c0 + tx] = h;
        dol[(size_t)r * CC + c0 + tx] = __float2bfloat16(v - __bfloat162float(h));
    }
    __syncthreads();
    #pragma unroll
    for (int i = 0; i < 4; i++) {
        int c = c0 + ty + i * 8;
        float v = tile[tx][ty + i * 8];
        bf16 h = __float2bfloat16(v);
        dth[(size_t)c * N4 + r0 + tx] = h;
        dtl[(size_t)c * N4 + r0 + tx] = __float2bfloat16(v - __bfloat162float(h));
    }
}

// ================= merged prep kernel =================
// segments: [0,2048) split_all(x); [2048,8192) split_all(mem);
//           [8192,9472) cvt5; [9472,9572) tdt; [9572,14692) zT
__global__ void __launch_bounds__(256)
prep_all_kernel(const float* __restrict__ x, const float* __restrict__ mem,
                const float* __restrict__ z,
                const float* __restrict__ q_w, const float* __restrict__ proj_w,
                const float* __restrict__ fc1_w, const float* __restrict__ fc2_w,
                const float* __restrict__ cw,
                const float* __restrict__ tdt1, const float* __restrict__ tdt2,
                bf16* xh, bf16* xl, bf16* xth, bf16* xtl,
                bf16* memh, bf16* meml, bf16* memth, bf16* memtl,
                bf16* zth, bf16* ztl,
                bf16* qwh, bf16* qwl, bf16* pwh, bf16* pwl,
                bf16* f1h, bf16* f1l, bf16* f2h, bf16* f2l,
                bf16* cwh, bf16* cwl,
                bf16* t1h, bf16* t1l, bf16* t2h, bf16* t2l)
{
    __shared__ float tile[32][33];
    int blk = blockIdx.x;
    int tid = threadIdx.x;
    int tx = tid & 31, ty = tid >> 5;

    if (blk < 2048) {
        int bx = blk & 127, by = (blk >> 7) & 7, bz = blk >> 10;
        split_all_body(tile, x, xh, xl, xth, xtl, bx, by, bz, tx, ty);
    } else if (blk < 8192) {
        int j = blk - 2048;
        int bx = j & 127, by = (j >> 7) & 7, bz = j >> 10;
        split_all_body(tile, mem, memh, meml, memth, memtl, bx, by, bz, tx, ty);
    } else if (blk < 9472) {
        int j = blk - 8192;
        int bx = j & 255, by = j >> 8;
        const float* in; bf16 *hi, *lo; int n;
        switch (by) {
            case 0: in = q_w; hi = qwh; lo = qwl; n = 65536; break;
            case 1: in = proj_w; hi = pwh; lo = pwl; n = 65536; break;
            case 2: in = fc1_w; hi = f1h; lo = f1l; n = 262144; break;
            case 3: in = fc2_w; hi = f2h; lo = f2l; n = 262144; break;
            default: in = cw; hi = cwh; lo = cwl; n = 38400; break;
        }
        int i = (bx * 256 + tid) * 4;
        if (i < n) split_store4(*(const float4*)(in + i), hi, lo, i);
    } else if (blk < 9572) {
        int i = (blk - 9472) * 256 + tid;
        if (i < KPAD * KPAD) {
            int j = i / KPAD, k = i % KPAD;
            float v1 = (j < NC && k < NC) ? tdt1[k * NC + j] : 0.f;
            float v2 = (j < NC && k < NC) ? tdt2[k * NC + j] : 0.f;
            bf16 h1 = __float2bfloat16(v1), h2 = __float2bfloat16(v2);
            t1h[i] = h1; t1l[i] = __float2bfloat16(v1 - __bfloat162float(h1));
            t2h[i] = h2; t2l[i] = __float2bfloat16(v2 - __bfloat162float(h2));
        }
    } else {
        int j = blk - 9572;                 // zT: grid (512,5,2)
        int bx = j & 511, by = (j >> 9) % 5, bz = j / 2560;
        int m0 = bx * 32, k0 = by * 32;
        #pragma unroll
        for (int i = 0; i < 4; i++) {
            int k = k0 + ty + i * 8;
            tile[ty + i * 8][tx] = (k < NC) ? z[((size_t)bz * NC + k) * TNE + m0 + tx] : 0.f;
        }
        __syncthreads();
        #pragma unroll
        for (int i = 0; i < 4; i++) {
            int m = m0 + ty + i * 8;
            float v = tile[tx][ty + i * 8];
            bf16 h = __float2bfloat16(v);
            size_t idx = ((size_t)bz * TNE + m) * KPAD + k0 + tx;
            zth[idx] = h;
            ztl[idx] = __float2bfloat16(v - __bfloat162float(h));
        }
    }
}

// ================= merged mid kernel: prompt + clT + zero_cen =================
// segments: [0,128) prompt; [128,5248) clT; [5248,5548) zero cen
__global__ void __launch_bounds__(256)
mid_kernel(const float* __restrict__ z, const float* __restrict__ cl,
           const float* __restrict__ p1, const float* __restrict__ p2,
           float* __restrict__ cz, float* __restrict__ cc,
           bf16* __restrict__ clth, bf16* __restrict__ cltl,
           float* __restrict__ cen)
{
    __shared__ float tile[32][33];
    int blk = blockIdx.x;
    int tid = threadIdx.x;

    if (blk < 128) {
        int bx = blk & 63, b = blk >> 6;
        int m = bx * 256 + tid;
        int t = m >> 12, n = m & 4095;
        const float* zrow = z + (size_t)b * NC * TNE + m;
        const float* crow = cl + ((size_t)(b * TT4 + t) * NC) * N4 + n;
        float dz = 0, nz = 0, dc = 0, ncs = 0, p1n = 0, p2n = 0;
        for (int k = 0; k < NC; k++) {
            float zv = zrow[(size_t)k * TNE];
            float cv = crow[(size_t)k * N4];
            float a = p1[k], bb = p2[k];
            dz += zv * a; nz += zv * zv; p1n += a * a;
            dc += cv * bb; ncs += cv * cv; p2n += bb * bb;
        }
        float vz = dz / (fmaxf(sqrtf(nz), 1e-12f) * fmaxf(sqrtf(p1n), 1e-12f));
        float vc = dc / (fmaxf(sqrtf(ncs), 1e-12f) * fmaxf(sqrtf(p2n), 1e-12f));
        cz[(size_t)b * TNE + m] = fminf(fmaxf(vz, 0.f), 1.f) * 0.5f;
        cc[(size_t)b * TNE + m] = fminf(fmaxf(vc, 0.f), 1.f) * 0.5f;
    } else if (blk < 5248) {
        int j = blk - 128;                 // clT: grid (128,5,8)
        int bx = j & 127, by = (j >> 7) % 5, bt = j / 640;
        int b = bt >> 2, t = bt & 3;
        int tx = tid & 31, ty = tid >> 5;
        int n0 = bx * 32, k0 = by * 32;
        const float* src = cl + (size_t)bt * 614400;
        #pragma unroll
        for (int i = 0; i < 4; i++) {
            int k = k0 + ty + i * 8;
            tile[ty + i * 8][tx] = (k < NC) ? src[(size_t)k * N4 + n0 + tx] : 0.f;
        }
        __syncthreads();
        #pragma unroll
        for (int i = 0; i < 4; i++) {
            int n = n0 + ty + i * 8;
            float v = tile[tx][ty + i * 8];
            bf16 h = __float2bfloat16(v);
            size_t idx = ((size_t)b * TNE + t * N4 + n) * KPAD + k0 + tx;
            clth[idx] = h;
            cltl[idx] = __float2bfloat16(v - __bfloat162float(h));
        }
    } else {
        int i = ((blk - 5248) * 256 + tid) * 4;
        if (i < 307200) *(float4*)(cen + i) = make_float4(0.f, 0.f, 0.f, 0.f);
    }
}

// ---------------- hybrid warp-shuffle block reductions (256 threads) -----
__device__ __forceinline__ float block_reduce_sum(float v, float* sbuf) {
    int tid = threadIdx.x, lane = tid & 31, wid = tid >> 5;
    #pragma unroll
    for (int off = 16; off > 0; off >>= 1)
        v += __shfl_xor_sync(0xffffffffu, v, off);
    if (lane == 0) sbuf[wid] = v;
    __syncthreads();
    float r = sbuf[0] + sbuf[1] + sbuf[2] + sbuf[3]
            + sbuf[4] + sbuf[5] + sbuf[6] + sbuf[7];
    __syncthreads();
    return r;
}
__device__ __forceinline__ float block_reduce_max(float v, float* sbuf) {
    int tid = threadIdx.x, lane = tid & 31, wid = tid >> 5;
    #pragma unroll
    for (int off = 16; off > 0; off >>= 1)
        v = fmaxf(v, __shfl_xor_sync(0xffffffffu, v, off));
    if (lane == 0) sbuf[wid] = v;
    __syncthreads();
    float r = fmaxf(fmaxf(fmaxf(sbuf[0], sbuf[1]), fmaxf(sbuf[2], sbuf[3])),
                    fmaxf(fmaxf(sbuf[4], sbuf[5]), fmaxf(sbuf[6], sbuf[7])));
    __syncthreads();
    return r;
}

// ======== merged k/v projection ====
#define OBM 64
#define OBN 64
#define OBK 16
__global__ void gemm_kv_kernel(const float* __restrict__ A,
                               const float* __restrict__ k_w, const float* __restrict__ k_b,
                               const float* __restrict__ v_w, const float* __restrict__ v_b,
                               float* __restrict__ kout, float* __restrict__ vout)
{
    const float* B = blockIdx.z ? v_w : k_w;
    const float* bias = blockIdx.z ? v_b : k_b;
    float* C = blockIdx.z ? vout : kout;
    const int M = BB * NC;
    __shared__ float As[OBK][OBM];
    __shared__ float Bs[OBK][OBN];
    int tid = threadIdx.x;
    int tx = tid & 15, ty = tid >> 4;
    int m0 = blockIdx.y * OBM, n0 = blockIdx.x * OBN;
    float acc[4][4] = {};
    for (int k0 = 0; k0 < CC; k0 += OBK) {
        #pragma unroll
        for (int j = 0; j < 4; j++) {
            int idx = tid + j * 256;
            int ml = idx / OBK, kl = idx % OBK;
            int m = m0 + ml;
            As[kl][ml] = (m < M) ? A[(size_t)m * CC + k0 + kl] : 0.f;
        }
        #pragma unroll
        for (int j = 0; j < 4; j++) {
            int idx = tid + j * 256;
            int nl = idx / OBK, kl = idx % OBK;
            Bs[kl][nl] = B[(size_t)(n0 + nl) * CC + k0 + kl];
        }
        __syncthreads();
        #pragma unroll
        for (int kk = 0; kk < OBK; kk++) {
            float a[4], b[4];
            *(float4*)a = *(const float4*)&As[kk][ty * 4];
            *(float4*)b = *(const float4*)&Bs[kk][tx * 4];
            #pragma unroll
            for (int i = 0; i < 4; i++)
                #pragma unroll
                for (int j = 0; j < 4; j++)
                    acc[i][j] += a[i] * b[j];
        }
        __syncthreads();
    }
    #pragma unroll
    for (int i = 0; i < 4; i++) {
        int m = m0 + ty * 4 + i;
        if (m >= M) continue;
        #pragma unroll
        for (int j = 0; j < 4; j++) {
            int n = n0 + tx * 4 + j;
            C[(size_t)m * CC + n] = acc[i][j] + bias[n];
        }
    }
}

// ---- softmax -> bf16 hi/lo ----
__global__ void softmax_kernel(const float* __restrict__ cxz,
                               bf16* __restrict__ softh, bf16* __restrict__ softl)
{
    __shared__ float sbuf[8];
    int r = blockIdx.x;
    int k = r % NC;
    int bt = r / NC;
    int b = bt / TT4, t = bt % TT4;
    const float* src = cxz + ((size_t)b * NC + k) * TNE + t * N4;
    bf16* dh = softh + (size_t)r * N4;
    bf16* dl = softl + (size_t)r * N4;
    int tid = threadIdx.x;
    float mx = -3.4e38f;
    for (int i = tid; i < N4; i += 256) mx = fmaxf(mx, src[i]);
    mx = block_reduce_max(mx, sbuf);
    float s = 0.f;
    float ev[16];
    #pragma unroll
    for (int j = 0; j < 16; j++) {
        int i = tid + j * 256;
        ev[j] = expf(src[i] - mx);
        s += ev[j];
    }
    s = block_reduce_sum(s, sbuf);
    float inv = 1.f / s;
    #pragma unroll
    for (int j = 0; j < 16; j++) {
        int i = tid + j * 256;
        float v = ev[j] * inv;
        bf16 h = __float2bfloat16(v);
        dh[i] = h;
        dl[i] = __float2bfloat16(v - __bfloat162float(h));
    }
}

// ---- C_in gating + LayerNorm ----
__global__ void cin_kernel(const float* __restrict__ cen,
                           const float* __restrict__ alpha,
                           const float* __restrict__ beta,
                           const float* __restrict__ nw,
                           const float* __restrict__ nb,
                           float* __restrict__ cinln)
{
    __shared__ float sbuf[8];
    int bk = blockIdx.x;
    int b = bk / NC, k = bk % NC;
    int c = threadIdx.x;
    float last = cen[((size_t)(b * TT4 + 3) * NC + k) * CC + c];
    float pv[3];
    #pragma unroll
    for (int t = 0; t < 3; t++)
        pv[t] = cen[((size_t)(b * TT4 + t) * NC + k) * CC + c];
    float nl = block_reduce_sum(last * last, sbuf);
    float al = alpha[0], be = beta[0];
    float g[3];
    #pragma unroll
    for (int t = 0; t < 3; t++) {
        float dt = block_reduce_sum(last * pv[t], sbuf);
        float np = block_reduce_sum(pv[t] * pv[t], sbuf);
        float denom = fmaxf(sqrtf(nl) * sqrtf(np), 1e-8f);
        g[t] = 1.f / (1.f + expf(-(be + al * dt / denom)));
    }
    float cin = last + g[0] * pv[0] + g[1] * pv[1] + g[2] * pv[2];
    float mean = block_reduce_sum(cin, sbuf) * (1.f / CC);
    float d = cin - mean;
    float var = block_reduce_sum(d * d, sbuf) * (1.f / CC);
    cinln[((size_t)b * NC + k) * CC + c] = d * rsqrtf(var + 1e-5f) * nw[c] + nb[c];
}

// ---- attention -> bf16 hi/lo output ----
__global__ void attn_kernel(const float* __restrict__ q,
                            const float* __restrict__ kbuf,
                            const float* __restrict__ vbuf,
                            bf16* __restrict__ obh, bf16* __restrict__ obl)
{
    __shared__ float kh[NC * 33];
    __shared__ float vh[NC * 33];
    int b = blockIdx.z, h = blockIdx.y;
    int tid = threadIdx.x;
    int warp = tid >> 5, lane = tid & 31;
    for (int idx = tid; idx < NC * HD; idx += blockDim.x) {
        int kk = idx / HD, d = idx % HD;
        kh[kk * 33 + d] = kbuf[((size_t)b * NC + kk) * CC + h * HD + d];
        vh[kk * 33 + d] = vbuf[((size_t)b * NC + kk) * CC + h * HD + d];
    }
    __syncthreads();
    const unsigned FULL = 0xffffffffu;
    for (int ni = warp; ni < 256; ni += 8) {
        int n = blockIdx.x * 256 + ni;
        float qv = q[((size_t)b * N4 + n) * CC + h * HD + lane];
        float lg[5];
        #pragma unroll
        for (int i = 0; i < 5; i++) {
            int kk = lane + 32 * i;
            int kks = (kk < NC) ? kk : (NC - 1);
            float acc = 0.f;
            #pragma unroll
            for (int d = 0; d < 32; d++) {
                float qd = __shfl_sync(FULL, qv, d);
                acc += qd * kh[kks * 33 + d];
            }
            lg[i] = (kk < NC) ? acc : -3.4e38f;
        }
        float mx = lg[0];
        #pragma unroll
        for (int i = 1; i < 5; i++) mx = fmaxf(mx, lg[i]);
        #pragma unroll
        for (int off = 16; off > 0; off >>= 1)
            mx = fmaxf(mx, __shfl_xor_sync(FULL, mx, off));
        float p[5], s = 0.f;
        #pragma unroll
        for (int i = 0; i < 5; i++) { p[i] = expf(lg[i] - mx); s += p[i]; }
        #pragma unroll
        for (int off = 16; off > 0; off >>= 1)
            s += __shfl_xor_sync(FULL, s, off);
        float inv = 1.f / s;
        float od = 0.f;
        #pragma unroll
        for (int i = 0; i < 5; i++) {
            float pi = p[i] * inv;
            #pragma unroll
            for (int l = 0; l < 32; l++) {
                float a = __shfl_sync(FULL, pi, l);
                int kk = l + 32 * i;
                if (kk < NC) od += a * vh[kk * 33 + lane];
            }
        }
        size_t idx = ((size_t)b * N4 + n) * CC + h * HD + lane;
        bf16 hh = __float2bfloat16(od);
        obh[idx] = hh;
        obl[idx] = __float2bfloat16(od - __bfloat162float(hh));
    }
}

// ---- out = base + LN(xin) ----
__global__ void ln_add_kernel(const float* __restrict__ base,
                              const float* __restrict__ xin,
                              const float* __restrict__ nw,
                              const float* __restrict__ nb,
                              float* __restrict__ out)
{
    __shared__ float sbuf[8];
    size_t row = blockIdx.x;
    int c = threadIdx.x;
    float v = xin[row * CC + c];
    float mean = block_reduce_sum(v, sbuf) * (1.f / CC);
    float d = v - mean;
    float var = block_reduce_sum(d * d, sbuf) * (1.f / CC);
    out[row * CC + c] = base[row * CC + c] + d * rsqrtf(var + 1e-5f) * nw[c] + nb[c];
}

// ---- out = base + LN(xin), + bf16 split ----
__global__ void ln_add_split_kernel(const float* __restrict__ base,
                                    const float* __restrict__ xin,
                                    const float* __restrict__ nw,
                                    const float* __restrict__ nb,
                                    float* __restrict__ out,
                                    bf16* __restrict__ ohi, bf16* __restrict__ olo)
{
    __shared__ float sbuf[8];
    size_t row = blockIdx.x;
    int c = threadIdx.x;
    float v = xin[row * CC + c];
    float mean = block_reduce_sum(v, sbuf) * (1.f / CC);
    float d = v - mean;
    float var = block_reduce_sum(d * d, sbuf) * (1.f / CC);
    float r = base[row * CC + c] + d * rsqrtf(var + 1e-5f) * nw[c] + nb[c];
    size_t idx = row * CC + c;
    out[idx] = r;
    bf16 h = __float2bfloat16(r);
    ohi[idx] = h;
    olo[idx] = __float2bfloat16(r - __bfloat162float(h));
}

// ---- depthwise conv + GELU -> bf16 hi/lo ----
__global__ void dwconv_gelu_bf16_kernel(const float* __restrict__ h1,
                                        const float* __restrict__ dw_w,
                                        const float* __restrict__ dw_b,
                                        bf16* __restrict__ gh, bf16* __restrict__ gl)
{
    int idx = blockIdx.x * blockDim.x + threadIdx.x;
    if (idx >= BB * N4 * HID) return;
    int ch = idx & (HID - 1);
    int r = idx >> 10;
    int n = r & (N4 - 1);
    int b = r >> 12;
    int y = n >> 6, x = n & 63;
    float acc = dw_b[ch];
    #pragma unroll
    for (int dy = 0; dy < 3; dy++) {
        int yy = y + dy - 1;
        if (yy < 0 || yy >= HH) continue;
        #pragma unroll
        for (int dx = 0; dx < 3; dx++) {
            int xx = x + dx - 1;
            if (xx < 0 || xx >= WW) continue;
            acc += h1[((size_t)b * N4 + yy * WW + xx) * HID + ch] *
                   dw_w[ch * 9 + dy * 3 + dx];
        }
    }
    float v = 0.5f * acc * (1.0f + erff(acc * 0.70710678118654752f));
    bf16 h = __float2bfloat16(v);
    gh[idx] = h;
    gl[idx] = __float2bfloat16(v - __bfloat162float(h));
}

// ================= host launcher =================
#define SMEM_W4  92160
#define SMEM_W8  122880

extern "C" void kernel_launch(void* const* d_in, const int* in_sizes, int n_in,
                              void* d_out, int out_size)
{
    const float* x      = (const float*)d_in[0];
    const float* z      = (const float*)d_in[1];
    const float* mem    = (const float*)d_in[2];
    const float* cw     = (const float*)d_in[3];
    const float* p1     = (const float*)d_in[4];
    const float* tdt1   = (const float*)d_in[5];
    const float* p2     = (const float*)d_in[6];
    const float* tdt2   = (const float*)d_in[7];
    const float* alpha  = (const float*)d_in[8];
    const float* beta   = (const float*)d_in[9];
    const float* q_w    = (const float*)d_in[10];
    const float* q_b    = (const float*)d_in[11];
    const float* k_w    = (const float*)d_in[12];
    const float* k_b    = (const float*)d_in[13];
    const float* v_w    = (const float*)d_in[14];
    const float* v_b    = (const float*)d_in[15];
    const float* proj_w = (const float*)d_in[16];
    const float* proj_b = (const float*)d_in[17];
    const float* norm_w = (const float*)d_in[18];
    const float* norm_b = (const float*)d_in[19];
    const float* fc1_w  = (const float*)d_in[20];
    const float* fc1_b  = (const float*)d_in[21];
    const float* dw_w   = (const float*)d_in[22];
    const float* dw_b   = (const float*)d_in[23];
    const float* fc2_w  = (const float*)d_in[24];
    const float* fc2_b  = (const float*)d_in[25];

    float* out0 = (float*)d_out;
    float* cxz  = out0 + OUT0_ELEMS;
    float* ctr  = out0 + OUT0_ELEMS + CXZ_ELEMS;

    float *cl, *cz, *cc, *cen, *cinln, *kb, *vb, *qb, *oproj, *out1, *h1, *h2;
    bf16 *xh, *xl, *memh, *meml, *xth, *xtl, *memth, *memtl, *cwh, *cwl;
    bf16 *t1h, *t1l, *t2h, *t2l, *zth, *ztl, *clth, *cltl;
    bf16 *softh, *softl, *obh, *obl, *o1h, *o1l, *gh, *gl;
    bf16 *qwh, *qwl, *pwh, *pwl, *f1h, *f1l, *f2h, *f2l;
    cudaGetSymbolAddress((void**)&cl,    g_cl);
    cudaGetSymbolAddress((void**)&cz,    g_cz);
    cudaGetSymbolAddress((void**)&cc,    g_cc);
    cudaGetSymbolAddress((void**)&cen,   g_cen);
    cudaGetSymbolAddress((void**)&cinln, g_cinln);
    cudaGetSymbolAddress((void**)&kb,    g_kbuf);
    cudaGetSymbolAddress((void**)&vb,    g_vbuf);
    cudaGetSymbolAddress((void**)&qb,    g_q);
    cudaGetSymbolAddress((void**)&oproj, g_oproj);
    cudaGetSymbolAddress((void**)&out1,  g_out1);
    cudaGetSymbolAddress((void**)&h1,    g_h1);
    cudaGetSymbolAddress((void**)&h2,    g_h2);
    cudaGetSymbolAddress((void**)&xh,   g_xh);   cudaGetSymbolAddress((void**)&xl,   g_xl);
    cudaGetSymbolAddress((void**)&memh, g_memh); cudaGetSymbolAddress((void**)&meml, g_meml);
    cudaGetSymbolAddress((void**)&xth,  g_xth);  cudaGetSymbolAddress((void**)&xtl,  g_xtl);
    cudaGetSymbolAddress((void**)&memth, g_memth); cudaGetSymbolAddress((void**)&memtl, g_memtl);
    cudaGetSymbolAddress((void**)&cwh,  g_cwh);  cudaGetSymbolAddress((void**)&cwl,  g_cwl);
    cudaGetSymbolAddress((void**)&t1h,  g_t1h);  cudaGetSymbolAddress((void**)&t1l,  g_t1l);
    cudaGetSymbolAddress((void**)&t2h,  g_t2h);  cudaGetSymbolAddress((void**)&t2l,  g_t2l);
    cudaGetSymbolAddress((void**)&zth,  g_zth);  cudaGetSymbolAddress((void**)&ztl,  g_ztl);
    cudaGetSymbolAddress((void**)&clth, g_clth); cudaGetSymbolAddress((void**)&cltl, g_cltl);
    cudaGetSymbolAddress((void**)&softh, g_softh); cudaGetSymbolAddress((void**)&softl, g_softl);
    cudaGetSymbolAddress((void**)&obh, g_obh); cudaGetSymbolAddress((void**)&obl, g_obl);
    cudaGetSymbolAddress((void**)&o1h, g_o1h); cudaGetSymbolAddress((void**)&o1l, g_o1l);
    cudaGetSymbolAddress((void**)&gh,  g_gh);  cudaGetSymbolAddress((void**)&gl,  g_gl);
    cudaGetSymbolAddress((void**)&qwh, g_qwh); cudaGetSymbolAddress((void**)&qwl, g_qwl);
    cudaGetSymbolAddress((void**)&pwh, g_pwh); cudaGetSymbolAddress((void**)&pwl, g_pwl);
    cudaGetSymbolAddress((void**)&f1h, g_f1h); cudaGetSymbolAddress((void**)&f1l, g_f1l);
    cudaGetSymbolAddress((void**)&f2h, g_f2h); cudaGetSymbolAddress((void**)&f2l, g_f2l);

    cudaFuncSetAttribute(hmma_gemm_kernel<4>,
                         cudaFuncAttributeMaxDynamicSharedMemorySize, SMEM_W4);
    cudaFuncSetAttribute(hmma_gemm_kernel<8>,
                         cudaFuncAttributeMaxDynamicSharedMemorySize, SMEM_W8);
    cudaFuncSetAttribute(clq_hmma_kernel,
                         cudaFuncAttributeMaxDynamicSharedMemorySize, SMEM_W8);
    cudaFuncSetAttribute(cen_hmma_kernel,
                         cudaFuncAttributeMaxDynamicSharedMemorySize, SMEM_W8);
    cudaFuncSetAttribute(comb_hmma_kernel,
                         cudaFuncAttributeMaxDynamicSharedMemorySize, SMEM_W4);

    // 0) merged prep (x/mem splits+transposes, weight splits, tdt, zT)
    prep_all_kernel<<<14692, 256>>>(
        x, mem, z, q_w, proj_w, fc1_w, fc2_w, cw, tdt1, tdt2,
        xh, xl, xth, xtl, memh, meml, memth, memtl, zth, ztl,
        qwh, qwl, pwh, pwl, f1h, f1l, f2h, f2l, cwh, cwl,
        t1h, t1l, t2h, t2l);

    // 1) merged cl GEMM + q projection (independent HMMA work)
    clq_hmma_kernel<<<dim3(32, 2, 12), 256, SMEM_W8>>>(
        cwh, cwl, xh, xl, memh, meml, cl, qwh, qwl, q_b, qb);

    // 2) merged prompt cos + clT split + zero cen
    mid_kernel<<<5548, 256>>>(z, cl, p1, p2, cz, cc, clth, cltl, cen);

    // 3) combine (HMMA) -> cluster_x_z + center
    comb_hmma_kernel<<<dim3(256, 2, 2), 256, SMEM_W4>>>(
        t1h, t1l, t2h, t2l, zth, ztl, clth, cltl, cz, cc, cxz, ctr);
    // 4) softmax -> bf16 hi/lo
    softmax_kernel<<<BB * TT4 * NC, 256>>>(cxz, softh, softl);
    // 5) cen (HMMA, split-K atomic)
    cen_hmma_kernel<<<dim3(2, 2, 64), 256, SMEM_W8>>>(softh, softl, xth, xtl, memth, memtl, cen);
    // 6) gating + LN
    cin_kernel<<<BB * NC, 256>>>(cen, alpha, beta, norm_w, norm_b, cinln);
    // 7) k/v projections (merged)
    gemm_kv_kernel<<<dim3(4, 5, 2), 256>>>(cinln, k_w, k_b, v_w, v_b, kb, vb);
    // 8) attention -> bf16 split
    attn_kernel<<<dim3(N4 / 256, NH, BB), 256>>>(qb, kb, vb, obh, obl);
    // 9) output projection
    hmma_gemm_kernel<4><<<dim3(4, 64), 256, SMEM_W4>>>(
        obh, obl, pwh, pwl, proj_b, oproj, CC, CC, 1.f);
    // 10) out1 = x + LN(oproj), + split
    ln_add_split_kernel<<<BB * N4, 256>>>(x, oproj, norm_w, norm_b, out1, o1h, o1l);
    // 11) fc1
    hmma_gemm_kernel<8><<<dim3(8, 64), 256, SMEM_W8>>>(
        o1h, o1l, f1h, f1l, fc1_b, h1, HID, CC, 1.f);
    // 12) depthwise conv + gelu -> split
    dwconv_gelu_bf16_kernel<<<(BB * N4 * HID + 255) / 256, 256>>>(h1, dw_w, dw_b, gh, gl);
    // 13) fc2
    hmma_gemm_kernel<4><<<dim3(4, 64), 256, SMEM_W4>>>(
        gh, gl, f2h, f2l, fc2_b, h2, CC, HID, 1.f);
    // 14) out = out1 + LN(h2)
    ln_add_kernel<<<BB * N4, 256>>>(out1, h2, norm_w, norm_b, out0);
}